// round 1
// baseline (speedup 1.0000x reference)
#include <cuda_runtime.h>
#include <math_constants.h>

#define N_NODES 32768
#define N_EDGES 524288
#define DMODEL  128
#define BATCH   32
#define SEQ     1024
#define HEADS   8
#define DHEAD   16
#define DFF     512
#define NTOT    (N_EDGES + N_NODES)

// ---------------- scratch (__device__ globals: allocation-guard safe) ------
static __device__ float g_dinv[N_NODES];
static __device__ int   g_counts[N_NODES];
static __device__ int   g_rowoff[N_NODES + 1];
static __device__ int   g_cursor[N_NODES];
static __device__ int   g_csr[NTOT];
static __device__ float g_h [N_NODES * DMODEL];
static __device__ float g_x1[N_NODES * DMODEL];
static __device__ float g_gx[N_NODES * DMODEL];
static __device__ float g_y [N_NODES * DMODEL];
static __device__ float g_Qb[N_NODES * DMODEL];
static __device__ float g_Kb[N_NODES * DMODEL];
static __device__ float g_Vb[N_NODES * DMODEL];
static __device__ float g_Ab[N_NODES * DMODEL];
static __device__ float g_Pb[N_NODES * DMODEL];
static __device__ float g_F1[N_NODES * DFF];
static __device__ float g_F2[N_NODES * DMODEL];

// ---------------- graph preprocessing --------------------------------------
__global__ void k_init_counts(int* counts) {
    int i = blockIdx.x * blockDim.x + threadIdx.x;
    counts[i] = 0;
}

__global__ void k_count(const int* __restrict__ eidx, int* __restrict__ counts) {
    int e = blockIdx.x * blockDim.x + threadIdx.x;   // e < N_EDGES
    atomicAdd(&counts[eidx[N_EDGES + e]], 1);        // dst row
}

// single block, 1024 threads: exclusive scan of (counts[i]+1), also dinv.
__global__ void k_scan(const int* __restrict__ counts, int* __restrict__ rowoff,
                       int* __restrict__ cursor, float* __restrict__ dinv) {
    __shared__ int part[1024];
    int tid = threadIdx.x;
    int base = tid * 32;
    int c[32];
    int s = 0;
#pragma unroll
    for (int i = 0; i < 32; i++) { c[i] = counts[base + i] + 1; s += c[i]; }
    part[tid] = s;
    __syncthreads();
    for (int off = 1; off < 1024; off <<= 1) {
        int v = (tid >= off) ? part[tid - off] : 0;
        __syncthreads();
        part[tid] += v;
        __syncthreads();
    }
    int run = part[tid] - s;  // exclusive prefix of this chunk
#pragma unroll
    for (int i = 0; i < 32; i++) {
        rowoff[base + i] = run;
        cursor[base + i] = run;
        dinv[base + i] = rsqrtf((float)c[i]);
        run += c[i];
    }
    if (tid == 1023) rowoff[N_NODES] = run;
}

__global__ void k_fill(const int* __restrict__ eidx, int* __restrict__ cursor,
                       int* __restrict__ csr) {
    int e = blockIdx.x * blockDim.x + threadIdx.x;   // e < NTOT
    int s, d;
    if (e < N_EDGES) { s = eidx[e]; d = eidx[N_EDGES + e]; }
    else             { s = d = e - N_EDGES; }        // self loop
    int pos = atomicAdd(&cursor[d], 1);
    csr[pos] = s;
}

// out[i] = relu( dinv[i] * sum_{e in row i} dinv[src]*h[src] + bias )
__global__ void k_aggregate(const float* __restrict__ h, const float* __restrict__ dinv,
                            const int* __restrict__ rowoff, const int* __restrict__ csr,
                            const float* __restrict__ bias, float* __restrict__ out) {
    int wid = threadIdx.x >> 5, lane = threadIdx.x & 31;
    int i = blockIdx.x * 8 + wid;
    const float4* h4 = (const float4*)h;
    float4 acc = make_float4(0.f, 0.f, 0.f, 0.f);
    int e = rowoff[i], end = rowoff[i + 1];
    for (; e + 2 <= end; e += 2) {
        int s0 = csr[e], s1 = csr[e + 1];
        float w0 = dinv[s0], w1 = dinv[s1];
        float4 v0 = h4[s0 * 32 + lane];
        float4 v1 = h4[s1 * 32 + lane];
        acc.x = fmaf(w0, v0.x, fmaf(w1, v1.x, acc.x));
        acc.y = fmaf(w0, v0.y, fmaf(w1, v1.y, acc.y));
        acc.z = fmaf(w0, v0.z, fmaf(w1, v1.z, acc.z));
        acc.w = fmaf(w0, v0.w, fmaf(w1, v1.w, acc.w));
    }
    if (e < end) {
        int s0 = csr[e];
        float w0 = dinv[s0];
        float4 v0 = h4[s0 * 32 + lane];
        acc.x = fmaf(w0, v0.x, acc.x);
        acc.y = fmaf(w0, v0.y, acc.y);
        acc.z = fmaf(w0, v0.z, acc.z);
        acc.w = fmaf(w0, v0.w, acc.w);
    }
    float di = dinv[i];
    float4 b4 = ((const float4*)bias)[lane];
    float4 o;
    o.x = fmaxf(fmaf(di, acc.x, b4.x), 0.f);
    o.y = fmaxf(fmaf(di, acc.y, b4.y), 0.f);
    o.z = fmaxf(fmaf(di, acc.z, b4.z), 0.f);
    o.w = fmaxf(fmaf(di, acc.w, b4.w), 0.f);
    ((float4*)out)[i * 32 + lane] = o;
}

// ---------------- generic GEMM: C[rows x ncols] = A[rows x K] @ W[K x ncols]
// block = 256 threads, tile 64 rows x 128 cols, BK = 64.
__global__ void k_gemm(const float* __restrict__ A, const float* __restrict__ W,
                       const float* __restrict__ bias, float* __restrict__ C,
                       int K, int ncols, int act) {
    __shared__ float As[64 * 64];     // 16 KB
    __shared__ float Ws[64 * 128];    // 32 KB
    int tid = threadIdx.x;
    int rowBase = blockIdx.x * 64, colBase = blockIdx.y * 128;
    int ry = tid >> 5, cx = tid & 31;

    float acc[8][4];
#pragma unroll
    for (int r = 0; r < 8; r++)
#pragma unroll
        for (int c = 0; c < 4; c++) acc[r][c] = 0.f;

    const float4* A4 = (const float4*)A;
    const float4* W4 = (const float4*)W;

    for (int kOff = 0; kOff < K; kOff += 64) {
#pragma unroll
        for (int t = 0; t < 4; t++) {                 // A tile: 64x64
            int idx = tid + 256 * t;
            int r = idx >> 4, c4 = idx & 15;
            ((float4*)As)[r * 16 + c4] = A4[(((rowBase + r) * K + kOff) >> 2) + c4];
        }
#pragma unroll
        for (int t = 0; t < 8; t++) {                 // W tile: 64x128
            int idx = tid + 256 * t;
            int r = idx >> 5, c4 = idx & 31;
            ((float4*)Ws)[r * 32 + c4] = W4[(((kOff + r) * ncols + colBase) >> 2) + c4];
        }
        __syncthreads();
#pragma unroll 8
        for (int kk = 0; kk < 64; kk++) {
            float a[8], w[4];
#pragma unroll
            for (int rr = 0; rr < 8; rr++) a[rr] = As[(ry + 8 * rr) * 64 + kk];
#pragma unroll
            for (int cc = 0; cc < 4; cc++) w[cc] = Ws[kk * 128 + cx + 32 * cc];
#pragma unroll
            for (int rr = 0; rr < 8; rr++)
#pragma unroll
                for (int cc = 0; cc < 4; cc++)
                    acc[rr][cc] = fmaf(a[rr], w[cc], acc[rr][cc]);
        }
        __syncthreads();
    }

    float wb[4] = {0.f, 0.f, 0.f, 0.f};
    if (bias) {
#pragma unroll
        for (int cc = 0; cc < 4; cc++) wb[cc] = bias[colBase + cx + 32 * cc];
    }
#pragma unroll
    for (int rr = 0; rr < 8; rr++) {
        int row = rowBase + ry + 8 * rr;
#pragma unroll
        for (int cc = 0; cc < 4; cc++) {
            float v = acc[rr][cc] + wb[cc];
            if (act) v = fmaxf(v, 0.f);
            C[row * ncols + colBase + cx + 32 * cc] = v;
        }
    }
}

// ---------------- attention: full K_h/V_h for one (b,h) resident in smem ----
// grid (SEQ/128, HEADS, BATCH), block 512. warp w handles 8 queries; per-lane
// online softmax over strided key subset, butterfly merge at the end.
__global__ void k_attn(const float* __restrict__ Q, const float* __restrict__ Kg,
                       const float* __restrict__ Vg, float* __restrict__ O) {
    extern __shared__ float4 sm[];
    float4* Ks4 = sm;               // [1024][5] padded (conflict-free LDS.128)
    float4* Vs4 = sm + 1024 * 5;
    int b = blockIdx.z, h = blockIdx.y;
    int tid = threadIdx.x, wid = tid >> 5, lane = tid & 31;
    const float4* Kg4 = (const float4*)Kg;
    const float4* Vg4 = (const float4*)Vg;
    const float4* Qg4 = (const float4*)Q;

#pragma unroll
    for (int t = 0; t < 8; t++) {
        int idx = tid + 512 * t;               // 0..4095
        int key = idx >> 2, c = idx & 3;
        int gi = (b * SEQ + key) * 32 + h * 4 + c;
        Ks4[key * 5 + c] = Kg4[gi];
        Vs4[key * 5 + c] = Vg4[gi];
    }
    __syncthreads();

    const float scale = 0.25f;                 // 1/sqrt(16)
    for (int qq = 0; qq < 8; qq++) {
        int q = blockIdx.x * 128 + wid * 8 + qq;
        int qb4 = (b * SEQ + q) * 32 + h * 4;
        float4 q0 = Qg4[qb4 + 0], q1 = Qg4[qb4 + 1], q2 = Qg4[qb4 + 2], q3 = Qg4[qb4 + 3];

        float m = -CUDART_INF_F, l = 0.f;
        float4 o0 = make_float4(0,0,0,0), o1 = o0, o2 = o0, o3 = o0;

#pragma unroll 4
        for (int it = 0; it < 32; it++) {
            int key = lane + it * 32;
            const float4* kp = &Ks4[key * 5];
            float4 k0 = kp[0], k1 = kp[1], k2 = kp[2], k3 = kp[3];
            float s;
            s = q0.x * k0.x;
            s = fmaf(q0.y, k0.y, s); s = fmaf(q0.z, k0.z, s); s = fmaf(q0.w, k0.w, s);
            s = fmaf(q1.x, k1.x, s); s = fmaf(q1.y, k1.y, s); s = fmaf(q1.z, k1.z, s); s = fmaf(q1.w, k1.w, s);
            s = fmaf(q2.x, k2.x, s); s = fmaf(q2.y, k2.y, s); s = fmaf(q2.z, k2.z, s); s = fmaf(q2.w, k2.w, s);
            s = fmaf(q3.x, k3.x, s); s = fmaf(q3.y, k3.y, s); s = fmaf(q3.z, k3.z, s); s = fmaf(q3.w, k3.w, s);
            s *= scale;
            float mN = fmaxf(m, s);
            float corr = __expf(m - mN);
            float p = __expf(s - mN);
            m = mN;
            l = fmaf(l, corr, p);
            const float4* vp = &Vs4[key * 5];
            float4 v0 = vp[0], v1 = vp[1], v2 = vp[2], v3 = vp[3];
            o0.x = fmaf(p, v0.x, o0.x * corr); o0.y = fmaf(p, v0.y, o0.y * corr);
            o0.z = fmaf(p, v0.z, o0.z * corr); o0.w = fmaf(p, v0.w, o0.w * corr);
            o1.x = fmaf(p, v1.x, o1.x * corr); o1.y = fmaf(p, v1.y, o1.y * corr);
            o1.z = fmaf(p, v1.z, o1.z * corr); o1.w = fmaf(p, v1.w, o1.w * corr);
            o2.x = fmaf(p, v2.x, o2.x * corr); o2.y = fmaf(p, v2.y, o2.y * corr);
            o2.z = fmaf(p, v2.z, o2.z * corr); o2.w = fmaf(p, v2.w, o2.w * corr);
            o3.x = fmaf(p, v3.x, o3.x * corr); o3.y = fmaf(p, v3.y, o3.y * corr);
            o3.z = fmaf(p, v3.z, o3.z * corr); o3.w = fmaf(p, v3.w, o3.w * corr);
        }

        // cross-lane merge
        float Mv = m;
#pragma unroll
        for (int off = 16; off; off >>= 1)
            Mv = fmaxf(Mv, __shfl_xor_sync(0xffffffffu, Mv, off));
        float sc = __expf(m - Mv);
        float Ls = l * sc;
#pragma unroll
        for (int off = 16; off; off >>= 1)
            Ls += __shfl_xor_sync(0xffffffffu, Ls, off);

        float ofl[16] = { o0.x*sc, o0.y*sc, o0.z*sc, o0.w*sc,
                          o1.x*sc, o1.y*sc, o1.z*sc, o1.w*sc,
                          o2.x*sc, o2.y*sc, o2.z*sc, o2.w*sc,
                          o3.x*sc, o3.y*sc, o3.z*sc, o3.w*sc };
        float myv = 0.f;
#pragma unroll
        for (int j = 0; j < 16; j++) {
            float t = ofl[j];
#pragma unroll
            for (int off = 16; off; off >>= 1)
                t += __shfl_xor_sync(0xffffffffu, t, off);
            if (lane == j) myv = t;
        }
        if (lane < 16)
            O[(b * SEQ + q) * DMODEL + h * DHEAD + lane] = myv / Ls;
    }
}

// ---------------- residual add + layernorm (row per warp) ------------------
__global__ void k_addln(const float* __restrict__ X, const float* __restrict__ R,
                        const float* __restrict__ g, const float* __restrict__ bta,
                        float* __restrict__ Y) {
    int wid = threadIdx.x >> 5, lane = threadIdx.x & 31;
    int i = blockIdx.x * 8 + wid;
    float4 v = ((const float4*)X)[i * 32 + lane];
    float4 r = ((const float4*)R)[i * 32 + lane];
    v.x += r.x; v.y += r.y; v.z += r.z; v.w += r.w;
    float s = v.x + v.y + v.z + v.w;
#pragma unroll
    for (int off = 16; off; off >>= 1) s += __shfl_xor_sync(0xffffffffu, s, off);
    float mu = s * (1.f / 128.f);
    float dx = v.x - mu, dy = v.y - mu, dz = v.z - mu, dw = v.w - mu;
    float ss = dx*dx + dy*dy + dz*dz + dw*dw;
#pragma unroll
    for (int off = 16; off; off >>= 1) ss += __shfl_xor_sync(0xffffffffu, ss, off);
    float inv = rsqrtf(ss * (1.f / 128.f) + 1e-5f);
    float4 gg = ((const float4*)g)[lane];
    float4 bb = ((const float4*)bta)[lane];
    float4 o;
    o.x = fmaf(dx * inv, gg.x, bb.x);
    o.y = fmaf(dy * inv, gg.y, bb.y);
    o.z = fmaf(dz * inv, gg.z, bb.z);
    o.w = fmaf(dw * inv, gg.w, bb.w);
    ((float4*)Y)[i * 32 + lane] = o;
}

// ---------------- host orchestration ---------------------------------------
extern "C" void kernel_launch(void* const* d_in, const int* in_sizes, int n_in,
                              void* d_out, int out_size) {
    const float* enc   = (const float*)d_in[0];
    const float* xraw  = (const float*)d_in[2];
    const int*   eidx  = (const int*)  d_in[3];
    const float* Wg1   = (const float*)d_in[4];
    const float* bg1   = (const float*)d_in[5];
    const float* Wg2   = (const float*)d_in[6];
    const float* bg2   = (const float*)d_in[7];
    const float* Wq    = (const float*)d_in[8];
    const float* Wk    = (const float*)d_in[9];
    const float* Wv    = (const float*)d_in[10];
    const float* Wo    = (const float*)d_in[11];
    const float* Wff1  = (const float*)d_in[12];
    const float* bff1  = (const float*)d_in[13];
    const float* Wff2  = (const float*)d_in[14];
    const float* bff2  = (const float*)d_in[15];
    const float* ln1g  = (const float*)d_in[16];
    const float* ln1b  = (const float*)d_in[17];
    const float* ln2g  = (const float*)d_in[18];
    const float* ln2b  = (const float*)d_in[19];
    float* outp = (float*)d_out;

    float *dinv, *h, *x1, *gx, *y, *Qb, *Kb, *Vb, *Ab, *Pb, *F1, *F2;
    int *counts, *rowoff, *cursor, *csr;
    cudaGetSymbolAddress((void**)&dinv,   g_dinv);
    cudaGetSymbolAddress((void**)&counts, g_counts);
    cudaGetSymbolAddress((void**)&rowoff, g_rowoff);
    cudaGetSymbolAddress((void**)&cursor, g_cursor);
    cudaGetSymbolAddress((void**)&csr,    g_csr);
    cudaGetSymbolAddress((void**)&h,  g_h);
    cudaGetSymbolAddress((void**)&x1, g_x1);
    cudaGetSymbolAddress((void**)&gx, g_gx);
    cudaGetSymbolAddress((void**)&y,  g_y);
    cudaGetSymbolAddress((void**)&Qb, g_Qb);
    cudaGetSymbolAddress((void**)&Kb, g_Kb);
    cudaGetSymbolAddress((void**)&Vb, g_Vb);
    cudaGetSymbolAddress((void**)&Ab, g_Ab);
    cudaGetSymbolAddress((void**)&Pb, g_Pb);
    cudaGetSymbolAddress((void**)&F1, g_F1);
    cudaGetSymbolAddress((void**)&F2, g_F2);

    cudaFuncSetAttribute(k_attn, cudaFuncAttributeMaxDynamicSharedMemorySize, 163840);

    const int ROWS = N_NODES;            // 32768 token/node rows, both streams

    // --- GCN preprocessing (CSR by dst, shared by both GCN layers) ---
    k_init_counts<<<N_NODES / 256, 256>>>(counts);
    k_count<<<N_EDGES / 256, 256>>>(eidx, counts);
    k_scan<<<1, 1024>>>(counts, rowoff, cursor, dinv);
    k_fill<<<NTOT / 256, 256>>>(eidx, cursor, csr);

    // --- GCN layer 1 ---
    k_gemm<<<dim3(ROWS / 64, 1), 256>>>(xraw, Wg1, nullptr, h, 128, 128, 0);
    k_aggregate<<<N_NODES / 8, 256>>>(h, dinv, rowoff, csr, bg1, x1);
    // --- GCN layer 2 ---
    k_gemm<<<dim3(ROWS / 64, 1), 256>>>(x1, Wg2, nullptr, h, 128, 128, 0);
    k_aggregate<<<N_NODES / 8, 256>>>(h, dinv, rowoff, csr, bg2, gx);

    // --- y = enc_out_vari ---
    cudaMemcpyAsync(y, enc, (size_t)ROWS * DMODEL * sizeof(float),
                    cudaMemcpyDeviceToDevice);

    for (int l = 0; l < 2; l++) {
        const float* wq = Wq + l * DMODEL * DMODEL;
        const float* wk = Wk + l * DMODEL * DMODEL;
        const float* wv = Wv + l * DMODEL * DMODEL;
        const float* wo = Wo + l * DMODEL * DMODEL;
        k_gemm<<<dim3(ROWS / 64, 1), 256>>>(y,  wq, nullptr, Qb, 128, 128, 0);
        k_gemm<<<dim3(ROWS / 64, 1), 256>>>(gx, wk, nullptr, Kb, 128, 128, 0);
        k_gemm<<<dim3(ROWS / 64, 1), 256>>>(gx, wv, nullptr, Vb, 128, 128, 0);
        k_attn<<<dim3(SEQ / 128, HEADS, BATCH), 512, 163840>>>(Qb, Kb, Vb, Ab);
        k_gemm<<<dim3(ROWS / 64, 1), 256>>>(Ab, wo, nullptr, Pb, 128, 128, 0);
        k_addln<<<ROWS / 8, 256>>>(y, Pb, ln1g + l * 128, ln1b + l * 128, y);
        k_gemm<<<dim3(ROWS / 64, DFF / 128), 256>>>(y, Wff1 + l * DMODEL * DFF,
                                                    bff1 + l * DFF, F1, 128, DFF, 1);
        k_gemm<<<dim3(ROWS / 64, 1), 256>>>(F1, Wff2 + l * DFF * DMODEL,
                                            bff2 + l * DMODEL, F2, DFF, 128, 0);
        float* dst = (l == 1) ? outp : y;
        k_addln<<<ROWS / 8, 256>>>(y, F2, ln2g + l * 128, ln2b + l * 128, dst);
    }
}

// round 3
// speedup vs baseline: 1.1526x; 1.1526x over previous
#include <cuda_runtime.h>
#include <cuda_bf16.h>
#include <math_constants.h>
#include <cstdint>

#define N_NODES 32768
#define N_EDGES 524288
#define DMODEL  128
#define BATCH   32
#define SEQ     1024
#define HEADS   8
#define DHEAD   16
#define DFF     512
#define NTOT    (N_EDGES + N_NODES)
#define WELEMS  425984           // total transposed-weight elements
#define AST     40               // smem row stride (bf16 elems), conflict-free

// ---------------- mma helpers (baseline ISA: ldmatrix + mma.sync) -----------
__device__ __forceinline__ uint32_t cvta_s(const void* p) {
    return (uint32_t)__cvta_generic_to_shared(p);
}
__device__ __forceinline__ void ldsm4(uint32_t* r, uint32_t a) {
    asm volatile("ldmatrix.sync.aligned.m8n8.x4.shared.b16 {%0,%1,%2,%3}, [%4];"
                 : "=r"(r[0]), "=r"(r[1]), "=r"(r[2]), "=r"(r[3]) : "r"(a));
}
__device__ __forceinline__ void mma_bf16(float* c, const uint32_t* a, const uint32_t* b) {
    asm volatile("mma.sync.aligned.m16n8k16.row.col.f32.bf16.bf16.f32 "
                 "{%0,%1,%2,%3}, {%4,%5,%6,%7}, {%8,%9}, {%0,%1,%2,%3};"
                 : "+f"(c[0]), "+f"(c[1]), "+f"(c[2]), "+f"(c[3])
                 : "r"(a[0]), "r"(a[1]), "r"(a[2]), "r"(a[3]), "r"(b[0]), "r"(b[1]));
}

// ---------------- scratch ----------------------------------------------------
static __device__ float g_dinv[N_NODES];
static __device__ int   g_counts[N_NODES];
static __device__ int   g_rowoff[N_NODES + 1];
static __device__ int   g_cursor[N_NODES];
static __device__ int   g_csr[NTOT];
static __device__ float g_h [N_NODES * DMODEL];
static __device__ float g_x1[N_NODES * DMODEL];
static __device__ float g_gx[N_NODES * DMODEL];
static __device__ float g_y [N_NODES * DMODEL];
static __device__ float g_Qb[N_NODES * DMODEL];
static __device__ float g_Kb[N_NODES * DMODEL];
static __device__ float g_Vb[N_NODES * DMODEL];
static __device__ float g_Ab[N_NODES * DMODEL];
static __device__ float g_Pb[N_NODES * DMODEL];
static __device__ float g_F1[N_NODES * DFF];
static __device__ float g_F2[N_NODES * DMODEL];
static __device__ __nv_bfloat16 g_whi[WELEMS];
static __device__ __nv_bfloat16 g_wlo[WELEMS];

// ---------------- graph preprocessing ---------------------------------------
__global__ void k_init_counts(int* counts) {
    counts[blockIdx.x * blockDim.x + threadIdx.x] = 0;
}
__global__ void k_count(const int* __restrict__ eidx, int* __restrict__ counts) {
    int e = blockIdx.x * blockDim.x + threadIdx.x;
    atomicAdd(&counts[eidx[N_EDGES + e]], 1);
}
__global__ void k_scan(const int* __restrict__ counts, int* __restrict__ rowoff,
                       int* __restrict__ cursor, float* __restrict__ dinv) {
    __shared__ int part[1024];
    int tid = threadIdx.x, base = tid * 32;
    int c[32], s = 0;
#pragma unroll
    for (int i = 0; i < 32; i++) { c[i] = counts[base + i] + 1; s += c[i]; }
    part[tid] = s;
    __syncthreads();
    for (int off = 1; off < 1024; off <<= 1) {
        int v = (tid >= off) ? part[tid - off] : 0;
        __syncthreads();
        part[tid] += v;
        __syncthreads();
    }
    int run = part[tid] - s;
#pragma unroll
    for (int i = 0; i < 32; i++) {
        rowoff[base + i] = run;
        cursor[base + i] = run;
        dinv[base + i] = rsqrtf((float)c[i]);
        run += c[i];
    }
    if (tid == 1023) rowoff[N_NODES] = run;
}
__global__ void k_fill(const int* __restrict__ eidx, int* __restrict__ cursor,
                       int* __restrict__ csr) {
    int e = blockIdx.x * blockDim.x + threadIdx.x;
    int s, d;
    if (e < N_EDGES) { s = eidx[e]; d = eidx[N_EDGES + e]; }
    else             { s = d = e - N_EDGES; }
    csr[atomicAdd(&cursor[d], 1)] = s;
}

__global__ void k_aggregate(const float* __restrict__ h, const float* __restrict__ dinv,
                            const int* __restrict__ rowoff, const int* __restrict__ csr,
                            const float* __restrict__ bias, float* __restrict__ out) {
    int wid = threadIdx.x >> 5, lane = threadIdx.x & 31;
    int i = blockIdx.x * 8 + wid;
    const float4* h4 = (const float4*)h;
    float4 acc = make_float4(0.f, 0.f, 0.f, 0.f);
    int e = rowoff[i], end = rowoff[i + 1];
    for (; e + 2 <= end; e += 2) {
        int s0 = csr[e], s1 = csr[e + 1];
        float w0 = dinv[s0], w1 = dinv[s1];
        float4 v0 = h4[s0 * 32 + lane];
        float4 v1 = h4[s1 * 32 + lane];
        acc.x = fmaf(w0, v0.x, fmaf(w1, v1.x, acc.x));
        acc.y = fmaf(w0, v0.y, fmaf(w1, v1.y, acc.y));
        acc.z = fmaf(w0, v0.z, fmaf(w1, v1.z, acc.z));
        acc.w = fmaf(w0, v0.w, fmaf(w1, v1.w, acc.w));
    }
    if (e < end) {
        int s0 = csr[e];
        float w0 = dinv[s0];
        float4 v0 = h4[s0 * 32 + lane];
        acc.x = fmaf(w0, v0.x, acc.x); acc.y = fmaf(w0, v0.y, acc.y);
        acc.z = fmaf(w0, v0.z, acc.z); acc.w = fmaf(w0, v0.w, acc.w);
    }
    float di = dinv[i];
    float4 b4 = ((const float4*)bias)[lane];
    float4 o;
    o.x = fmaxf(fmaf(di, acc.x, b4.x), 0.f);
    o.y = fmaxf(fmaf(di, acc.y, b4.y), 0.f);
    o.z = fmaxf(fmaf(di, acc.z, b4.z), 0.f);
    o.w = fmaxf(fmaf(di, acc.w, b4.w), 0.f);
    ((float4*)out)[i * 32 + lane] = o;
}

// ---------------- weight prep: W[K x N] -> Wt[n][k] bf16 hi/lo --------------
__global__ void k_prep_w(const float* __restrict__ W, __nv_bfloat16* __restrict__ hi,
                         __nv_bfloat16* __restrict__ lo, int K, int ncols) {
    int idx = blockIdx.x * 256 + threadIdx.x;
    int k = idx / ncols, n = idx % ncols;
    float v = W[idx];
    __nv_bfloat16 h = __float2bfloat16(v);
    __nv_bfloat16 l = __float2bfloat16(v - __bfloat162float(h));
    hi[n * K + k] = h;
    lo[n * K + k] = l;
}

// ---------------- tensor-core GEMM (mma.sync): C = A @ W  -------------------
// block 256 thr, tile 128x128, BK=32; warps 4(m) x 2(n), warp tile 32x64.
__global__ void __launch_bounds__(256)
k_gemm_tc(const float* __restrict__ A, const __nv_bfloat16* __restrict__ Whi,
          const __nv_bfloat16* __restrict__ Wlo, const float* __restrict__ bias,
          float* __restrict__ C, int K, int ncols, int act) {
    __shared__ __nv_bfloat16 As_hi[128 * AST];
    __shared__ __nv_bfloat16 As_lo[128 * AST];
    __shared__ __nv_bfloat16 Ws_hi[128 * AST];
    __shared__ __nv_bfloat16 Ws_lo[128 * AST];

    int tid = threadIdx.x, wid = tid >> 5, lane = tid & 31;
    int wm = wid & 3, wn = wid >> 2;           // warp tile (32 m, 64 n)
    int rowBase = blockIdx.x * 128, colBase = blockIdx.y * 128;

    float acc[2][8][4];
#pragma unroll
    for (int i = 0; i < 2; i++)
#pragma unroll
        for (int j = 0; j < 8; j++)
#pragma unroll
            for (int q = 0; q < 4; q++) acc[i][j][q] = 0.f;

    // per-lane ldmatrix offsets
    int ar = (lane & 7) + ((lane >> 3) & 1) * 8;   // a-frag row
    int ak = (lane >> 4) * 8;                      // a-frag col
    int bn = (lane & 7) + ((lane >> 4) & 1) * 8;   // b-frag n
    int bk = ((lane >> 3) & 1) * 8;                // b-frag k

    uint32_t sAh = cvta_s(As_hi), sAl = cvta_s(As_lo);
    uint32_t sWh = cvta_s(Ws_hi), sWl = cvta_s(Ws_lo);

    for (int kb = 0; kb < K; kb += 32) {
        // --- W tiles: straight bf16 copy (already [n][k]) ---
#pragma unroll
        for (int j = 0; j < 2; j++) {
            int i = tid + 256 * j;                 // 512 chunks of 8 bf16
            int n = i >> 2, c = i & 3;
            const uint4* src_h = (const uint4*)&Whi[(size_t)(colBase + n) * K + kb + c * 8];
            const uint4* src_l = (const uint4*)&Wlo[(size_t)(colBase + n) * K + kb + c * 8];
            *(uint4*)&Ws_hi[n * AST + c * 8] = *src_h;
            *(uint4*)&Ws_lo[n * AST + c * 8] = *src_l;
        }
        // --- A tile: fp32 -> bf16 hi/lo ---
#pragma unroll
        for (int j = 0; j < 4; j++) {
            int i = tid + 256 * j;                 // 1024 float4 chunks
            int r = i >> 3, c4 = i & 7;
            float4 a4 = *(const float4*)&A[(size_t)(rowBase + r) * K + kb + c4 * 4];
            __nv_bfloat16 h0 = __float2bfloat16(a4.x), h1 = __float2bfloat16(a4.y);
            __nv_bfloat16 h2 = __float2bfloat16(a4.z), h3 = __float2bfloat16(a4.w);
            __nv_bfloat16 l0 = __float2bfloat16(a4.x - __bfloat162float(h0));
            __nv_bfloat16 l1 = __float2bfloat16(a4.y - __bfloat162float(h1));
            __nv_bfloat16 l2 = __float2bfloat16(a4.z - __bfloat162float(h2));
            __nv_bfloat16 l3 = __float2bfloat16(a4.w - __bfloat162float(h3));
            uint2 ph, pl;
            ph.x = ((uint32_t)__bfloat16_as_ushort(h1) << 16) | __bfloat16_as_ushort(h0);
            ph.y = ((uint32_t)__bfloat16_as_ushort(h3) << 16) | __bfloat16_as_ushort(h2);
            pl.x = ((uint32_t)__bfloat16_as_ushort(l1) << 16) | __bfloat16_as_ushort(l0);
            pl.y = ((uint32_t)__bfloat16_as_ushort(l3) << 16) | __bfloat16_as_ushort(l2);
            *(uint2*)&As_hi[r * AST + c4 * 4] = ph;
            *(uint2*)&As_lo[r * AST + c4 * 4] = pl;
        }
        __syncthreads();

#pragma unroll
        for (int ks = 0; ks < 32; ks += 16) {
            uint32_t ah[2][4], al[2][4];
#pragma unroll
            for (int ma = 0; ma < 2; ma++) {
                uint32_t off = (uint32_t)((wm * 32 + ma * 16 + ar) * AST + ks + ak) * 2;
                ldsm4(ah[ma], sAh + off);
                ldsm4(al[ma], sAl + off);
            }
            uint32_t bh[4][4], bl[4][4];
#pragma unroll
            for (int nb = 0; nb < 4; nb++) {
                uint32_t off = (uint32_t)((wn * 64 + nb * 16 + bn) * AST + ks + bk) * 2;
                ldsm4(bh[nb], sWh + off);
                ldsm4(bl[nb], sWl + off);
            }
#pragma unroll
            for (int ma = 0; ma < 2; ma++)
#pragma unroll
                for (int na = 0; na < 8; na++) {
                    float* c = acc[ma][na];
                    const uint32_t* pbh = &bh[na >> 1][(na & 1) * 2];
                    const uint32_t* pbl = &bl[na >> 1][(na & 1) * 2];
                    mma_bf16(c, ah[ma], pbh);
                    mma_bf16(c, ah[ma], pbl);
                    mma_bf16(c, al[ma], pbh);
                }
        }
        __syncthreads();
    }

    // --- epilogue ---
#pragma unroll
    for (int ma = 0; ma < 2; ma++)
#pragma unroll
        for (int na = 0; na < 8; na++) {
            int row = rowBase + wm * 32 + ma * 16 + (lane >> 2);
            int col = colBase + wn * 64 + na * 8 + (lane & 3) * 2;
            float b0 = 0.f, b1 = 0.f;
            if (bias) { b0 = bias[col]; b1 = bias[col + 1]; }
            float v0 = acc[ma][na][0] + b0, v1 = acc[ma][na][1] + b1;
            float v2 = acc[ma][na][2] + b0, v3 = acc[ma][na][3] + b1;
            if (act) {
                v0 = fmaxf(v0, 0.f); v1 = fmaxf(v1, 0.f);
                v2 = fmaxf(v2, 0.f); v3 = fmaxf(v3, 0.f);
            }
            *(float2*)&C[(size_t)row * ncols + col] = make_float2(v0, v1);
            *(float2*)&C[(size_t)(row + 8) * ncols + col] = make_float2(v2, v3);
        }
}

// ---------------- attention ---------------------------------------------------
__global__ void k_attn(const float* __restrict__ Q, const float* __restrict__ Kg,
                       const float* __restrict__ Vg, float* __restrict__ O) {
    extern __shared__ float4 sm[];
    float4* Ks4 = sm;
    float4* Vs4 = sm + 1024 * 5;
    int b = blockIdx.z, h = blockIdx.y;
    int tid = threadIdx.x, wid = tid >> 5, lane = tid & 31;
    const float4* Kg4 = (const float4*)Kg;
    const float4* Vg4 = (const float4*)Vg;
    const float4* Qg4 = (const float4*)Q;

#pragma unroll
    for (int t = 0; t < 8; t++) {
        int idx = tid + 512 * t;
        int key = idx >> 2, c = idx & 3;
        int gi = (b * SEQ + key) * 32 + h * 4 + c;
        Ks4[key * 5 + c] = Kg4[gi];
        Vs4[key * 5 + c] = Vg4[gi];
    }
    __syncthreads();

    const float scale = 0.25f;
    for (int qq = 0; qq < 8; qq++) {
        int q = blockIdx.x * 128 + wid * 8 + qq;
        int qb4 = (b * SEQ + q) * 32 + h * 4;
        float4 q0 = Qg4[qb4 + 0], q1 = Qg4[qb4 + 1], q2 = Qg4[qb4 + 2], q3 = Qg4[qb4 + 3];

        float m = -CUDART_INF_F, l = 0.f;
        float4 o0 = make_float4(0, 0, 0, 0), o1 = o0, o2 = o0, o3 = o0;

#pragma unroll 4
        for (int it = 0; it < 32; it++) {
            int key = lane + it * 32;
            const float4* kp = &Ks4[key * 5];
            float4 k0 = kp[0], k1 = kp[1], k2 = kp[2], k3 = kp[3];
            float s;
            s = q0.x * k0.x;
            s = fmaf(q0.y, k0.y, s); s = fmaf(q0.z, k0.z, s); s = fmaf(q0.w, k0.w, s);
            s = fmaf(q1.x, k1.x, s); s = fmaf(q1.y, k1.y, s); s = fmaf(q1.z, k1.z, s); s = fmaf(q1.w, k1.w, s);
            s = fmaf(q2.x, k2.x, s); s = fmaf(q2.y, k2.y, s); s = fmaf(q2.z, k2.z, s); s = fmaf(q2.w, k2.w, s);
            s = fmaf(q3.x, k3.x, s); s = fmaf(q3.y, k3.y, s); s = fmaf(q3.z, k3.z, s); s = fmaf(q3.w, k3.w, s);
            s *= scale;
            float mN = fmaxf(m, s);
            float corr = __expf(m - mN);
            float p = __expf(s - mN);
            m = mN;
            l = fmaf(l, corr, p);
            const float4* vp = &Vs4[key * 5];
            float4 v0 = vp[0], v1 = vp[1], v2 = vp[2], v3 = vp[3];
            o0.x = fmaf(p, v0.x, o0.x * corr); o0.y = fmaf(p, v0.y, o0.y * corr);
            o0.z = fmaf(p, v0.z, o0.z * corr); o0.w = fmaf(p, v0.w, o0.w * corr);
            o1.x = fmaf(p, v1.x, o1.x * corr); o1.y = fmaf(p, v1.y, o1.y * corr);
            o1.z = fmaf(p, v1.z, o1.z * corr); o1.w = fmaf(p, v1.w, o1.w * corr);
            o2.x = fmaf(p, v2.x, o2.x * corr); o2.y = fmaf(p, v2.y, o2.y * corr);
            o2.z = fmaf(p, v2.z, o2.z * corr); o2.w = fmaf(p, v2.w, o2.w * corr);
            o3.x = fmaf(p, v3.x, o3.x * corr); o3.y = fmaf(p, v3.y, o3.y * corr);
            o3.z = fmaf(p, v3.z, o3.z * corr); o3.w = fmaf(p, v3.w, o3.w * corr);
        }

        float Mv = m;
#pragma unroll
        for (int off = 16; off; off >>= 1)
            Mv = fmaxf(Mv, __shfl_xor_sync(0xffffffffu, Mv, off));
        float sc = __expf(m - Mv);
        float Ls = l * sc;
#pragma unroll
        for (int off = 16; off; off >>= 1)
            Ls += __shfl_xor_sync(0xffffffffu, Ls, off);

        float ofl[16] = { o0.x*sc, o0.y*sc, o0.z*sc, o0.w*sc,
                          o1.x*sc, o1.y*sc, o1.z*sc, o1.w*sc,
                          o2.x*sc, o2.y*sc, o2.z*sc, o2.w*sc,
                          o3.x*sc, o3.y*sc, o3.z*sc, o3.w*sc };
        float myv = 0.f;
#pragma unroll
        for (int j = 0; j < 16; j++) {
            float t = ofl[j];
#pragma unroll
            for (int off = 16; off; off >>= 1)
                t += __shfl_xor_sync(0xffffffffu, t, off);
            if (lane == j) myv = t;
        }
        if (lane < 16)
            O[(b * SEQ + q) * DMODEL + h * DHEAD + lane] = myv / Ls;
    }
}

// ---------------- residual add + layernorm -----------------------------------
__global__ void k_addln(const float* __restrict__ X, const float* __restrict__ R,
                        const float* __restrict__ g, const float* __restrict__ bta,
                        float* __restrict__ Y) {
    int wid = threadIdx.x >> 5, lane = threadIdx.x & 31;
    int i = blockIdx.x * 8 + wid;
    float4 v = ((const float4*)X)[i * 32 + lane];
    float4 r = ((const float4*)R)[i * 32 + lane];
    v.x += r.x; v.y += r.y; v.z += r.z; v.w += r.w;
    float s = v.x + v.y + v.z + v.w;
#pragma unroll
    for (int off = 16; off; off >>= 1) s += __shfl_xor_sync(0xffffffffu, s, off);
    float mu = s * (1.f / 128.f);
    float dx = v.x - mu, dy = v.y - mu, dz = v.z - mu, dw = v.w - mu;
    float ss = dx*dx + dy*dy + dz*dz + dw*dw;
#pragma unroll
    for (int off = 16; off; off >>= 1) ss += __shfl_xor_sync(0xffffffffu, ss, off);
    float inv = rsqrtf(ss * (1.f / 128.f) + 1e-5f);
    float4 gg = ((const float4*)g)[lane];
    float4 bb = ((const float4*)bta)[lane];
    float4 o;
    o.x = fmaf(dx * inv, gg.x, bb.x);
    o.y = fmaf(dy * inv, gg.y, bb.y);
    o.z = fmaf(dz * inv, gg.z, bb.z);
    o.w = fmaf(dw * inv, gg.w, bb.w);
    ((float4*)Y)[i * 32 + lane] = o;
}

// ---------------- host orchestration -----------------------------------------
extern "C" void kernel_launch(void* const* d_in, const int* in_sizes, int n_in,
                              void* d_out, int out_size) {
    const float* enc   = (const float*)d_in[0];
    const float* xraw  = (const float*)d_in[2];
    const int*   eidx  = (const int*)  d_in[3];
    const float* Wg1   = (const float*)d_in[4];
    const float* bg1   = (const float*)d_in[5];
    const float* Wg2   = (const float*)d_in[6];
    const float* bg2   = (const float*)d_in[7];
    const float* Wq    = (const float*)d_in[8];
    const float* Wk    = (const float*)d_in[9];
    const float* Wv    = (const float*)d_in[10];
    const float* Wo    = (const float*)d_in[11];
    const float* Wff1  = (const float*)d_in[12];
    const float* bff1  = (const float*)d_in[13];
    const float* Wff2  = (const float*)d_in[14];
    const float* bff2  = (const float*)d_in[15];
    const float* ln1g  = (const float*)d_in[16];
    const float* ln1b  = (const float*)d_in[17];
    const float* ln2g  = (const float*)d_in[18];
    const float* ln2b  = (const float*)d_in[19];
    float* outp = (float*)d_out;

    float *dinv, *h, *x1, *gx, *y, *Qb, *Kb, *Vb, *Ab, *Pb, *F1, *F2;
    int *counts, *rowoff, *cursor, *csr;
    __nv_bfloat16 *whi, *wlo;
    cudaGetSymbolAddress((void**)&dinv,   g_dinv);
    cudaGetSymbolAddress((void**)&counts, g_counts);
    cudaGetSymbolAddress((void**)&rowoff, g_rowoff);
    cudaGetSymbolAddress((void**)&cursor, g_cursor);
    cudaGetSymbolAddress((void**)&csr,    g_csr);
    cudaGetSymbolAddress((void**)&h,  g_h);
    cudaGetSymbolAddress((void**)&x1, g_x1);
    cudaGetSymbolAddress((void**)&gx, g_gx);
    cudaGetSymbolAddress((void**)&y,  g_y);
    cudaGetSymbolAddress((void**)&Qb, g_Qb);
    cudaGetSymbolAddress((void**)&Kb, g_Kb);
    cudaGetSymbolAddress((void**)&Vb, g_Vb);
    cudaGetSymbolAddress((void**)&Ab, g_Ab);
    cudaGetSymbolAddress((void**)&Pb, g_Pb);
    cudaGetSymbolAddress((void**)&F1, g_F1);
    cudaGetSymbolAddress((void**)&F2, g_F2);
    cudaGetSymbolAddress((void**)&whi, g_whi);
    cudaGetSymbolAddress((void**)&wlo, g_wlo);

    cudaFuncSetAttribute(k_attn, cudaFuncAttributeMaxDynamicSharedMemorySize, 163840);

    const int ROWS = N_NODES;

    // transposed weight offsets (elements)
    const size_t OFF_G1 = 0, OFF_G2 = 16384;
    const size_t LSTR = 4 * 16384 + 2 * 65536;          // per-layer stride
    auto offQ  = [&](int l) { return 32768 + (size_t)l * LSTR; };
    auto offK  = [&](int l) { return offQ(l) + 16384; };
    auto offV  = [&](int l) { return offQ(l) + 32768; };
    auto offO  = [&](int l) { return offQ(l) + 49152; };
    auto offF1 = [&](int l) { return offQ(l) + 65536; };
    auto offF2 = [&](int l) { return offQ(l) + 131072; };

    // --- weight prep ---
    k_prep_w<<<64, 256>>>(Wg1, whi + OFF_G1, wlo + OFF_G1, 128, 128);
    k_prep_w<<<64, 256>>>(Wg2, whi + OFF_G2, wlo + OFF_G2, 128, 128);
    for (int l = 0; l < 2; l++) {
        k_prep_w<<<64, 256>>>(Wq + l * 16384, whi + offQ(l), wlo + offQ(l), 128, 128);
        k_prep_w<<<64, 256>>>(Wk + l * 16384, whi + offK(l), wlo + offK(l), 128, 128);
        k_prep_w<<<64, 256>>>(Wv + l * 16384, whi + offV(l), wlo + offV(l), 128, 128);
        k_prep_w<<<64, 256>>>(Wo + l * 16384, whi + offO(l), wlo + offO(l), 128, 128);
        k_prep_w<<<256, 256>>>(Wff1 + l * 65536, whi + offF1(l), wlo + offF1(l), 128, 512);
        k_prep_w<<<256, 256>>>(Wff2 + l * 65536, whi + offF2(l), wlo + offF2(l), 512, 128);
    }

    auto GEMM = [&](const float* A, size_t woff, const float* bias, float* C,
                    int K, int ncols, int act) {
        dim3 g(ROWS / 128, ncols / 128);
        k_gemm_tc<<<g, 256>>>(A, whi + woff, wlo + woff, bias, C, K, ncols, act);
    };

    // --- GCN preprocessing ---
    k_init_counts<<<N_NODES / 256, 256>>>(counts);
    k_count<<<N_EDGES / 256, 256>>>(eidx, counts);
    k_scan<<<1, 1024>>>(counts, rowoff, cursor, dinv);
    k_fill<<<NTOT / 256, 256>>>(eidx, cursor, csr);

    // --- GCN stack ---
    GEMM(xraw, OFF_G1, nullptr, h, 128, 128, 0);
    k_aggregate<<<N_NODES / 8, 256>>>(h, dinv, rowoff, csr, bg1, x1);
    GEMM(x1, OFF_G2, nullptr, h, 128, 128, 0);
    k_aggregate<<<N_NODES / 8, 256>>>(h, dinv, rowoff, csr, bg2, gx);

    cudaMemcpyAsync(y, enc, (size_t)ROWS * DMODEL * sizeof(float),
                    cudaMemcpyDeviceToDevice);

    for (int l = 0; l < 2; l++) {
        GEMM(y,  offQ(l), nullptr, Qb, 128, 128, 0);
        GEMM(gx, offK(l), nullptr, Kb, 128, 128, 0);
        GEMM(gx, offV(l), nullptr, Vb, 128, 128, 0);
        k_attn<<<dim3(SEQ / 128, HEADS, BATCH), 512, 163840>>>(Qb, Kb, Vb, Ab);
        GEMM(Ab, offO(l), nullptr, Pb, 128, 128, 0);
        k_addln<<<ROWS / 8, 256>>>(y, Pb, ln1g + l * 128, ln1b + l * 128, y);
        GEMM(y, offF1(l), bff1 + l * DFF, F1, 128, DFF, 1);
        GEMM(F1, offF2(l), bff2 + l * DMODEL, F2, DFF, 128, 0);
        float* dst = (l == 1) ? outp : y;
        k_addln<<<ROWS / 8, 256>>>(y, F2, ln2g + l * 128, ln2b + l * 128, dst);
    }
}

// round 4
// speedup vs baseline: 2.3795x; 2.0644x over previous
#include <cuda_runtime.h>
#include <cuda_bf16.h>
#include <math_constants.h>
#include <cstdint>

#define N_NODES 32768
#define N_EDGES 524288
#define DMODEL  128
#define BATCH   32
#define SEQ     1024
#define HEADS   8
#define DFF     512
#define NTOT    (N_EDGES + N_NODES)
#define WELEMS  425984
#define GST     72               // gemm smem row stride (bf16), conflict-free
#define QST     24               // attn smem row stride (bf16), conflict-free
#define SCALE   0.25f

// ---------------- mma helpers ------------------------------------------------
__device__ __forceinline__ uint32_t cvta_s(const void* p) {
    return (uint32_t)__cvta_generic_to_shared(p);
}
__device__ __forceinline__ void ldsm4(uint32_t* r, uint32_t a) {
    asm volatile("ldmatrix.sync.aligned.m8n8.x4.shared.b16 {%0,%1,%2,%3}, [%4];"
                 : "=r"(r[0]), "=r"(r[1]), "=r"(r[2]), "=r"(r[3]) : "r"(a));
}
__device__ __forceinline__ void ldsm4t(uint32_t* r, uint32_t a) {
    asm volatile("ldmatrix.sync.aligned.m8n8.x4.trans.shared.b16 {%0,%1,%2,%3}, [%4];"
                 : "=r"(r[0]), "=r"(r[1]), "=r"(r[2]), "=r"(r[3]) : "r"(a));
}
__device__ __forceinline__ void mma_bf16(float* c, const uint32_t* a, const uint32_t* b) {
    asm volatile("mma.sync.aligned.m16n8k16.row.col.f32.bf16.bf16.f32 "
                 "{%0,%1,%2,%3}, {%4,%5,%6,%7}, {%8,%9}, {%0,%1,%2,%3};"
                 : "+f"(c[0]), "+f"(c[1]), "+f"(c[2]), "+f"(c[3])
                 : "r"(a[0]), "r"(a[1]), "r"(a[2]), "r"(a[3]), "r"(b[0]), "r"(b[1]));
}
__device__ __forceinline__ uint32_t cvt2bf(float lo, float hi) {
    uint32_t r;
    asm("cvt.rn.bf16x2.f32 %0, %1, %2;" : "=r"(r) : "f"(hi), "f"(lo));
    return r;
}
__device__ __forceinline__ void split_pack(float a, float b, uint32_t& hi, uint32_t& lo) {
    __nv_bfloat16 ha = __float2bfloat16(a), hb = __float2bfloat16(b);
    float ra = a - __bfloat162float(ha), rb = b - __bfloat162float(hb);
    __nv_bfloat16 la = __float2bfloat16(ra), lb = __float2bfloat16(rb);
    hi = ((uint32_t)__bfloat16_as_ushort(hb) << 16) | __bfloat16_as_ushort(ha);
    lo = ((uint32_t)__bfloat16_as_ushort(lb) << 16) | __bfloat16_as_ushort(la);
}

// ---------------- scratch ----------------------------------------------------
static __device__ float g_dinv[N_NODES];
static __device__ int   g_counts[N_NODES];
static __device__ int   g_rowoff[N_NODES + 1];
static __device__ int   g_cursor[N_NODES];
static __device__ int   g_csr[NTOT];
static __device__ float g_h [N_NODES * DMODEL];
static __device__ float g_y [N_NODES * DMODEL];
static __device__ float g_Pb[N_NODES * DMODEL];
static __device__ float g_F2[N_NODES * DMODEL];
static __device__ __nv_bfloat16 g_whi[WELEMS];
static __device__ __nv_bfloat16 g_wlo[WELEMS];
static __device__ __nv_bfloat16 g_xrhi[N_NODES * DMODEL];
static __device__ __nv_bfloat16 g_xrlo[N_NODES * DMODEL];
static __device__ __nv_bfloat16 g_x1hi[N_NODES * DMODEL];
static __device__ __nv_bfloat16 g_x1lo[N_NODES * DMODEL];
static __device__ __nv_bfloat16 g_gxhi[N_NODES * DMODEL];
static __device__ __nv_bfloat16 g_gxlo[N_NODES * DMODEL];
static __device__ __nv_bfloat16 g_yhi[N_NODES * DMODEL];
static __device__ __nv_bfloat16 g_ylo[N_NODES * DMODEL];
static __device__ __nv_bfloat16 g_Qbb[N_NODES * DMODEL];
static __device__ __nv_bfloat16 g_Kbb[N_NODES * DMODEL];
static __device__ __nv_bfloat16 g_Vbb[N_NODES * DMODEL];
static __device__ __nv_bfloat16 g_Abhi[N_NODES * DMODEL];
static __device__ __nv_bfloat16 g_Ablo[N_NODES * DMODEL];
static __device__ __nv_bfloat16 g_F1hi[N_NODES * DFF];
static __device__ __nv_bfloat16 g_F1lo[N_NODES * DFF];

// ---------------- graph preprocessing ---------------------------------------
__global__ void k_init_counts(int* counts) {
    counts[blockIdx.x * blockDim.x + threadIdx.x] = 0;
}
__global__ void k_count(const int* __restrict__ eidx, int* __restrict__ counts) {
    int e = blockIdx.x * blockDim.x + threadIdx.x;
    atomicAdd(&counts[eidx[N_EDGES + e]], 1);
}
__global__ void k_scan(const int* __restrict__ counts, int* __restrict__ rowoff,
                       int* __restrict__ cursor, float* __restrict__ dinv) {
    __shared__ int part[1024];
    int tid = threadIdx.x, base = tid * 32;
    int c[32], s = 0;
#pragma unroll
    for (int i = 0; i < 32; i++) { c[i] = counts[base + i] + 1; s += c[i]; }
    part[tid] = s;
    __syncthreads();
    for (int off = 1; off < 1024; off <<= 1) {
        int v = (tid >= off) ? part[tid - off] : 0;
        __syncthreads();
        part[tid] += v;
        __syncthreads();
    }
    int run = part[tid] - s;
#pragma unroll
    for (int i = 0; i < 32; i++) {
        rowoff[base + i] = run;
        cursor[base + i] = run;
        dinv[base + i] = rsqrtf((float)c[i]);
        run += c[i];
    }
    if (tid == 1023) rowoff[N_NODES] = run;
}
__global__ void k_fill(const int* __restrict__ eidx, int* __restrict__ cursor,
                       int* __restrict__ csr) {
    int e = blockIdx.x * blockDim.x + threadIdx.x;
    int s, d;
    if (e < N_EDGES) { s = eidx[e]; d = eidx[N_EDGES + e]; }
    else             { s = d = e - N_EDGES; }
    csr[atomicAdd(&cursor[d], 1)] = s;
}

// aggregate: fp32 gather-sum, emits bf16 hi/lo directly
__global__ void k_aggregate(const float* __restrict__ h, const float* __restrict__ dinv,
                            const int* __restrict__ rowoff, const int* __restrict__ csr,
                            const float* __restrict__ bias,
                            __nv_bfloat16* __restrict__ ohi, __nv_bfloat16* __restrict__ olo) {
    int wid = threadIdx.x >> 5, lane = threadIdx.x & 31;
    int i = blockIdx.x * 8 + wid;
    const float4* h4 = (const float4*)h;
    float4 acc = make_float4(0.f, 0.f, 0.f, 0.f);
    int e = rowoff[i], end = rowoff[i + 1];
    for (; e + 2 <= end; e += 2) {
        int s0 = csr[e], s1 = csr[e + 1];
        float w0 = dinv[s0], w1 = dinv[s1];
        float4 v0 = h4[s0 * 32 + lane];
        float4 v1 = h4[s1 * 32 + lane];
        acc.x = fmaf(w0, v0.x, fmaf(w1, v1.x, acc.x));
        acc.y = fmaf(w0, v0.y, fmaf(w1, v1.y, acc.y));
        acc.z = fmaf(w0, v0.z, fmaf(w1, v1.z, acc.z));
        acc.w = fmaf(w0, v0.w, fmaf(w1, v1.w, acc.w));
    }
    if (e < end) {
        int s0 = csr[e];
        float w0 = dinv[s0];
        float4 v0 = h4[s0 * 32 + lane];
        acc.x = fmaf(w0, v0.x, acc.x); acc.y = fmaf(w0, v0.y, acc.y);
        acc.z = fmaf(w0, v0.z, acc.z); acc.w = fmaf(w0, v0.w, acc.w);
    }
    float di = dinv[i];
    float4 b4 = ((const float4*)bias)[lane];
    float o0 = fmaxf(fmaf(di, acc.x, b4.x), 0.f);
    float o1 = fmaxf(fmaf(di, acc.y, b4.y), 0.f);
    float o2 = fmaxf(fmaf(di, acc.z, b4.z), 0.f);
    float o3 = fmaxf(fmaf(di, acc.w, b4.w), 0.f);
    uint2 hh, ll;
    split_pack(o0, o1, hh.x, ll.x);
    split_pack(o2, o3, hh.y, ll.y);
    *(uint2*)&ohi[(size_t)i * DMODEL + lane * 4] = hh;
    *(uint2*)&olo[(size_t)i * DMODEL + lane * 4] = ll;
}

// fp32 -> bf16 hi/lo elementwise
__global__ void k_cvt(const float* __restrict__ src, __nv_bfloat16* __restrict__ hi,
                      __nv_bfloat16* __restrict__ lo) {
    int i = blockIdx.x * blockDim.x + threadIdx.x;
    float4 v = ((const float4*)src)[i];
    uint2 hh, ll;
    split_pack(v.x, v.y, hh.x, ll.x);
    split_pack(v.z, v.w, hh.y, ll.y);
    ((uint2*)hi)[i] = hh;
    ((uint2*)lo)[i] = ll;
}

// weight prep: W[K x N] -> Wt[n][k] bf16 hi/lo
__global__ void k_prep_w(const float* __restrict__ W, __nv_bfloat16* __restrict__ hi,
                         __nv_bfloat16* __restrict__ lo, int K, int ncols) {
    int idx = blockIdx.x * 256 + threadIdx.x;
    int k = idx / ncols, n = idx % ncols;
    float v = W[idx];
    __nv_bfloat16 h = __float2bfloat16(v);
    __nv_bfloat16 l = __float2bfloat16(v - __bfloat162float(h));
    hi[n * K + k] = h;
    lo[n * K + k] = l;
}

// ---------------- tensor-core GEMM, A pre-split bf16 -------------------------
// block 256, tile 128x128, BK=64; warps 4(m)x2(n). out modes: fp32 / bf16 / hi-lo
#define GT_SMEM (4 * 128 * GST * 2)
__global__ void __launch_bounds__(256)
k_gemm_tc(const __nv_bfloat16* __restrict__ Ahi, const __nv_bfloat16* __restrict__ Alo,
          const __nv_bfloat16* __restrict__ Whi, const __nv_bfloat16* __restrict__ Wlo,
          const float* __restrict__ bias, float* __restrict__ Cf,
          __nv_bfloat16* __restrict__ Cb, __nv_bfloat16* __restrict__ Chi,
          __nv_bfloat16* __restrict__ Clo, int K, int ncols, int act) {
    extern __shared__ char smem[];
    __nv_bfloat16* As_hi = (__nv_bfloat16*)smem;
    __nv_bfloat16* As_lo = (__nv_bfloat16*)(smem + 128 * GST * 2);
    __nv_bfloat16* Ws_hi = (__nv_bfloat16*)(smem + 2 * 128 * GST * 2);
    __nv_bfloat16* Ws_lo = (__nv_bfloat16*)(smem + 3 * 128 * GST * 2);

    int tid = threadIdx.x, wid = tid >> 5, lane = tid & 31;
    int wm = wid & 3, wn = wid >> 2;
    int rowBase = blockIdx.x * 128, colBase = blockIdx.y * 128;

    float acc[2][8][4];
#pragma unroll
    for (int i = 0; i < 2; i++)
#pragma unroll
        for (int j = 0; j < 8; j++)
#pragma unroll
            for (int q = 0; q < 4; q++) acc[i][j][q] = 0.f;

    int ar = (lane & 7) + ((lane >> 3) & 1) * 8;
    int ak = (lane >> 4) * 8;
    int bn = (lane & 7) + ((lane >> 4) & 1) * 8;
    int bk = ((lane >> 3) & 1) * 8;

    uint32_t sAh = cvta_s(As_hi), sAl = cvta_s(As_lo);
    uint32_t sWh = cvta_s(Ws_hi), sWl = cvta_s(Ws_lo);

    for (int kb = 0; kb < K; kb += 64) {
#pragma unroll
        for (int j = 0; j < 4; j++) {
            int i = tid + 256 * j;
            int r = i >> 3, c = i & 7;
            *(uint4*)&As_hi[r * GST + c * 8] = *(const uint4*)&Ahi[(size_t)(rowBase + r) * K + kb + c * 8];
            *(uint4*)&As_lo[r * GST + c * 8] = *(const uint4*)&Alo[(size_t)(rowBase + r) * K + kb + c * 8];
            *(uint4*)&Ws_hi[r * GST + c * 8] = *(const uint4*)&Whi[(size_t)(colBase + r) * K + kb + c * 8];
            *(uint4*)&Ws_lo[r * GST + c * 8] = *(const uint4*)&Wlo[(size_t)(colBase + r) * K + kb + c * 8];
        }
        __syncthreads();

#pragma unroll
        for (int ks = 0; ks < 64; ks += 16) {
            uint32_t ah[2][4], al[2][4];
#pragma unroll
            for (int ma = 0; ma < 2; ma++) {
                uint32_t off = (uint32_t)((wm * 32 + ma * 16 + ar) * GST + ks + ak) * 2;
                ldsm4(ah[ma], sAh + off);
                ldsm4(al[ma], sAl + off);
            }
            uint32_t bh[4][4], bl[4][4];
#pragma unroll
            for (int nb = 0; nb < 4; nb++) {
                uint32_t off = (uint32_t)((wn * 64 + nb * 16 + bn) * GST + ks + bk) * 2;
                ldsm4(bh[nb], sWh + off);
                ldsm4(bl[nb], sWl + off);
            }
#pragma unroll
            for (int ma = 0; ma < 2; ma++)
#pragma unroll
                for (int na = 0; na < 8; na++) {
                    float* c = acc[ma][na];
                    const uint32_t* pbh = &bh[na >> 1][(na & 1) * 2];
                    const uint32_t* pbl = &bl[na >> 1][(na & 1) * 2];
                    mma_bf16(c, ah[ma], pbh);
                    mma_bf16(c, ah[ma], pbl);
                    mma_bf16(c, al[ma], pbh);
                }
        }
        __syncthreads();
    }

#pragma unroll
    for (int ma = 0; ma < 2; ma++)
#pragma unroll
        for (int na = 0; na < 8; na++) {
            int row = rowBase + wm * 32 + ma * 16 + (lane >> 2);
            int col = colBase + wn * 64 + na * 8 + (lane & 3) * 2;
            float b0 = 0.f, b1 = 0.f;
            if (bias) { b0 = bias[col]; b1 = bias[col + 1]; }
            float v0 = acc[ma][na][0] + b0, v1 = acc[ma][na][1] + b1;
            float v2 = acc[ma][na][2] + b0, v3 = acc[ma][na][3] + b1;
            if (act) {
                v0 = fmaxf(v0, 0.f); v1 = fmaxf(v1, 0.f);
                v2 = fmaxf(v2, 0.f); v3 = fmaxf(v3, 0.f);
            }
            size_t i0 = (size_t)row * ncols + col, i1 = (size_t)(row + 8) * ncols + col;
            if (Cf) {
                *(float2*)&Cf[i0] = make_float2(v0, v1);
                *(float2*)&Cf[i1] = make_float2(v2, v3);
            }
            if (Cb) {
                *(uint32_t*)&Cb[i0] = cvt2bf(v0, v1);
                *(uint32_t*)&Cb[i1] = cvt2bf(v2, v3);
            }
            if (Chi) {
                uint32_t h0, l0, h1, l1;
                split_pack(v0, v1, h0, l0);
                split_pack(v2, v3, h1, l1);
                *(uint32_t*)&Chi[i0] = h0; *(uint32_t*)&Clo[i0] = l0;
                *(uint32_t*)&Chi[i1] = h1; *(uint32_t*)&Clo[i1] = l1;
            }
        }
}

// ---------------- flash attention (mma.sync, bf16) ---------------------------
// grid (8 qtiles, 8 heads, 32 batch), block 128 (4 warps x 32 q-rows), KT=64.
__global__ void __launch_bounds__(128, 2)
k_attn_tc(const __nv_bfloat16* __restrict__ Qb, const __nv_bfloat16* __restrict__ Kb,
          const __nv_bfloat16* __restrict__ Vb,
          __nv_bfloat16* __restrict__ Ohi, __nv_bfloat16* __restrict__ Olo) {
    __shared__ __nv_bfloat16 sQ[128 * QST];
    __shared__ __nv_bfloat16 sK[64 * QST];
    __shared__ __nv_bfloat16 sV[64 * QST];

    int b = blockIdx.z, hd = blockIdx.y, qbase = blockIdx.x * 128;
    int tid = threadIdx.x, wm = tid >> 5, lane = tid & 31;

    // stage Q (rows 128 x 16 bf16)
#pragma unroll
    for (int j = 0; j < 2; j++) {
        int i = tid + 128 * j;
        int row = i >> 1, half = i & 1;
        *(uint4*)&sQ[row * QST + half * 8] =
            *(const uint4*)&Qb[(size_t)(b * SEQ + qbase + row) * DMODEL + hd * 16 + half * 8];
    }
    __syncthreads();

    int ar = (lane & 7) + ((lane >> 3) & 1) * 8;
    int ak = (lane >> 4) * 8;
    int bn = (lane & 7) + ((lane >> 4) & 1) * 8;   // non-trans B row sel
    int bk = ((lane >> 3) & 1) * 8;
    // trans-V lane address: storage row = key, col = dh
    int vkey = (lane & 7) + ((lane >> 3) & 1) * 8;
    int vdh = ((lane >> 4) & 1) * 8;

    uint32_t sQa = cvta_s(sQ), sKa = cvta_s(sK), sVa = cvta_s(sV);

    uint32_t qf[2][4];
#pragma unroll
    for (int ma = 0; ma < 2; ma++)
        ldsm4(qf[ma], sQa + (uint32_t)((wm * 32 + ma * 16 + ar) * QST + ak) * 2);

    float mst[4] = {-CUDART_INF_F, -CUDART_INF_F, -CUDART_INF_F, -CUDART_INF_F};
    float lst[4] = {0.f, 0.f, 0.f, 0.f};
    float of[2][2][4];
#pragma unroll
    for (int a = 0; a < 2; a++)
#pragma unroll
        for (int c = 0; c < 2; c++)
#pragma unroll
            for (int q = 0; q < 4; q++) of[a][c][q] = 0.f;

    for (int kt = 0; kt < SEQ / 64; kt++) {
        int kb = kt * 64;
        __syncthreads();
        {
            int i = tid;
            int row = i >> 1, half = i & 1;
            *(uint4*)&sK[row * QST + half * 8] =
                *(const uint4*)&Kb[(size_t)(b * SEQ + kb + row) * DMODEL + hd * 16 + half * 8];
            *(uint4*)&sV[row * QST + half * 8] =
                *(const uint4*)&Vb[(size_t)(b * SEQ + kb + row) * DMODEL + hd * 16 + half * 8];
        }
        __syncthreads();

        // S = Q @ K^T (raw, scale folded into softmax)
        float sf[2][8][4];
#pragma unroll
        for (int a = 0; a < 2; a++)
#pragma unroll
            for (int j = 0; j < 8; j++)
#pragma unroll
                for (int q = 0; q < 4; q++) sf[a][j][q] = 0.f;
#pragma unroll
        for (int nb = 0; nb < 4; nb++) {
            uint32_t kf[4];
            ldsm4(kf, sKa + (uint32_t)((nb * 16 + bn) * QST + bk) * 2);
#pragma unroll
            for (int ma = 0; ma < 2; ma++) {
                mma_bf16(sf[ma][2 * nb], qf[ma], &kf[0]);
                mma_bf16(sf[ma][2 * nb + 1], qf[ma], &kf[2]);
            }
        }

        // online softmax (m in raw units; exp arg scaled)
#pragma unroll
        for (int ma = 0; ma < 2; ma++)
#pragma unroll
            for (int hr = 0; hr < 2; hr++) {
                int ridx = ma * 2 + hr;
                float mx = sf[ma][0][hr * 2];
#pragma unroll
                for (int j = 0; j < 8; j++) {
                    mx = fmaxf(mx, sf[ma][j][hr * 2]);
                    mx = fmaxf(mx, sf[ma][j][hr * 2 + 1]);
                }
                mx = fmaxf(mx, __shfl_xor_sync(0xffffffffu, mx, 1));
                mx = fmaxf(mx, __shfl_xor_sync(0xffffffffu, mx, 2));
                float mnew = fmaxf(mst[ridx], mx);
                float corr = __expf((mst[ridx] - mnew) * SCALE);
                float rsum = 0.f;
#pragma unroll
                for (int j = 0; j < 8; j++) {
                    float p0 = __expf((sf[ma][j][hr * 2] - mnew) * SCALE);
                    float p1 = __expf((sf[ma][j][hr * 2 + 1] - mnew) * SCALE);
                    sf[ma][j][hr * 2] = p0;
                    sf[ma][j][hr * 2 + 1] = p1;
                    rsum += p0 + p1;
                }
                rsum += __shfl_xor_sync(0xffffffffu, rsum, 1);
                rsum += __shfl_xor_sync(0xffffffffu, rsum, 2);
                lst[ridx] = lst[ridx] * corr + rsum;
                mst[ridx] = mnew;
#pragma unroll
                for (int nh = 0; nh < 2; nh++) {
                    of[ma][nh][hr * 2] *= corr;
                    of[ma][nh][hr * 2 + 1] *= corr;
                }
            }

        // O += P @ V  (P packed to A-frags, V via ldmatrix.trans)
#pragma unroll
        for (int kf = 0; kf < 4; kf++) {
            uint32_t vf[4];
            ldsm4t(vf, sVa + (uint32_t)((kf * 16 + vkey) * QST + vdh) * 2);
#pragma unroll
            for (int ma = 0; ma < 2; ma++) {
                uint32_t pa[4];
                pa[0] = cvt2bf(sf[ma][2 * kf][0], sf[ma][2 * kf][1]);
                pa[1] = cvt2bf(sf[ma][2 * kf][2], sf[ma][2 * kf][3]);
                pa[2] = cvt2bf(sf[ma][2 * kf + 1][0], sf[ma][2 * kf + 1][1]);
                pa[3] = cvt2bf(sf[ma][2 * kf + 1][2], sf[ma][2 * kf + 1][3]);
                mma_bf16(of[ma][0], pa, &vf[0]);
                mma_bf16(of[ma][1], pa, &vf[2]);
            }
        }
    }

    // epilogue: divide by l, split hi/lo, store
#pragma unroll
    for (int ma = 0; ma < 2; ma++)
#pragma unroll
        for (int hr = 0; hr < 2; hr++) {
            float inv = 1.f / lst[ma * 2 + hr];
            int grow = b * SEQ + qbase + wm * 32 + ma * 16 + (lane >> 2) + hr * 8;
#pragma unroll
            for (int nh = 0; nh < 2; nh++) {
                float v0 = of[ma][nh][hr * 2] * inv;
                float v1 = of[ma][nh][hr * 2 + 1] * inv;
                int col = hd * 16 + nh * 8 + (lane & 3) * 2;
                uint32_t hh, ll;
                split_pack(v0, v1, hh, ll);
                *(uint32_t*)&Ohi[(size_t)grow * DMODEL + col] = hh;
                *(uint32_t*)&Olo[(size_t)grow * DMODEL + col] = ll;
            }
        }
}

// ---------------- residual add + layernorm (+ optional hi/lo emit) -----------
__global__ void k_addln(const float* __restrict__ X, const float* __restrict__ R,
                        const float* __restrict__ g, const float* __restrict__ bta,
                        float* __restrict__ Y, __nv_bfloat16* __restrict__ Yhi,
                        __nv_bfloat16* __restrict__ Ylo) {
    int wid = threadIdx.x >> 5, lane = threadIdx.x & 31;
    int i = blockIdx.x * 8 + wid;
    float4 v = ((const float4*)X)[i * 32 + lane];
    float4 r = ((const float4*)R)[i * 32 + lane];
    v.x += r.x; v.y += r.y; v.z += r.z; v.w += r.w;
    float s = v.x + v.y + v.z + v.w;
#pragma unroll
    for (int off = 16; off; off >>= 1) s += __shfl_xor_sync(0xffffffffu, s, off);
    float mu = s * (1.f / 128.f);
    float dx = v.x - mu, dy = v.y - mu, dz = v.z - mu, dw = v.w - mu;
    float ss = dx * dx + dy * dy + dz * dz + dw * dw;
#pragma unroll
    for (int off = 16; off; off >>= 1) ss += __shfl_xor_sync(0xffffffffu, ss, off);
    float inv = rsqrtf(ss * (1.f / 128.f) + 1e-5f);
    float4 gg = ((const float4*)g)[lane];
    float4 bb = ((const float4*)bta)[lane];
    float o0 = fmaf(dx * inv, gg.x, bb.x);
    float o1 = fmaf(dy * inv, gg.y, bb.y);
    float o2 = fmaf(dz * inv, gg.z, bb.z);
    float o3 = fmaf(dw * inv, gg.w, bb.w);
    ((float4*)Y)[i * 32 + lane] = make_float4(o0, o1, o2, o3);
    if (Yhi) {
        uint2 hh, ll;
        split_pack(o0, o1, hh.x, ll.x);
        split_pack(o2, o3, hh.y, ll.y);
        *(uint2*)&Yhi[(size_t)i * DMODEL + lane * 4] = hh;
        *(uint2*)&Ylo[(size_t)i * DMODEL + lane * 4] = ll;
    }
}

// ---------------- host orchestration -----------------------------------------
extern "C" void kernel_launch(void* const* d_in, const int* in_sizes, int n_in,
                              void* d_out, int out_size) {
    const float* enc   = (const float*)d_in[0];
    const float* xraw  = (const float*)d_in[2];
    const int*   eidx  = (const int*)  d_in[3];
    const float* Wg1   = (const float*)d_in[4];
    const float* bg1   = (const float*)d_in[5];
    const float* Wg2   = (const float*)d_in[6];
    const float* bg2   = (const float*)d_in[7];
    const float* Wq    = (const float*)d_in[8];
    const float* Wk    = (const float*)d_in[9];
    const float* Wv    = (const float*)d_in[10];
    const float* Wo    = (const float*)d_in[11];
    const float* Wff1  = (const float*)d_in[12];
    const float* bff1  = (const float*)d_in[13];
    const float* Wff2  = (const float*)d_in[14];
    const float* bff2  = (const float*)d_in[15];
    const float* ln1g  = (const float*)d_in[16];
    const float* ln1b  = (const float*)d_in[17];
    const float* ln2g  = (const float*)d_in[18];
    const float* ln2b  = (const float*)d_in[19];
    float* outp = (float*)d_out;

    float *dinv, *h, *y, *Pb, *F2;
    int *counts, *rowoff, *cursor, *csr;
    __nv_bfloat16 *whi, *wlo, *xrhi, *xrlo, *x1hi, *x1lo, *gxhi, *gxlo;
    __nv_bfloat16 *yhi, *ylo, *Qbb, *Kbb, *Vbb, *Abhi, *Ablo, *F1hi, *F1lo;
    cudaGetSymbolAddress((void**)&dinv,   g_dinv);
    cudaGetSymbolAddress((void**)&counts, g_counts);
    cudaGetSymbolAddress((void**)&rowoff, g_rowoff);
    cudaGetSymbolAddress((void**)&cursor, g_cursor);
    cudaGetSymbolAddress((void**)&csr,    g_csr);
    cudaGetSymbolAddress((void**)&h,   g_h);
    cudaGetSymbolAddress((void**)&y,   g_y);
    cudaGetSymbolAddress((void**)&Pb,  g_Pb);
    cudaGetSymbolAddress((void**)&F2,  g_F2);
    cudaGetSymbolAddress((void**)&whi, g_whi);
    cudaGetSymbolAddress((void**)&wlo, g_wlo);
    cudaGetSymbolAddress((void**)&xrhi, g_xrhi);
    cudaGetSymbolAddress((void**)&xrlo, g_xrlo);
    cudaGetSymbolAddress((void**)&x1hi, g_x1hi);
    cudaGetSymbolAddress((void**)&x1lo, g_x1lo);
    cudaGetSymbolAddress((void**)&gxhi, g_gxhi);
    cudaGetSymbolAddress((void**)&gxlo, g_gxlo);
    cudaGetSymbolAddress((void**)&yhi, g_yhi);
    cudaGetSymbolAddress((void**)&ylo, g_ylo);
    cudaGetSymbolAddress((void**)&Qbb, g_Qbb);
    cudaGetSymbolAddress((void**)&Kbb, g_Kbb);
    cudaGetSymbolAddress((void**)&Vbb, g_Vbb);
    cudaGetSymbolAddress((void**)&Abhi, g_Abhi);
    cudaGetSymbolAddress((void**)&Ablo, g_Ablo);
    cudaGetSymbolAddress((void**)&F1hi, g_F1hi);
    cudaGetSymbolAddress((void**)&F1lo, g_F1lo);

    cudaFuncSetAttribute(k_gemm_tc, cudaFuncAttributeMaxDynamicSharedMemorySize, GT_SMEM);

    const int ROWS = N_NODES;
    const size_t OFF_G1 = 0, OFF_G2 = 16384;
    const size_t LSTR = 4 * 16384 + 2 * 65536;
    auto offQ  = [&](int l) { return 32768 + (size_t)l * LSTR; };
    auto offK  = [&](int l) { return offQ(l) + 16384; };
    auto offV  = [&](int l) { return offQ(l) + 32768; };
    auto offO  = [&](int l) { return offQ(l) + 49152; };
    auto offF1 = [&](int l) { return offQ(l) + 65536; };
    auto offF2 = [&](int l) { return offQ(l) + 131072; };

    // weight prep
    k_prep_w<<<64, 256>>>(Wg1, whi + OFF_G1, wlo + OFF_G1, 128, 128);
    k_prep_w<<<64, 256>>>(Wg2, whi + OFF_G2, wlo + OFF_G2, 128, 128);
    for (int l = 0; l < 2; l++) {
        k_prep_w<<<64, 256>>>(Wq + l * 16384, whi + offQ(l), wlo + offQ(l), 128, 128);
        k_prep_w<<<64, 256>>>(Wk + l * 16384, whi + offK(l), wlo + offK(l), 128, 128);
        k_prep_w<<<64, 256>>>(Wv + l * 16384, whi + offV(l), wlo + offV(l), 128, 128);
        k_prep_w<<<64, 256>>>(Wo + l * 16384, whi + offO(l), wlo + offO(l), 128, 128);
        k_prep_w<<<256, 256>>>(Wff1 + l * 65536, whi + offF1(l), wlo + offF1(l), 128, 512);
        k_prep_w<<<256, 256>>>(Wff2 + l * 65536, whi + offF2(l), wlo + offF2(l), 512, 128);
    }

    auto GEMM = [&](const __nv_bfloat16* Ah, const __nv_bfloat16* Al, size_t woff,
                    const float* bias, float* Cf, __nv_bfloat16* Cb,
                    __nv_bfloat16* Chi, __nv_bfloat16* Clo, int K, int ncols, int act) {
        dim3 g(ROWS / 128, ncols / 128);
        k_gemm_tc<<<g, 256, GT_SMEM>>>(Ah, Al, whi + woff, wlo + woff, bias,
                                       Cf, Cb, Chi, Clo, K, ncols, act);
    };

    // graph preprocessing + input conversion
    k_init_counts<<<N_NODES / 256, 256>>>(counts);
    k_count<<<N_EDGES / 256, 256>>>(eidx, counts);
    k_scan<<<1, 1024>>>(counts, rowoff, cursor, dinv);
    k_fill<<<NTOT / 256, 256>>>(eidx, cursor, csr);
    k_cvt<<<N_NODES * DMODEL / 1024, 256>>>(xraw, xrhi, xrlo);

    // GCN stack
    GEMM(xrhi, xrlo, OFF_G1, nullptr, h, nullptr, nullptr, nullptr, 128, 128, 0);
    k_aggregate<<<N_NODES / 8, 256>>>(h, dinv, rowoff, csr, bg1, x1hi, x1lo);
    GEMM(x1hi, x1lo, OFF_G2, nullptr, h, nullptr, nullptr, nullptr, 128, 128, 0);
    k_aggregate<<<N_NODES / 8, 256>>>(h, dinv, rowoff, csr, bg2, gxhi, gxlo);

    cudaMemcpyAsync(y, enc, (size_t)ROWS * DMODEL * sizeof(float),
                    cudaMemcpyDeviceToDevice);
    k_cvt<<<N_NODES * DMODEL / 1024, 256>>>(enc, yhi, ylo);

    for (int l = 0; l < 2; l++) {
        GEMM(yhi, ylo, offQ(l), nullptr, nullptr, Qbb, nullptr, nullptr, 128, 128, 0);
        GEMM(gxhi, gxlo, offK(l), nullptr, nullptr, Kbb, nullptr, nullptr, 128, 128, 0);
        GEMM(gxhi, gxlo, offV(l), nullptr, nullptr, Vbb, nullptr, nullptr, 128, 128, 0);
        k_attn_tc<<<dim3(SEQ / 128, HEADS, BATCH), 128>>>(Qbb, Kbb, Vbb, Abhi, Ablo);
        GEMM(Abhi, Ablo, offO(l), nullptr, Pb, nullptr, nullptr, nullptr, 128, 128, 0);
        k_addln<<<ROWS / 8, 256>>>(y, Pb, ln1g + l * 128, ln1b + l * 128, y, yhi, ylo);
        GEMM(yhi, ylo, offF1(l), bff1 + l * DFF, nullptr, nullptr, F1hi, F1lo, 128, DFF, 1);
        GEMM(F1hi, F1lo, offF2(l), bff2 + l * DMODEL, F2, nullptr, nullptr, nullptr, 512, 128, 0);
        if (l == 1)
            k_addln<<<ROWS / 8, 256>>>(y, F2, ln2g + l * 128, ln2b + l * 128, outp, nullptr, nullptr);
        else
            k_addln<<<ROWS / 8, 256>>>(y, F2, ln2g + l * 128, ln2b + l * 128, y, yhi, ylo);
    }
}

// round 5
// speedup vs baseline: 3.6879x; 1.5499x over previous
#include <cuda_runtime.h>
#include <cuda_bf16.h>
#include <math_constants.h>
#include <cstdint>

#define N_NODES 32768
#define N_EDGES 524288
#define DMODEL  128
#define BATCH   32
#define SEQ     1024
#define HEADS   8
#define DFF     512
#define NTOT    (N_EDGES + N_NODES)
#define WELEMS  425984
#define GST     72
#define QST     24
#define SC2     0.360673760222241f   /* 0.25 * log2(e) */

// ---------------- mma helpers ------------------------------------------------
__device__ __forceinline__ uint32_t cvta_s(const void* p) {
    return (uint32_t)__cvta_generic_to_shared(p);
}
__device__ __forceinline__ void ldsm4(uint32_t* r, uint32_t a) {
    asm volatile("ldmatrix.sync.aligned.m8n8.x4.shared.b16 {%0,%1,%2,%3}, [%4];"
                 : "=r"(r[0]), "=r"(r[1]), "=r"(r[2]), "=r"(r[3]) : "r"(a));
}
__device__ __forceinline__ void ldsm4t(uint32_t* r, uint32_t a) {
    asm volatile("ldmatrix.sync.aligned.m8n8.x4.trans.shared.b16 {%0,%1,%2,%3}, [%4];"
                 : "=r"(r[0]), "=r"(r[1]), "=r"(r[2]), "=r"(r[3]) : "r"(a));
}
__device__ __forceinline__ void mma_bf16(float* c, const uint32_t* a, const uint32_t* b) {
    asm volatile("mma.sync.aligned.m16n8k16.row.col.f32.bf16.bf16.f32 "
                 "{%0,%1,%2,%3}, {%4,%5,%6,%7}, {%8,%9}, {%0,%1,%2,%3};"
                 : "+f"(c[0]), "+f"(c[1]), "+f"(c[2]), "+f"(c[3])
                 : "r"(a[0]), "r"(a[1]), "r"(a[2]), "r"(a[3]), "r"(b[0]), "r"(b[1]));
}
__device__ __forceinline__ uint32_t cvt2bf(float lo, float hi) {
    uint32_t r;
    asm("cvt.rn.bf16x2.f32 %0, %1, %2;" : "=r"(r) : "f"(hi), "f"(lo));
    return r;
}
__device__ __forceinline__ void split_pack(float a, float b, uint32_t& hi, uint32_t& lo) {
    __nv_bfloat16 ha = __float2bfloat16(a), hb = __float2bfloat16(b);
    float ra = a - __bfloat162float(ha), rb = b - __bfloat162float(hb);
    __nv_bfloat16 la = __float2bfloat16(ra), lb = __float2bfloat16(rb);
    hi = ((uint32_t)__bfloat16_as_ushort(hb) << 16) | __bfloat16_as_ushort(ha);
    lo = ((uint32_t)__bfloat16_as_ushort(lb) << 16) | __bfloat16_as_ushort(la);
}

// ---------------- scratch ----------------------------------------------------
static __device__ float g_dinv[N_NODES];
static __device__ int   g_counts[N_NODES];
static __device__ int   g_rowoff[N_NODES + 1];
static __device__ int   g_cursor[N_NODES];
static __device__ int   g_csr[NTOT];
static __device__ float g_h [N_NODES * DMODEL];
static __device__ float g_y [N_NODES * DMODEL];
static __device__ __nv_bfloat16 g_whi[WELEMS];
static __device__ __nv_bfloat16 g_wlo[WELEMS];
static __device__ __nv_bfloat16 g_xrhi[N_NODES * DMODEL];
static __device__ __nv_bfloat16 g_xrlo[N_NODES * DMODEL];
static __device__ __nv_bfloat16 g_x1hi[N_NODES * DMODEL];
static __device__ __nv_bfloat16 g_x1lo[N_NODES * DMODEL];
static __device__ __nv_bfloat16 g_gxhi[N_NODES * DMODEL];
static __device__ __nv_bfloat16 g_gxlo[N_NODES * DMODEL];
static __device__ __nv_bfloat16 g_yhi[N_NODES * DMODEL];
static __device__ __nv_bfloat16 g_ylo[N_NODES * DMODEL];
static __device__ __nv_bfloat16 g_Qp[HEADS * N_NODES * 16];
static __device__ __nv_bfloat16 g_KVp[2 * HEADS * N_NODES * 16];
static __device__ __nv_bfloat16 g_Abhi[N_NODES * DMODEL];
static __device__ __nv_bfloat16 g_Ablo[N_NODES * DMODEL];
static __device__ __nv_bfloat16 g_F1hi[N_NODES * DFF];
static __device__ __nv_bfloat16 g_F1lo[N_NODES * DFF];

// ---------------- graph preprocessing ---------------------------------------
__global__ void k_init_counts(int* counts) {
    counts[blockIdx.x * blockDim.x + threadIdx.x] = 0;
}
__global__ void k_count(const int* __restrict__ eidx, int* __restrict__ counts) {
    int e = blockIdx.x * blockDim.x + threadIdx.x;
    atomicAdd(&counts[eidx[N_EDGES + e]], 1);
}
__global__ void k_scan(const int* __restrict__ counts, int* __restrict__ rowoff,
                       int* __restrict__ cursor, float* __restrict__ dinv) {
    __shared__ int part[1024];
    int tid = threadIdx.x, base = tid * 32;
    int c[32], s = 0;
#pragma unroll
    for (int i = 0; i < 32; i++) { c[i] = counts[base + i] + 1; s += c[i]; }
    part[tid] = s;
    __syncthreads();
    for (int off = 1; off < 1024; off <<= 1) {
        int v = (tid >= off) ? part[tid - off] : 0;
        __syncthreads();
        part[tid] += v;
        __syncthreads();
    }
    int run = part[tid] - s;
#pragma unroll
    for (int i = 0; i < 32; i++) {
        rowoff[base + i] = run;
        cursor[base + i] = run;
        dinv[base + i] = rsqrtf((float)c[i]);
        run += c[i];
    }
    if (tid == 1023) rowoff[N_NODES] = run;
}
__global__ void k_fill(const int* __restrict__ eidx, int* __restrict__ cursor,
                       int* __restrict__ csr) {
    int e = blockIdx.x * blockDim.x + threadIdx.x;
    int s, d;
    if (e < N_EDGES) { s = eidx[e]; d = eidx[N_EDGES + e]; }
    else             { s = d = e - N_EDGES; }
    csr[atomicAdd(&cursor[d], 1)] = s;
}

__global__ void k_aggregate(const float* __restrict__ h, const float* __restrict__ dinv,
                            const int* __restrict__ rowoff, const int* __restrict__ csr,
                            const float* __restrict__ bias,
                            __nv_bfloat16* __restrict__ ohi, __nv_bfloat16* __restrict__ olo) {
    int wid = threadIdx.x >> 5, lane = threadIdx.x & 31;
    int i = blockIdx.x * 8 + wid;
    const float4* h4 = (const float4*)h;
    float4 acc = make_float4(0.f, 0.f, 0.f, 0.f);
    int e = rowoff[i], end = rowoff[i + 1];
    for (; e + 2 <= end; e += 2) {
        int s0 = csr[e], s1 = csr[e + 1];
        float w0 = dinv[s0], w1 = dinv[s1];
        float4 v0 = h4[s0 * 32 + lane];
        float4 v1 = h4[s1 * 32 + lane];
        acc.x = fmaf(w0, v0.x, fmaf(w1, v1.x, acc.x));
        acc.y = fmaf(w0, v0.y, fmaf(w1, v1.y, acc.y));
        acc.z = fmaf(w0, v0.z, fmaf(w1, v1.z, acc.z));
        acc.w = fmaf(w0, v0.w, fmaf(w1, v1.w, acc.w));
    }
    if (e < end) {
        int s0 = csr[e];
        float w0 = dinv[s0];
        float4 v0 = h4[s0 * 32 + lane];
        acc.x = fmaf(w0, v0.x, acc.x); acc.y = fmaf(w0, v0.y, acc.y);
        acc.z = fmaf(w0, v0.z, acc.z); acc.w = fmaf(w0, v0.w, acc.w);
    }
    float di = dinv[i];
    float4 b4 = ((const float4*)bias)[lane];
    float o0 = fmaxf(fmaf(di, acc.x, b4.x), 0.f);
    float o1 = fmaxf(fmaf(di, acc.y, b4.y), 0.f);
    float o2 = fmaxf(fmaf(di, acc.z, b4.z), 0.f);
    float o3 = fmaxf(fmaf(di, acc.w, b4.w), 0.f);
    uint2 hh, ll;
    split_pack(o0, o1, hh.x, ll.x);
    split_pack(o2, o3, hh.y, ll.y);
    *(uint2*)&ohi[(size_t)i * DMODEL + lane * 4] = hh;
    *(uint2*)&olo[(size_t)i * DMODEL + lane * 4] = ll;
}

// fp32 -> bf16 hi/lo (+ optional fp32 copy)
__global__ void k_cvt(const float* __restrict__ src, __nv_bfloat16* __restrict__ hi,
                      __nv_bfloat16* __restrict__ lo, float* __restrict__ fdst) {
    int i = blockIdx.x * blockDim.x + threadIdx.x;
    float4 v = ((const float4*)src)[i];
    uint2 hh, ll;
    split_pack(v.x, v.y, hh.x, ll.x);
    split_pack(v.z, v.w, hh.y, ll.y);
    ((uint2*)hi)[i] = hh;
    ((uint2*)lo)[i] = ll;
    if (fdst) ((float4*)fdst)[i] = v;
}

// ---------------- mega weight prep (one launch) -------------------------------
struct Seg { const float* src; int K; int N; int off; int blk0; };
struct PrepArgs { Seg s[14]; int nseg; };

__global__ void k_prep_all(PrepArgs pa, __nv_bfloat16* __restrict__ hi,
                           __nv_bfloat16* __restrict__ lo) {
    int b = blockIdx.x;
    int si = 0;
    while (si + 1 < pa.nseg && pa.s[si + 1].blk0 <= b) si++;
    Seg sg = pa.s[si];
    int idx = (b - sg.blk0) * 256 + threadIdx.x;
    int k = idx / sg.N, n = idx % sg.N;
    float v = sg.src[idx];
    __nv_bfloat16 h = __float2bfloat16(v);
    __nv_bfloat16 l = __float2bfloat16(v - __bfloat162float(h));
    hi[sg.off + n * sg.K + k] = h;
    lo[sg.off + n * sg.K + k] = l;
}

// ---------------- tensor-core GEMM -------------------------------------------
#define GT_SMEM (4 * 128 * GST * 2)
__global__ void __launch_bounds__(256)
k_gemm_tc(const __nv_bfloat16* __restrict__ Ahi, const __nv_bfloat16* __restrict__ Alo,
          const __nv_bfloat16* __restrict__ Whi, const __nv_bfloat16* __restrict__ Wlo,
          const float* __restrict__ bias, float* __restrict__ Cf,
          __nv_bfloat16* __restrict__ Cb, __nv_bfloat16* __restrict__ Chi,
          __nv_bfloat16* __restrict__ Clo, int K, int ncols, int act, int perm) {
    extern __shared__ char smem[];
    __nv_bfloat16* As_hi = (__nv_bfloat16*)smem;
    __nv_bfloat16* As_lo = (__nv_bfloat16*)(smem + 128 * GST * 2);
    __nv_bfloat16* Ws_hi = (__nv_bfloat16*)(smem + 2 * 128 * GST * 2);
    __nv_bfloat16* Ws_lo = (__nv_bfloat16*)(smem + 3 * 128 * GST * 2);

    int tid = threadIdx.x, wid = tid >> 5, lane = tid & 31;
    int wm = wid & 3, wn = wid >> 2;
    int rowBase = blockIdx.x * 128, colBase = blockIdx.y * 128;

    float acc[2][8][4];
#pragma unroll
    for (int i = 0; i < 2; i++)
#pragma unroll
        for (int j = 0; j < 8; j++)
#pragma unroll
            for (int q = 0; q < 4; q++) acc[i][j][q] = 0.f;

    int ar = (lane & 7) + ((lane >> 3) & 1) * 8;
    int ak = (lane >> 4) * 8;
    int bn = (lane & 7) + ((lane >> 4) & 1) * 8;
    int bk = ((lane >> 3) & 1) * 8;

    uint32_t sAh = cvta_s(As_hi), sAl = cvta_s(As_lo);
    uint32_t sWh = cvta_s(Ws_hi), sWl = cvta_s(Ws_lo);

    for (int kb = 0; kb < K; kb += 64) {
#pragma unroll
        for (int j = 0; j < 4; j++) {
            int i = tid + 256 * j;
            int r = i >> 3, c = i & 7;
            *(uint4*)&As_hi[r * GST + c * 8] = *(const uint4*)&Ahi[(size_t)(rowBase + r) * K + kb + c * 8];
            *(uint4*)&As_lo[r * GST + c * 8] = *(const uint4*)&Alo[(size_t)(rowBase + r) * K + kb + c * 8];
            *(uint4*)&Ws_hi[r * GST + c * 8] = *(const uint4*)&Whi[(size_t)(colBase + r) * K + kb + c * 8];
            *(uint4*)&Ws_lo[r * GST + c * 8] = *(const uint4*)&Wlo[(size_t)(colBase + r) * K + kb + c * 8];
        }
        __syncthreads();

#pragma unroll
        for (int ks = 0; ks < 64; ks += 16) {
            uint32_t ah[2][4], al[2][4];
#pragma unroll
            for (int ma = 0; ma < 2; ma++) {
                uint32_t off = (uint32_t)((wm * 32 + ma * 16 + ar) * GST + ks + ak) * 2;
                ldsm4(ah[ma], sAh + off);
                ldsm4(al[ma], sAl + off);
            }
            uint32_t bh[4][4], bl[4][4];
#pragma unroll
            for (int nb = 0; nb < 4; nb++) {
                uint32_t off = (uint32_t)((wn * 64 + nb * 16 + bn) * GST + ks + bk) * 2;
                ldsm4(bh[nb], sWh + off);
                ldsm4(bl[nb], sWl + off);
            }
#pragma unroll
            for (int ma = 0; ma < 2; ma++)
#pragma unroll
                for (int na = 0; na < 8; na++) {
                    float* c = acc[ma][na];
                    const uint32_t* pbh = &bh[na >> 1][(na & 1) * 2];
                    const uint32_t* pbl = &bl[na >> 1][(na & 1) * 2];
                    mma_bf16(c, ah[ma], pbh);
                    mma_bf16(c, ah[ma], pbl);
                    mma_bf16(c, al[ma], pbh);
                }
        }
        __syncthreads();
    }

#pragma unroll
    for (int ma = 0; ma < 2; ma++)
#pragma unroll
        for (int na = 0; na < 8; na++) {
            int row = rowBase + wm * 32 + ma * 16 + (lane >> 2);
            int col = colBase + wn * 64 + na * 8 + (lane & 3) * 2;
            float b0 = 0.f, b1 = 0.f;
            if (bias) { b0 = bias[col]; b1 = bias[col + 1]; }
            float v0 = acc[ma][na][0] + b0, v1 = acc[ma][na][1] + b1;
            float v2 = acc[ma][na][2] + b0, v3 = acc[ma][na][3] + b1;
            if (act) {
                v0 = fmaxf(v0, 0.f); v1 = fmaxf(v1, 0.f);
                v2 = fmaxf(v2, 0.f); v3 = fmaxf(v3, 0.f);
            }
            if (Cf) {
                size_t i0 = (size_t)row * ncols + col, i1 = (size_t)(row + 8) * ncols + col;
                *(float2*)&Cf[i0] = make_float2(v0, v1);
                *(float2*)&Cf[i1] = make_float2(v2, v3);
            }
            if (Cb) {
                if (perm) {   // head-major: [col>>4][row][col&15]
                    size_t j0 = ((size_t)(col >> 4) * N_NODES + row) * 16 + (col & 15);
                    size_t j1 = ((size_t)(col >> 4) * N_NODES + row + 8) * 16 + (col & 15);
                    *(uint32_t*)&Cb[j0] = cvt2bf(v0, v1);
                    *(uint32_t*)&Cb[j1] = cvt2bf(v2, v3);
                } else {
                    size_t i0 = (size_t)row * ncols + col, i1 = (size_t)(row + 8) * ncols + col;
                    *(uint32_t*)&Cb[i0] = cvt2bf(v0, v1);
                    *(uint32_t*)&Cb[i1] = cvt2bf(v2, v3);
                }
            }
            if (Chi) {
                size_t i0 = (size_t)row * ncols + col, i1 = (size_t)(row + 8) * ncols + col;
                uint32_t h0, l0, h1, l1;
                split_pack(v0, v1, h0, l0);
                split_pack(v2, v3, h1, l1);
                *(uint32_t*)&Chi[i0] = h0; *(uint32_t*)&Clo[i0] = l0;
                *(uint32_t*)&Chi[i1] = h1; *(uint32_t*)&Clo[i1] = l1;
            }
        }
}

// ---------------- GEMM + residual + LayerNorm fused (ncols=128) ---------------
__global__ void __launch_bounds__(256)
k_gemm_ln(const __nv_bfloat16* __restrict__ Ahi, const __nv_bfloat16* __restrict__ Alo,
          const __nv_bfloat16* __restrict__ Whi, const __nv_bfloat16* __restrict__ Wlo,
          const float* __restrict__ bias, const float* __restrict__ R,
          const float* __restrict__ gamma, const float* __restrict__ beta,
          float* __restrict__ Yf, __nv_bfloat16* __restrict__ Yhi,
          __nv_bfloat16* __restrict__ Ylo, int K) {
    extern __shared__ char smem[];
    __nv_bfloat16* As_hi = (__nv_bfloat16*)smem;
    __nv_bfloat16* As_lo = (__nv_bfloat16*)(smem + 128 * GST * 2);
    __nv_bfloat16* Ws_hi = (__nv_bfloat16*)(smem + 2 * 128 * GST * 2);
    __nv_bfloat16* Ws_lo = (__nv_bfloat16*)(smem + 3 * 128 * GST * 2);
    __shared__ float red[128][2][2];

    int tid = threadIdx.x, wid = tid >> 5, lane = tid & 31;
    int wm = wid & 3, wn = wid >> 2;
    int rowBase = blockIdx.x * 128;

    float acc[2][8][4];
#pragma unroll
    for (int i = 0; i < 2; i++)
#pragma unroll
        for (int j = 0; j < 8; j++)
#pragma unroll
            for (int q = 0; q < 4; q++) acc[i][j][q] = 0.f;

    int ar = (lane & 7) + ((lane >> 3) & 1) * 8;
    int ak = (lane >> 4) * 8;
    int bn = (lane & 7) + ((lane >> 4) & 1) * 8;
    int bk = ((lane >> 3) & 1) * 8;

    uint32_t sAh = cvta_s(As_hi), sAl = cvta_s(As_lo);
    uint32_t sWh = cvta_s(Ws_hi), sWl = cvta_s(Ws_lo);

    for (int kb = 0; kb < K; kb += 64) {
#pragma unroll
        for (int j = 0; j < 4; j++) {
            int i = tid + 256 * j;
            int r = i >> 3, c = i & 7;
            *(uint4*)&As_hi[r * GST + c * 8] = *(const uint4*)&Ahi[(size_t)(rowBase + r) * K + kb + c * 8];
            *(uint4*)&As_lo[r * GST + c * 8] = *(const uint4*)&Alo[(size_t)(rowBase + r) * K + kb + c * 8];
            *(uint4*)&Ws_hi[r * GST + c * 8] = *(const uint4*)&Whi[(size_t)r * K + kb + c * 8];
            *(uint4*)&Ws_lo[r * GST + c * 8] = *(const uint4*)&Wlo[(size_t)r * K + kb + c * 8];
        }
        __syncthreads();

#pragma unroll
        for (int ks = 0; ks < 64; ks += 16) {
            uint32_t ah[2][4], al[2][4];
#pragma unroll
            for (int ma = 0; ma < 2; ma++) {
                uint32_t off = (uint32_t)((wm * 32 + ma * 16 + ar) * GST + ks + ak) * 2;
                ldsm4(ah[ma], sAh + off);
                ldsm4(al[ma], sAl + off);
            }
            uint32_t bh[4][4], bl[4][4];
#pragma unroll
            for (int nb = 0; nb < 4; nb++) {
                uint32_t off = (uint32_t)((wn * 64 + nb * 16 + bn) * GST + ks + bk) * 2;
                ldsm4(bh[nb], sWh + off);
                ldsm4(bl[nb], sWl + off);
            }
#pragma unroll
            for (int ma = 0; ma < 2; ma++)
#pragma unroll
                for (int na = 0; na < 8; na++) {
                    float* c = acc[ma][na];
                    const uint32_t* pbh = &bh[na >> 1][(na & 1) * 2];
                    const uint32_t* pbl = &bl[na >> 1][(na & 1) * 2];
                    mma_bf16(c, ah[ma], pbh);
                    mma_bf16(c, ah[ma], pbl);
                    mma_bf16(c, al[ma], pbh);
                }
        }
        __syncthreads();
    }

    // bias + residual
#pragma unroll
    for (int ma = 0; ma < 2; ma++)
#pragma unroll
        for (int na = 0; na < 8; na++) {
            int row = rowBase + wm * 32 + ma * 16 + (lane >> 2);
            int col = wn * 64 + na * 8 + (lane & 3) * 2;
            float b0 = 0.f, b1 = 0.f;
            if (bias) { b0 = bias[col]; b1 = bias[col + 1]; }
            float2 r0 = *(const float2*)&R[(size_t)row * DMODEL + col];
            float2 r1 = *(const float2*)&R[(size_t)(row + 8) * DMODEL + col];
            acc[ma][na][0] += b0 + r0.x;
            acc[ma][na][1] += b1 + r0.y;
            acc[ma][na][2] += b0 + r1.x;
            acc[ma][na][3] += b1 + r1.y;
        }

    // row partial sums (quad-reduce over lane&3, then cross-warp via smem)
#pragma unroll
    for (int ma = 0; ma < 2; ma++)
#pragma unroll
        for (int hr = 0; hr < 2; hr++) {
            float s = 0.f, s2 = 0.f;
#pragma unroll
            for (int na = 0; na < 8; na++) {
                float a = acc[ma][na][hr * 2], b = acc[ma][na][hr * 2 + 1];
                s += a + b;
                s2 += a * a + b * b;
            }
            s  += __shfl_xor_sync(0xffffffffu, s, 1);
            s  += __shfl_xor_sync(0xffffffffu, s, 2);
            s2 += __shfl_xor_sync(0xffffffffu, s2, 1);
            s2 += __shfl_xor_sync(0xffffffffu, s2, 2);
            int rl = wm * 32 + ma * 16 + (lane >> 2) + hr * 8;
            if ((lane & 3) == 0) { red[rl][wn][0] = s; red[rl][wn][1] = s2; }
        }
    __syncthreads();

#pragma unroll
    for (int ma = 0; ma < 2; ma++)
#pragma unroll
        for (int hr = 0; hr < 2; hr++) {
            int rl = wm * 32 + ma * 16 + (lane >> 2) + hr * 8;
            float S  = red[rl][0][0] + red[rl][1][0];
            float S2 = red[rl][0][1] + red[rl][1][1];
            float mu = S * (1.f / 128.f);
            float var = S2 * (1.f / 128.f) - mu * mu;
            float inv = rsqrtf(var + 1e-5f);
            int row = rowBase + rl;
#pragma unroll
            for (int na = 0; na < 8; na++) {
                int col = wn * 64 + na * 8 + (lane & 3) * 2;
                float g0 = gamma[col], g1 = gamma[col + 1];
                float t0 = beta[col], t1 = beta[col + 1];
                float v0 = fmaf((acc[ma][na][hr * 2] - mu) * inv, g0, t0);
                float v1 = fmaf((acc[ma][na][hr * 2 + 1] - mu) * inv, g1, t1);
                *(float2*)&Yf[(size_t)row * DMODEL + col] = make_float2(v0, v1);
                if (Yhi) {
                    uint32_t hh, ll;
                    split_pack(v0, v1, hh, ll);
                    *(uint32_t*)&Yhi[(size_t)row * DMODEL + col] = hh;
                    *(uint32_t*)&Ylo[(size_t)row * DMODEL + col] = ll;
                }
            }
        }
}

// ---------------- flash attention (8 warps, head-major layouts) ---------------
__global__ void __launch_bounds__(256)
k_attn_tc(const __nv_bfloat16* __restrict__ Qp, const __nv_bfloat16* __restrict__ KVp,
          __nv_bfloat16* __restrict__ Ohi, __nv_bfloat16* __restrict__ Olo) {
    __shared__ __nv_bfloat16 sQ[128 * QST];
    __shared__ __nv_bfloat16 sK[64 * QST];
    __shared__ __nv_bfloat16 sV[64 * QST];

    int b = blockIdx.z, hd = blockIdx.y, qbase = blockIdx.x * 128;
    int tid = threadIdx.x, wm = tid >> 5, lane = tid & 31;

    const __nv_bfloat16* Qh = Qp + ((size_t)hd * N_NODES + b * SEQ + qbase) * 16;
    const __nv_bfloat16* Kh = KVp + ((size_t)hd * N_NODES + b * SEQ) * 16;
    const __nv_bfloat16* Vh = KVp + ((size_t)(hd + HEADS) * N_NODES + b * SEQ) * 16;

    {   // stage Q: 128 rows x 16, fully coalesced
        int row = tid >> 1, half = tid & 1;
        *(uint4*)&sQ[row * QST + half * 8] = *(const uint4*)&Qh[row * 16 + half * 8];
    }

    int slot = tid & 127, trow = slot >> 1, thalf = slot & 1;
    const __nv_bfloat16* tsrc = (tid < 128) ? Kh : Vh;
    __nv_bfloat16* tdst = (tid < 128) ? sK : sV;

    uint4 rbuf = *(const uint4*)&tsrc[(size_t)trow * 16 + thalf * 8];
    *(uint4*)&tdst[trow * QST + thalf * 8] = rbuf;
    __syncthreads();

    int ar = (lane & 7) + ((lane >> 3) & 1) * 8;
    int ak = (lane >> 4) * 8;
    int bn = (lane & 7) + ((lane >> 4) & 1) * 8;
    int bk = ((lane >> 3) & 1) * 8;
    int vkey = (lane & 7) + ((lane >> 3) & 1) * 8;
    int vdh = ((lane >> 4) & 1) * 8;

    uint32_t sQa = cvta_s(sQ), sKa = cvta_s(sK), sVa = cvta_s(sV);
    uint32_t qf[4];
    ldsm4(qf, sQa + (uint32_t)((wm * 16 + ar) * QST + ak) * 2);

    float mst[2] = {-CUDART_INF_F, -CUDART_INF_F};
    float lst[2] = {0.f, 0.f};
    float of[2][4] = {{0.f, 0.f, 0.f, 0.f}, {0.f, 0.f, 0.f, 0.f}};

    for (int kt = 0; kt < SEQ / 64; kt++) {
        if (kt + 1 < SEQ / 64)
            rbuf = *(const uint4*)&tsrc[(size_t)((kt + 1) * 64 + trow) * 16 + thalf * 8];

        float sf[8][4];
#pragma unroll
        for (int j = 0; j < 8; j++)
#pragma unroll
            for (int q = 0; q < 4; q++) sf[j][q] = 0.f;
#pragma unroll
        for (int nb = 0; nb < 4; nb++) {
            uint32_t kf[4];
            ldsm4(kf, sKa + (uint32_t)((nb * 16 + bn) * QST + bk) * 2);
            mma_bf16(sf[2 * nb], qf, &kf[0]);
            mma_bf16(sf[2 * nb + 1], qf, &kf[2]);
        }
#pragma unroll
        for (int j = 0; j < 8; j++)
#pragma unroll
            for (int q = 0; q < 4; q++) sf[j][q] *= SC2;

#pragma unroll
        for (int hr = 0; hr < 2; hr++) {
            float mx = sf[0][hr * 2];
#pragma unroll
            for (int j = 0; j < 8; j++) {
                mx = fmaxf(mx, sf[j][hr * 2]);
                mx = fmaxf(mx, sf[j][hr * 2 + 1]);
            }
            mx = fmaxf(mx, __shfl_xor_sync(0xffffffffu, mx, 1));
            mx = fmaxf(mx, __shfl_xor_sync(0xffffffffu, mx, 2));
            float mnew = fmaxf(mst[hr], mx);
            float corr = exp2f(mst[hr] - mnew);
            float rsum = 0.f;
#pragma unroll
            for (int j = 0; j < 8; j++) {
                float p0 = exp2f(sf[j][hr * 2] - mnew);
                float p1 = exp2f(sf[j][hr * 2 + 1] - mnew);
                sf[j][hr * 2] = p0;
                sf[j][hr * 2 + 1] = p1;
                rsum += p0 + p1;
            }
            rsum += __shfl_xor_sync(0xffffffffu, rsum, 1);
            rsum += __shfl_xor_sync(0xffffffffu, rsum, 2);
            lst[hr] = lst[hr] * corr + rsum;
            mst[hr] = mnew;
#pragma unroll
            for (int nh = 0; nh < 2; nh++) {
                of[nh][hr * 2] *= corr;
                of[nh][hr * 2 + 1] *= corr;
            }
        }

#pragma unroll
        for (int kf = 0; kf < 4; kf++) {
            uint32_t vf[4];
            ldsm4t(vf, sVa + (uint32_t)((kf * 16 + vkey) * QST + vdh) * 2);
            uint32_t pa[4];
            pa[0] = cvt2bf(sf[2 * kf][0], sf[2 * kf][1]);
            pa[1] = cvt2bf(sf[2 * kf][2], sf[2 * kf][3]);
            pa[2] = cvt2bf(sf[2 * kf + 1][0], sf[2 * kf + 1][1]);
            pa[3] = cvt2bf(sf[2 * kf + 1][2], sf[2 * kf + 1][3]);
            mma_bf16(of[0], pa, &vf[0]);
            mma_bf16(of[1], pa, &vf[2]);
        }

        __syncthreads();
        if (kt + 1 < SEQ / 64)
            *(uint4*)&tdst[trow * QST + thalf * 8] = rbuf;
        __syncthreads();
    }

#pragma unroll
    for (int hr = 0; hr < 2; hr++) {
        float inv = 1.f / lst[hr];
        int grow = b * SEQ + qbase + wm * 16 + (lane >> 2) + hr * 8;
#pragma unroll
        for (int nh = 0; nh < 2; nh++) {
            float v0 = of[nh][hr * 2] * inv;
            float v1 = of[nh][hr * 2 + 1] * inv;
            int col = hd * 16 + nh * 8 + (lane & 3) * 2;
            uint32_t hh, ll;
            split_pack(v0, v1, hh, ll);
            *(uint32_t*)&Ohi[(size_t)grow * DMODEL + col] = hh;
            *(uint32_t*)&Olo[(size_t)grow * DMODEL + col] = ll;
        }
    }
}

// ---------------- host orchestration -----------------------------------------
extern "C" void kernel_launch(void* const* d_in, const int* in_sizes, int n_in,
                              void* d_out, int out_size) {
    const float* enc   = (const float*)d_in[0];
    const float* xraw  = (const float*)d_in[2];
    const int*   eidx  = (const int*)  d_in[3];
    const float* Wg1   = (const float*)d_in[4];
    const float* bg1   = (const float*)d_in[5];
    const float* Wg2   = (const float*)d_in[6];
    const float* bg2   = (const float*)d_in[7];
    const float* Wq    = (const float*)d_in[8];
    const float* Wk    = (const float*)d_in[9];
    const float* Wv    = (const float*)d_in[10];
    const float* Wo    = (const float*)d_in[11];
    const float* Wff1  = (const float*)d_in[12];
    const float* bff1  = (const float*)d_in[13];
    const float* Wff2  = (const float*)d_in[14];
    const float* bff2  = (const float*)d_in[15];
    const float* ln1g  = (const float*)d_in[16];
    const float* ln1b  = (const float*)d_in[17];
    const float* ln2g  = (const float*)d_in[18];
    const float* ln2b  = (const float*)d_in[19];
    float* outp = (float*)d_out;

    float *dinv, *h, *y;
    int *counts, *rowoff, *cursor, *csr;
    __nv_bfloat16 *whi, *wlo, *xrhi, *xrlo, *x1hi, *x1lo, *gxhi, *gxlo;
    __nv_bfloat16 *yhi, *ylo, *Qp, *KVp, *Abhi, *Ablo, *F1hi, *F1lo;
    cudaGetSymbolAddress((void**)&dinv,   g_dinv);
    cudaGetSymbolAddress((void**)&counts, g_counts);
    cudaGetSymbolAddress((void**)&rowoff, g_rowoff);
    cudaGetSymbolAddress((void**)&cursor, g_cursor);
    cudaGetSymbolAddress((void**)&csr,    g_csr);
    cudaGetSymbolAddress((void**)&h,   g_h);
    cudaGetSymbolAddress((void**)&y,   g_y);
    cudaGetSymbolAddress((void**)&whi, g_whi);
    cudaGetSymbolAddress((void**)&wlo, g_wlo);
    cudaGetSymbolAddress((void**)&xrhi, g_xrhi);
    cudaGetSymbolAddress((void**)&xrlo, g_xrlo);
    cudaGetSymbolAddress((void**)&x1hi, g_x1hi);
    cudaGetSymbolAddress((void**)&x1lo, g_x1lo);
    cudaGetSymbolAddress((void**)&gxhi, g_gxhi);
    cudaGetSymbolAddress((void**)&gxlo, g_gxlo);
    cudaGetSymbolAddress((void**)&yhi, g_yhi);
    cudaGetSymbolAddress((void**)&ylo, g_ylo);
    cudaGetSymbolAddress((void**)&Qp,  g_Qp);
    cudaGetSymbolAddress((void**)&KVp, g_KVp);
    cudaGetSymbolAddress((void**)&Abhi, g_Abhi);
    cudaGetSymbolAddress((void**)&Ablo, g_Ablo);
    cudaGetSymbolAddress((void**)&F1hi, g_F1hi);
    cudaGetSymbolAddress((void**)&F1lo, g_F1lo);

    cudaFuncSetAttribute(k_gemm_tc, cudaFuncAttributeMaxDynamicSharedMemorySize, GT_SMEM);
    cudaFuncSetAttribute(k_gemm_ln, cudaFuncAttributeMaxDynamicSharedMemorySize, GT_SMEM);

    const int ROWS = N_NODES;
    const int OFF_G1 = 0, OFF_G2 = 16384;
    const int LSTR = 4 * 16384 + 2 * 65536;
    auto offQ  = [&](int l) { return 32768 + l * LSTR; };
    auto offK  = [&](int l) { return offQ(l) + 16384; };
    auto offO  = [&](int l) { return offQ(l) + 49152; };
    auto offF1 = [&](int l) { return offQ(l) + 65536; };
    auto offF2 = [&](int l) { return offQ(l) + 131072; };

    // ---- one-shot weight prep ----
    PrepArgs pa;
    int blk = 0, si = 0;
    auto addseg = [&](const float* src, int K, int N, int off) {
        pa.s[si].src = src; pa.s[si].K = K; pa.s[si].N = N;
        pa.s[si].off = off; pa.s[si].blk0 = blk;
        si++; blk += K * N / 256;
    };
    addseg(Wg1, 128, 128, OFF_G1);
    addseg(Wg2, 128, 128, OFF_G2);
    for (int l = 0; l < 2; l++) {
        addseg(Wq + l * 16384, 128, 128, offQ(l));
        addseg(Wk + l * 16384, 128, 128, offK(l));
        addseg(Wv + l * 16384, 128, 128, offK(l) + 16384);
        addseg(Wo + l * 16384, 128, 128, offO(l));
        addseg(Wff1 + l * 65536, 128, 512, offF1(l));
        addseg(Wff2 + l * 65536, 512, 128, offF2(l));
    }
    pa.nseg = si;
    k_prep_all<<<blk, 256>>>(pa, whi, wlo);

    auto GEMM = [&](const __nv_bfloat16* Ah, const __nv_bfloat16* Al, int woff,
                    const float* bias, float* Cf, __nv_bfloat16* Cb,
                    __nv_bfloat16* Chi, __nv_bfloat16* Clo, int K, int ncols,
                    int act, int perm) {
        dim3 g(ROWS / 128, ncols / 128);
        k_gemm_tc<<<g, 256, GT_SMEM>>>(Ah, Al, whi + woff, wlo + woff, bias,
                                       Cf, Cb, Chi, Clo, K, ncols, act, perm);
    };

    // ---- graph preprocessing + input conversion ----
    k_init_counts<<<N_NODES / 256, 256>>>(counts);
    k_count<<<N_EDGES / 256, 256>>>(eidx, counts);
    k_scan<<<1, 1024>>>(counts, rowoff, cursor, dinv);
    k_fill<<<NTOT / 256, 256>>>(eidx, cursor, csr);
    k_cvt<<<N_NODES * DMODEL / 1024, 256>>>(xraw, xrhi, xrlo, nullptr);
    k_cvt<<<N_NODES * DMODEL / 1024, 256>>>(enc, yhi, ylo, y);

    // ---- GCN stack ----
    GEMM(xrhi, xrlo, OFF_G1, nullptr, h, nullptr, nullptr, nullptr, 128, 128, 0, 0);
    k_aggregate<<<N_NODES / 8, 256>>>(h, dinv, rowoff, csr, bg1, x1hi, x1lo);
    GEMM(x1hi, x1lo, OFF_G2, nullptr, h, nullptr, nullptr, nullptr, 128, 128, 0, 0);
    k_aggregate<<<N_NODES / 8, 256>>>(h, dinv, rowoff, csr, bg2, gxhi, gxlo);

    // ---- transformer layers ----
    for (int l = 0; l < 2; l++) {
        GEMM(yhi, ylo, offQ(l), nullptr, nullptr, Qp, nullptr, nullptr, 128, 128, 0, 1);
        GEMM(gxhi, gxlo, offK(l), nullptr, nullptr, KVp, nullptr, nullptr, 128, 256, 0, 1);
        k_attn_tc<<<dim3(SEQ / 128, HEADS, BATCH), 256>>>(Qp, KVp, Abhi, Ablo);
        k_gemm_ln<<<ROWS / 128, 256, GT_SMEM>>>(Abhi, Ablo, whi + offO(l), wlo + offO(l),
                                                nullptr, y, ln1g + l * 128, ln1b + l * 128,
                                                y, yhi, ylo, 128);
        GEMM(yhi, ylo, offF1(l), bff1 + l * DFF, nullptr, nullptr, F1hi, F1lo, 128, DFF, 1, 0);
        if (l == 1)
            k_gemm_ln<<<ROWS / 128, 256, GT_SMEM>>>(F1hi, F1lo, whi + offF2(l), wlo + offF2(l),
                                                    bff2 + l * DMODEL, y, ln2g + l * 128,
                                                    ln2b + l * 128, outp, nullptr, nullptr, 512);
        else
            k_gemm_ln<<<ROWS / 128, 256, GT_SMEM>>>(F1hi, F1lo, whi + offF2(l), wlo + offF2(l),
                                                    bff2 + l * DMODEL, y, ln2g + l * 128,
                                                    ln2b + l * 128, y, yhi, ylo, 512);
    }
}

// round 8
// speedup vs baseline: 4.1695x; 1.1306x over previous
#include <cuda_runtime.h>
#include <cuda_bf16.h>
#include <cuda_fp16.h>
#include <math_constants.h>
#include <cstdint>

#define N_NODES 32768
#define N_EDGES 524288
#define DMODEL  128
#define BATCH   32
#define SEQ     1024
#define HEADS   8
#define DFF     512
#define NTOT    (N_EDGES + N_NODES)
#define WELEMS  425984
#define GST     72
#define QST     24
#define SC2     0.360673760222241f   /* 0.25 * log2(e) */

// ---------------- mma helpers ------------------------------------------------
__device__ __forceinline__ uint32_t cvta_s(const void* p) {
    return (uint32_t)__cvta_generic_to_shared(p);
}
__device__ __forceinline__ void ldsm4(uint32_t* r, uint32_t a) {
    asm volatile("ldmatrix.sync.aligned.m8n8.x4.shared.b16 {%0,%1,%2,%3}, [%4];"
                 : "=r"(r[0]), "=r"(r[1]), "=r"(r[2]), "=r"(r[3]) : "r"(a));
}
__device__ __forceinline__ void ldsm4t(uint32_t* r, uint32_t a) {
    asm volatile("ldmatrix.sync.aligned.m8n8.x4.trans.shared.b16 {%0,%1,%2,%3}, [%4];"
                 : "=r"(r[0]), "=r"(r[1]), "=r"(r[2]), "=r"(r[3]) : "r"(a));
}
__device__ __forceinline__ void mma_bf16(float* c, const uint32_t* a, const uint32_t* b) {
    asm volatile("mma.sync.aligned.m16n8k16.row.col.f32.bf16.bf16.f32 "
                 "{%0,%1,%2,%3}, {%4,%5,%6,%7}, {%8,%9}, {%0,%1,%2,%3};"
                 : "+f"(c[0]), "+f"(c[1]), "+f"(c[2]), "+f"(c[3])
                 : "r"(a[0]), "r"(a[1]), "r"(a[2]), "r"(a[3]), "r"(b[0]), "r"(b[1]));
}
__device__ __forceinline__ void mma_f16(float* c, const uint32_t* a, const uint32_t* b) {
    asm volatile("mma.sync.aligned.m16n8k16.row.col.f32.f16.f16.f32 "
                 "{%0,%1,%2,%3}, {%4,%5,%6,%7}, {%8,%9}, {%0,%1,%2,%3};"
                 : "+f"(c[0]), "+f"(c[1]), "+f"(c[2]), "+f"(c[3])
                 : "r"(a[0]), "r"(a[1]), "r"(a[2]), "r"(a[3]), "r"(b[0]), "r"(b[1]));
}
__device__ __forceinline__ uint32_t cvt2bf(float lo, float hi) {
    uint32_t r;
    asm("cvt.rn.bf16x2.f32 %0, %1, %2;" : "=r"(r) : "f"(hi), "f"(lo));
    return r;
}
__device__ __forceinline__ uint32_t pack_h16(float lo, float hi) {
    uint32_t r;
    asm("cvt.rn.f16x2.f32 %0, %1, %2;" : "=r"(r) : "f"(hi), "f"(lo));
    return r;
}
__device__ __forceinline__ void split_pack(float a, float b, uint32_t& hi, uint32_t& lo) {
    __nv_bfloat16 ha = __float2bfloat16(a), hb = __float2bfloat16(b);
    float ra = a - __bfloat162float(ha), rb = b - __bfloat162float(hb);
    __nv_bfloat16 la = __float2bfloat16(ra), lb = __float2bfloat16(rb);
    hi = ((uint32_t)__bfloat16_as_ushort(hb) << 16) | __bfloat16_as_ushort(ha);
    lo = ((uint32_t)__bfloat16_as_ushort(lb) << 16) | __bfloat16_as_ushort(la);
}

// ---------------- scratch ----------------------------------------------------
static __device__ float g_dinv[N_NODES];
static __device__ int   g_counts[N_NODES];
static __device__ int   g_rowoff[N_NODES + 1];
static __device__ int   g_cursor[N_NODES];
static __device__ int   g_bsum[128];
static __device__ int   g_boff[128];
static __device__ int   g_csr[NTOT];
static __device__ float g_h [N_NODES * DMODEL];
static __device__ float g_y [N_NODES * DMODEL];
static __device__ __nv_bfloat16 g_whi[WELEMS];
static __device__ __nv_bfloat16 g_wlo[WELEMS];
static __device__ __nv_bfloat16 g_xrhi[N_NODES * DMODEL];
static __device__ __nv_bfloat16 g_xrlo[N_NODES * DMODEL];
static __device__ __nv_bfloat16 g_x1hi[N_NODES * DMODEL];
static __device__ __nv_bfloat16 g_x1lo[N_NODES * DMODEL];
static __device__ __nv_bfloat16 g_gxhi[N_NODES * DMODEL];
static __device__ __nv_bfloat16 g_gxlo[N_NODES * DMODEL];
static __device__ __nv_bfloat16 g_yhi[N_NODES * DMODEL];
static __device__ __nv_bfloat16 g_ylo[N_NODES * DMODEL];
static __device__ __half g_Qp[HEADS * N_NODES * 16];
static __device__ __half g_KVp[2 * HEADS * N_NODES * 16];
static __device__ __nv_bfloat16 g_Abhi[N_NODES * DMODEL];
static __device__ __nv_bfloat16 g_Ablo[N_NODES * DMODEL];
static __device__ __nv_bfloat16 g_F1hi[N_NODES * DFF];
static __device__ __nv_bfloat16 g_F1lo[N_NODES * DFF];

// ---------------- graph preprocessing ---------------------------------------
__global__ void k_init_counts(int* counts) {
    counts[blockIdx.x * blockDim.x + threadIdx.x] = 0;
}
__global__ void k_count(const int* __restrict__ eidx, int* __restrict__ counts) {
    int e = blockIdx.x * blockDim.x + threadIdx.x;
    atomicAdd(&counts[eidx[N_EDGES + e]], 1);
}

// ---- 3-phase parallel exclusive scan of (counts[i]+1), coalesced ----
__global__ void k_scan_bsum(const int* __restrict__ counts, int* __restrict__ bsum) {
    __shared__ int ws[8];
    int t = threadIdx.x;
    int c = counts[blockIdx.x * 256 + t] + 1;
#pragma unroll
    for (int o = 16; o; o >>= 1) c += __shfl_xor_sync(0xffffffffu, c, o);
    if ((t & 31) == 0) ws[t >> 5] = c;
    __syncthreads();
    if (t == 0) {
        int s = 0;
#pragma unroll
        for (int w = 0; w < 8; w++) s += ws[w];
        bsum[blockIdx.x] = s;
    }
}
__global__ void k_scan_boff(const int* __restrict__ bsum, int* __restrict__ boff) {
    __shared__ int sm[128];
    int t = threadIdx.x;
    int v = bsum[t];
    sm[t] = v;
    __syncthreads();
    for (int off = 1; off < 128; off <<= 1) {
        int u = (t >= off) ? sm[t - off] : 0;
        __syncthreads();
        sm[t] += u;
        __syncthreads();
    }
    boff[t] = sm[t] - v;   // exclusive
}
__global__ void k_scan_fin(const int* __restrict__ counts, const int* __restrict__ boff,
                           int* __restrict__ rowoff, int* __restrict__ cursor,
                           float* __restrict__ dinv) {
    __shared__ int ws[8];
    int t = threadIdx.x, lane = t & 31, w = t >> 5;
    int i = blockIdx.x * 256 + t;
    int c = counts[i] + 1;
    int x = c;
#pragma unroll
    for (int o = 1; o < 32; o <<= 1) {
        int u = __shfl_up_sync(0xffffffffu, x, o);
        if (lane >= o) x += u;
    }
    if (lane == 31) ws[w] = x;
    __syncthreads();
    int wo = 0;
#pragma unroll
    for (int k = 0; k < 8; k++) if (k < w) wo += ws[k];
    int excl = boff[blockIdx.x] + wo + x - c;
    rowoff[i] = excl;
    cursor[i] = excl;
    dinv[i] = rsqrtf((float)c);
    if (i == N_NODES - 1) rowoff[N_NODES] = excl + c;
}

__global__ void k_fill(const int* __restrict__ eidx, int* __restrict__ cursor,
                       int* __restrict__ csr) {
    int e = blockIdx.x * blockDim.x + threadIdx.x;
    int s, d;
    if (e < N_EDGES) { s = eidx[e]; d = eidx[N_EDGES + e]; }
    else             { s = d = e - N_EDGES; }
    csr[atomicAdd(&cursor[d], 1)] = s;
}

__global__ void k_aggregate(const float* __restrict__ h, const float* __restrict__ dinv,
                            const int* __restrict__ rowoff, const int* __restrict__ csr,
                            const float* __restrict__ bias,
                            __nv_bfloat16* __restrict__ ohi, __nv_bfloat16* __restrict__ olo) {
    int wid = threadIdx.x >> 5, lane = threadIdx.x & 31;
    int i = blockIdx.x * 8 + wid;
    const float4* h4 = (const float4*)h;
    float4 acc = make_float4(0.f, 0.f, 0.f, 0.f);
    int e = rowoff[i], end = rowoff[i + 1];
    for (; e + 2 <= end; e += 2) {
        int s0 = csr[e], s1 = csr[e + 1];
        float w0 = dinv[s0], w1 = dinv[s1];
        float4 v0 = h4[s0 * 32 + lane];
        float4 v1 = h4[s1 * 32 + lane];
        acc.x = fmaf(w0, v0.x, fmaf(w1, v1.x, acc.x));
        acc.y = fmaf(w0, v0.y, fmaf(w1, v1.y, acc.y));
        acc.z = fmaf(w0, v0.z, fmaf(w1, v1.z, acc.z));
        acc.w = fmaf(w0, v0.w, fmaf(w1, v1.w, acc.w));
    }
    if (e < end) {
        int s0 = csr[e];
        float w0 = dinv[s0];
        float4 v0 = h4[s0 * 32 + lane];
        acc.x = fmaf(w0, v0.x, acc.x); acc.y = fmaf(w0, v0.y, acc.y);
        acc.z = fmaf(w0, v0.z, acc.z); acc.w = fmaf(w0, v0.w, acc.w);
    }
    float di = dinv[i];
    float4 b4 = ((const float4*)bias)[lane];
    float o0 = fmaxf(fmaf(di, acc.x, b4.x), 0.f);
    float o1 = fmaxf(fmaf(di, acc.y, b4.y), 0.f);
    float o2 = fmaxf(fmaf(di, acc.z, b4.z), 0.f);
    float o3 = fmaxf(fmaf(di, acc.w, b4.w), 0.f);
    uint2 hh, ll;
    split_pack(o0, o1, hh.x, ll.x);
    split_pack(o2, o3, hh.y, ll.y);
    *(uint2*)&ohi[(size_t)i * DMODEL + lane * 4] = hh;
    *(uint2*)&olo[(size_t)i * DMODEL + lane * 4] = ll;
}

__global__ void k_cvt(const float* __restrict__ src, __nv_bfloat16* __restrict__ hi,
                      __nv_bfloat16* __restrict__ lo, float* __restrict__ fdst) {
    int i = blockIdx.x * blockDim.x + threadIdx.x;
    float4 v = ((const float4*)src)[i];
    uint2 hh, ll;
    split_pack(v.x, v.y, hh.x, ll.x);
    split_pack(v.z, v.w, hh.y, ll.y);
    ((uint2*)hi)[i] = hh;
    ((uint2*)lo)[i] = ll;
    if (fdst) ((float4*)fdst)[i] = v;
}

// ---------------- mega weight prep -------------------------------------------
struct Seg { const float* src; int K; int N; int off; int blk0; };
struct PrepArgs { Seg s[14]; int nseg; };

__global__ void k_prep_all(PrepArgs pa, __nv_bfloat16* __restrict__ hi,
                           __nv_bfloat16* __restrict__ lo) {
    int b = blockIdx.x;
    int si = 0;
    while (si + 1 < pa.nseg && pa.s[si + 1].blk0 <= b) si++;
    Seg sg = pa.s[si];
    int idx = (b - sg.blk0) * 256 + threadIdx.x;
    int k = idx / sg.N, n = idx % sg.N;
    float v = sg.src[idx];
    __nv_bfloat16 h = __float2bfloat16(v);
    __nv_bfloat16 l = __float2bfloat16(v - __bfloat162float(h));
    hi[sg.off + n * sg.K + k] = h;
    lo[sg.off + n * sg.K + k] = l;
}

// ---------------- tensor-core GEMM -------------------------------------------
#define GT_SMEM (4 * 128 * GST * 2)
__global__ void __launch_bounds__(256)
k_gemm_tc(const __nv_bfloat16* __restrict__ Ahi, const __nv_bfloat16* __restrict__ Alo,
          const __nv_bfloat16* __restrict__ Whi, const __nv_bfloat16* __restrict__ Wlo,
          const float* __restrict__ bias, float* __restrict__ Cf,
          __half* __restrict__ Ch, __nv_bfloat16* __restrict__ Chi,
          __nv_bfloat16* __restrict__ Clo, int K, int ncols, int act, float premul) {
    extern __shared__ char smem[];
    __nv_bfloat16* As_hi = (__nv_bfloat16*)smem;
    __nv_bfloat16* As_lo = (__nv_bfloat16*)(smem + 128 * GST * 2);
    __nv_bfloat16* Ws_hi = (__nv_bfloat16*)(smem + 2 * 128 * GST * 2);
    __nv_bfloat16* Ws_lo = (__nv_bfloat16*)(smem + 3 * 128 * GST * 2);

    int tid = threadIdx.x, wid = tid >> 5, lane = tid & 31;
    int wm = wid & 3, wn = wid >> 2;
    int rowBase = blockIdx.x * 128, colBase = blockIdx.y * 128;

    float acc[2][8][4];
#pragma unroll
    for (int i = 0; i < 2; i++)
#pragma unroll
        for (int j = 0; j < 8; j++)
#pragma unroll
            for (int q = 0; q < 4; q++) acc[i][j][q] = 0.f;

    int ar = (lane & 7) + ((lane >> 3) & 1) * 8;
    int ak = (lane >> 4) * 8;
    int bn = (lane & 7) + ((lane >> 4) & 1) * 8;
    int bk = ((lane >> 3) & 1) * 8;

    uint32_t sAh = cvta_s(As_hi), sAl = cvta_s(As_lo);
    uint32_t sWh = cvta_s(Ws_hi), sWl = cvta_s(Ws_lo);

    for (int kb = 0; kb < K; kb += 64) {
#pragma unroll
        for (int j = 0; j < 4; j++) {
            int i = tid + 256 * j;
            int r = i >> 3, c = i & 7;
            *(uint4*)&As_hi[r * GST + c * 8] = *(const uint4*)&Ahi[(size_t)(rowBase + r) * K + kb + c * 8];
            *(uint4*)&As_lo[r * GST + c * 8] = *(const uint4*)&Alo[(size_t)(rowBase + r) * K + kb + c * 8];
            *(uint4*)&Ws_hi[r * GST + c * 8] = *(const uint4*)&Whi[(size_t)(colBase + r) * K + kb + c * 8];
            *(uint4*)&Ws_lo[r * GST + c * 8] = *(const uint4*)&Wlo[(size_t)(colBase + r) * K + kb + c * 8];
        }
        __syncthreads();

#pragma unroll
        for (int ks = 0; ks < 64; ks += 16) {
            uint32_t ah[2][4], al[2][4];
#pragma unroll
            for (int ma = 0; ma < 2; ma++) {
                uint32_t off = (uint32_t)((wm * 32 + ma * 16 + ar) * GST + ks + ak) * 2;
                ldsm4(ah[ma], sAh + off);
                ldsm4(al[ma], sAl + off);
            }
            uint32_t bh[4][4], bl[4][4];
#pragma unroll
            for (int nb = 0; nb < 4; nb++) {
                uint32_t off = (uint32_t)((wn * 64 + nb * 16 + bn) * GST + ks + bk) * 2;
                ldsm4(bh[nb], sWh + off);
                ldsm4(bl[nb], sWl + off);
            }
#pragma unroll
            for (int ma = 0; ma < 2; ma++)
#pragma unroll
                for (int na = 0; na < 8; na++) {
                    float* c = acc[ma][na];
                    const uint32_t* pbh = &bh[na >> 1][(na & 1) * 2];
                    const uint32_t* pbl = &bl[na >> 1][(na & 1) * 2];
                    mma_bf16(c, ah[ma], pbh);
                    mma_bf16(c, ah[ma], pbl);
                    mma_bf16(c, al[ma], pbh);
                }
        }
        __syncthreads();
    }

#pragma unroll
    for (int ma = 0; ma < 2; ma++)
#pragma unroll
        for (int na = 0; na < 8; na++) {
            int row = rowBase + wm * 32 + ma * 16 + (lane >> 2);
            int col = colBase + wn * 64 + na * 8 + (lane & 3) * 2;
            float b0 = 0.f, b1 = 0.f;
            if (bias) { b0 = bias[col]; b1 = bias[col + 1]; }
            float v0 = (acc[ma][na][0] + b0) * premul, v1 = (acc[ma][na][1] + b1) * premul;
            float v2 = (acc[ma][na][2] + b0) * premul, v3 = (acc[ma][na][3] + b1) * premul;
            if (act) {
                v0 = fmaxf(v0, 0.f); v1 = fmaxf(v1, 0.f);
                v2 = fmaxf(v2, 0.f); v3 = fmaxf(v3, 0.f);
            }
            if (Cf) {
                size_t i0 = (size_t)row * ncols + col, i1 = (size_t)(row + 8) * ncols + col;
                *(float2*)&Cf[i0] = make_float2(v0, v1);
                *(float2*)&Cf[i1] = make_float2(v2, v3);
            }
            if (Ch) {   // head-major f16: [col>>4][row][col&15]
                size_t j0 = ((size_t)(col >> 4) * N_NODES + row) * 16 + (col & 15);
                size_t j1 = ((size_t)(col >> 4) * N_NODES + row + 8) * 16 + (col & 15);
                *(uint32_t*)&Ch[j0] = pack_h16(v0, v1);
                *(uint32_t*)&Ch[j1] = pack_h16(v2, v3);
            }
            if (Chi) {
                size_t i0 = (size_t)row * ncols + col, i1 = (size_t)(row + 8) * ncols + col;
                uint32_t h0, l0, h1, l1;
                split_pack(v0, v1, h0, l0);
                split_pack(v2, v3, h1, l1);
                *(uint32_t*)&Chi[i0] = h0; *(uint32_t*)&Clo[i0] = l0;
                *(uint32_t*)&Chi[i1] = h1; *(uint32_t*)&Clo[i1] = l1;
            }
        }
}

// ---------------- GEMM + residual + LayerNorm fused ---------------------------
__global__ void __launch_bounds__(256)
k_gemm_ln(const __nv_bfloat16* __restrict__ Ahi, const __nv_bfloat16* __restrict__ Alo,
          const __nv_bfloat16* __restrict__ Whi, const __nv_bfloat16* __restrict__ Wlo,
          const float* __restrict__ bias, const float* __restrict__ R,
          const float* __restrict__ gamma, const float* __restrict__ beta,
          float* __restrict__ Yf, __nv_bfloat16* __restrict__ Yhi,
          __nv_bfloat16* __restrict__ Ylo, int K) {
    extern __shared__ char smem[];
    __nv_bfloat16* As_hi = (__nv_bfloat16*)smem;
    __nv_bfloat16* As_lo = (__nv_bfloat16*)(smem + 128 * GST * 2);
    __nv_bfloat16* Ws_hi = (__nv_bfloat16*)(smem + 2 * 128 * GST * 2);
    __nv_bfloat16* Ws_lo = (__nv_bfloat16*)(smem + 3 * 128 * GST * 2);
    __shared__ float red[128][2][2];

    int tid = threadIdx.x, wid = tid >> 5, lane = tid & 31;
    int wm = wid & 3, wn = wid >> 2;
    int rowBase = blockIdx.x * 128;

    float acc[2][8][4];
#pragma unroll
    for (int i = 0; i < 2; i++)
#pragma unroll
        for (int j = 0; j < 8; j++)
#pragma unroll
            for (int q = 0; q < 4; q++) acc[i][j][q] = 0.f;

    int ar = (lane & 7) + ((lane >> 3) & 1) * 8;
    int ak = (lane >> 4) * 8;
    int bn = (lane & 7) + ((lane >> 4) & 1) * 8;
    int bk = ((lane >> 3) & 1) * 8;

    uint32_t sAh = cvta_s(As_hi), sAl = cvta_s(As_lo);
    uint32_t sWh = cvta_s(Ws_hi), sWl = cvta_s(Ws_lo);

    for (int kb = 0; kb < K; kb += 64) {
#pragma unroll
        for (int j = 0; j < 4; j++) {
            int i = tid + 256 * j;
            int r = i >> 3, c = i & 7;
            *(uint4*)&As_hi[r * GST + c * 8] = *(const uint4*)&Ahi[(size_t)(rowBase + r) * K + kb + c * 8];
            *(uint4*)&As_lo[r * GST + c * 8] = *(const uint4*)&Alo[(size_t)(rowBase + r) * K + kb + c * 8];
            *(uint4*)&Ws_hi[r * GST + c * 8] = *(const uint4*)&Whi[(size_t)r * K + kb + c * 8];
            *(uint4*)&Ws_lo[r * GST + c * 8] = *(const uint4*)&Wlo[(size_t)r * K + kb + c * 8];
        }
        __syncthreads();

#pragma unroll
        for (int ks = 0; ks < 64; ks += 16) {
            uint32_t ah[2][4], al[2][4];
#pragma unroll
            for (int ma = 0; ma < 2; ma++) {
                uint32_t off = (uint32_t)((wm * 32 + ma * 16 + ar) * GST + ks + ak) * 2;
                ldsm4(ah[ma], sAh + off);
                ldsm4(al[ma], sAl + off);
            }
            uint32_t bh[4][4], bl[4][4];
#pragma unroll
            for (int nb = 0; nb < 4; nb++) {
                uint32_t off = (uint32_t)((wn * 64 + nb * 16 + bn) * GST + ks + bk) * 2;
                ldsm4(bh[nb], sWh + off);
                ldsm4(bl[nb], sWl + off);
            }
#pragma unroll
            for (int ma = 0; ma < 2; ma++)
#pragma unroll
                for (int na = 0; na < 8; na++) {
                    float* c = acc[ma][na];
                    const uint32_t* pbh = &bh[na >> 1][(na & 1) * 2];
                    const uint32_t* pbl = &bl[na >> 1][(na & 1) * 2];
                    mma_bf16(c, ah[ma], pbh);
                    mma_bf16(c, ah[ma], pbl);
                    mma_bf16(c, al[ma], pbh);
                }
        }
        __syncthreads();
    }

#pragma unroll
    for (int ma = 0; ma < 2; ma++)
#pragma unroll
        for (int na = 0; na < 8; na++) {
            int row = rowBase + wm * 32 + ma * 16 + (lane >> 2);
            int col = wn * 64 + na * 8 + (lane & 3) * 2;
            float b0 = 0.f, b1 = 0.f;
            if (bias) { b0 = bias[col]; b1 = bias[col + 1]; }
            float2 r0 = *(const float2*)&R[(size_t)row * DMODEL + col];
            float2 r1 = *(const float2*)&R[(size_t)(row + 8) * DMODEL + col];
            acc[ma][na][0] += b0 + r0.x;
            acc[ma][na][1] += b1 + r0.y;
            acc[ma][na][2] += b0 + r1.x;
            acc[ma][na][3] += b1 + r1.y;
        }

#pragma unroll
    for (int ma = 0; ma < 2; ma++)
#pragma unroll
        for (int hr = 0; hr < 2; hr++) {
            float s = 0.f, s2 = 0.f;
#pragma unroll
            for (int na = 0; na < 8; na++) {
                float a = acc[ma][na][hr * 2], b = acc[ma][na][hr * 2 + 1];
                s += a + b;
                s2 += a * a + b * b;
            }
            s  += __shfl_xor_sync(0xffffffffu, s, 1);
            s  += __shfl_xor_sync(0xffffffffu, s, 2);
            s2 += __shfl_xor_sync(0xffffffffu, s2, 1);
            s2 += __shfl_xor_sync(0xffffffffu, s2, 2);
            int rl = wm * 32 + ma * 16 + (lane >> 2) + hr * 8;
            if ((lane & 3) == 0) { red[rl][wn][0] = s; red[rl][wn][1] = s2; }
        }
    __syncthreads();

#pragma unroll
    for (int ma = 0; ma < 2; ma++)
#pragma unroll
        for (int hr = 0; hr < 2; hr++) {
            int rl = wm * 32 + ma * 16 + (lane >> 2) + hr * 8;
            float S  = red[rl][0][0] + red[rl][1][0];
            float S2 = red[rl][0][1] + red[rl][1][1];
            float mu = S * (1.f / 128.f);
            float var = S2 * (1.f / 128.f) - mu * mu;
            float inv = rsqrtf(var + 1e-5f);
            int row = rowBase + rl;
#pragma unroll
            for (int na = 0; na < 8; na++) {
                int col = wn * 64 + na * 8 + (lane & 3) * 2;
                float g0 = gamma[col], g1 = gamma[col + 1];
                float t0 = beta[col], t1 = beta[col + 1];
                float v0 = fmaf((acc[ma][na][hr * 2] - mu) * inv, g0, t0);
                float v1 = fmaf((acc[ma][na][hr * 2 + 1] - mu) * inv, g1, t1);
                *(float2*)&Yf[(size_t)row * DMODEL + col] = make_float2(v0, v1);
                if (Yhi) {
                    uint32_t hh, ll;
                    split_pack(v0, v1, hh, ll);
                    *(uint32_t*)&Yhi[(size_t)row * DMODEL + col] = hh;
                    *(uint32_t*)&Ylo[(size_t)row * DMODEL + col] = ll;
                }
            }
        }
}

// ---------------- flash attention (f16, h2exp2) -------------------------------
__global__ void __launch_bounds__(256)
k_attn_tc(const __half* __restrict__ Qp, const __half* __restrict__ KVp,
          __nv_bfloat16* __restrict__ Ohi, __nv_bfloat16* __restrict__ Olo) {
    __shared__ __half sQ[128 * QST];
    __shared__ __half sK[64 * QST];
    __shared__ __half sV[64 * QST];

    int b = blockIdx.z, hd = blockIdx.y, qbase = blockIdx.x * 128;
    int tid = threadIdx.x, wm = tid >> 5, lane = tid & 31;

    const __half* Qh = Qp + ((size_t)hd * N_NODES + b * SEQ + qbase) * 16;
    const __half* Kh = KVp + ((size_t)hd * N_NODES + b * SEQ) * 16;
    const __half* Vh = KVp + ((size_t)(hd + HEADS) * N_NODES + b * SEQ) * 16;

    {
        int row = tid >> 1, half = tid & 1;
        *(uint4*)&sQ[row * QST + half * 8] = *(const uint4*)&Qh[row * 16 + half * 8];
    }
    int slot = tid & 127, trow = slot >> 1, thalf = slot & 1;
    const __half* tsrc = (tid < 128) ? Kh : Vh;
    __half* tdst = (tid < 128) ? sK : sV;

    uint4 rbuf = *(const uint4*)&tsrc[(size_t)trow * 16 + thalf * 8];
    *(uint4*)&tdst[trow * QST + thalf * 8] = rbuf;
    __syncthreads();

    int ar = (lane & 7) + ((lane >> 3) & 1) * 8;
    int ak = (lane >> 4) * 8;
    int bn = (lane & 7) + ((lane >> 4) & 1) * 8;
    int bk = ((lane >> 3) & 1) * 8;
    int vkey = (lane & 7) + ((lane >> 3) & 1) * 8;
    int vdh = ((lane >> 4) & 1) * 8;

    uint32_t sQa = cvta_s(sQ), sKa = cvta_s(sK), sVa = cvta_s(sV);
    uint32_t qf[4];
    ldsm4(qf, sQa + (uint32_t)((wm * 16 + ar) * QST + ak) * 2);

    float mst[2] = {-CUDART_INF_F, -CUDART_INF_F};
    float lst[2] = {0.f, 0.f};
    float of[2][4] = {{0.f, 0.f, 0.f, 0.f}, {0.f, 0.f, 0.f, 0.f}};

    for (int kt = 0; kt < SEQ / 64; kt++) {
        if (kt + 1 < SEQ / 64)
            rbuf = *(const uint4*)&tsrc[(size_t)((kt + 1) * 64 + trow) * 16 + thalf * 8];

        float sf[8][4];
#pragma unroll
        for (int j = 0; j < 8; j++)
#pragma unroll
            for (int q = 0; q < 4; q++) sf[j][q] = 0.f;
#pragma unroll
        for (int nb = 0; nb < 4; nb++) {
            uint32_t kf[4];
            ldsm4(kf, sKa + (uint32_t)((nb * 16 + bn) * QST + bk) * 2);
            mma_f16(sf[2 * nb], qf, &kf[0]);
            mma_f16(sf[2 * nb + 1], qf, &kf[2]);
        }

        __half2 ep[8][2];
#pragma unroll
        for (int hr = 0; hr < 2; hr++) {
            float mx = sf[0][hr * 2];
#pragma unroll
            for (int j = 0; j < 8; j++) {
                mx = fmaxf(mx, sf[j][hr * 2]);
                mx = fmaxf(mx, sf[j][hr * 2 + 1]);
            }
            mx = fmaxf(mx, __shfl_xor_sync(0xffffffffu, mx, 1));
            mx = fmaxf(mx, __shfl_xor_sync(0xffffffffu, mx, 2));
            float mnew = fmaxf(mst[hr], mx);
            float corr = exp2f(mst[hr] - mnew);
            __half2 hsum = __floats2half2_rn(0.f, 0.f);
#pragma unroll
            for (int j = 0; j < 8; j++) {
                float d0 = sf[j][hr * 2] - mnew;
                float d1 = sf[j][hr * 2 + 1] - mnew;
                __half2 p2 = h2exp2(__floats2half2_rn(d0, d1));
                ep[j][hr] = p2;
                hsum = __hadd2(hsum, p2);
            }
            float2 fs = __half22float2(hsum);
            float rsum = fs.x + fs.y;
            rsum += __shfl_xor_sync(0xffffffffu, rsum, 1);
            rsum += __shfl_xor_sync(0xffffffffu, rsum, 2);
            lst[hr] = lst[hr] * corr + rsum;
            mst[hr] = mnew;
#pragma unroll
            for (int nh = 0; nh < 2; nh++) {
                of[nh][hr * 2] *= corr;
                of[nh][hr * 2 + 1] *= corr;
            }
        }

#pragma unroll
        for (int kf = 0; kf < 4; kf++) {
            uint32_t vf[4];
            ldsm4t(vf, sVa + (uint32_t)((kf * 16 + vkey) * QST + vdh) * 2);
            uint32_t pa[4];
            pa[0] = *(uint32_t*)&ep[2 * kf][0];
            pa[1] = *(uint32_t*)&ep[2 * kf][1];
            pa[2] = *(uint32_t*)&ep[2 * kf + 1][0];
            pa[3] = *(uint32_t*)&ep[2 * kf + 1][1];
            mma_f16(of[0], pa, &vf[0]);
            mma_f16(of[1], pa, &vf[2]);
        }

        __syncthreads();
        if (kt + 1 < SEQ / 64)
            *(uint4*)&tdst[trow * QST + thalf * 8] = rbuf;
        __syncthreads();
    }

#pragma unroll
    for (int hr = 0; hr < 2; hr++) {
        float inv = 1.f / lst[hr];
        int grow = b * SEQ + qbase + wm * 16 + (lane >> 2) + hr * 8;
#pragma unroll
        for (int nh = 0; nh < 2; nh++) {
            float v0 = of[nh][hr * 2] * inv;
            float v1 = of[nh][hr * 2 + 1] * inv;
            int col = hd * 16 + nh * 8 + (lane & 3) * 2;
            uint32_t hh, ll;
            split_pack(v0, v1, hh, ll);
            *(uint32_t*)&Ohi[(size_t)grow * DMODEL + col] = hh;
            *(uint32_t*)&Olo[(size_t)grow * DMODEL + col] = ll;
        }
    }
}

// ---------------- host orchestration -----------------------------------------
extern "C" void kernel_launch(void* const* d_in, const int* in_sizes, int n_in,
                              void* d_out, int out_size) {
    const float* enc   = (const float*)d_in[0];
    const float* xraw  = (const float*)d_in[2];
    const int*   eidx  = (const int*)  d_in[3];
    const float* Wg1   = (const float*)d_in[4];
    const float* bg1   = (const float*)d_in[5];
    const float* Wg2   = (const float*)d_in[6];
    const float* bg2   = (const float*)d_in[7];
    const float* Wq    = (const float*)d_in[8];
    const float* Wk    = (const float*)d_in[9];
    const float* Wv    = (const float*)d_in[10];
    const float* Wo    = (const float*)d_in[11];
    const float* Wff1  = (const float*)d_in[12];
    const float* bff1  = (const float*)d_in[13];
    const float* Wff2  = (const float*)d_in[14];
    const float* bff2  = (const float*)d_in[15];
    const float* ln1g  = (const float*)d_in[16];
    const float* ln1b  = (const float*)d_in[17];
    const float* ln2g  = (const float*)d_in[18];
    const float* ln2b  = (const float*)d_in[19];
    float* outp = (float*)d_out;

    float *dinv, *h, *y;
    int *counts, *rowoff, *cursor, *csr, *bsum, *boff;
    __nv_bfloat16 *whi, *wlo, *xrhi, *xrlo, *x1hi, *x1lo, *gxhi, *gxlo;
    __nv_bfloat16 *yhi, *ylo, *Abhi, *Ablo, *F1hi, *F1lo;
    __half *Qp, *KVp;
    cudaGetSymbolAddress((void**)&dinv,   g_dinv);
    cudaGetSymbolAddress((void**)&counts, g_counts);
    cudaGetSymbolAddress((void**)&rowoff, g_rowoff);
    cudaGetSymbolAddress((void**)&cursor, g_cursor);
    cudaGetSymbolAddress((void**)&csr,    g_csr);
    cudaGetSymbolAddress((void**)&bsum,   g_bsum);
    cudaGetSymbolAddress((void**)&boff,   g_boff);
    cudaGetSymbolAddress((void**)&h,   g_h);
    cudaGetSymbolAddress((void**)&y,   g_y);
    cudaGetSymbolAddress((void**)&whi, g_whi);
    cudaGetSymbolAddress((void**)&wlo, g_wlo);
    cudaGetSymbolAddress((void**)&xrhi, g_xrhi);
    cudaGetSymbolAddress((void**)&xrlo, g_xrlo);
    cudaGetSymbolAddress((void**)&x1hi, g_x1hi);
    cudaGetSymbolAddress((void**)&x1lo, g_x1lo);
    cudaGetSymbolAddress((void**)&gxhi, g_gxhi);
    cudaGetSymbolAddress((void**)&gxlo, g_gxlo);
    cudaGetSymbolAddress((void**)&yhi, g_yhi);
    cudaGetSymbolAddress((void**)&ylo, g_ylo);
    cudaGetSymbolAddress((void**)&Qp,  g_Qp);
    cudaGetSymbolAddress((void**)&KVp, g_KVp);
    cudaGetSymbolAddress((void**)&Abhi, g_Abhi);
    cudaGetSymbolAddress((void**)&Ablo, g_Ablo);
    cudaGetSymbolAddress((void**)&F1hi, g_F1hi);
    cudaGetSymbolAddress((void**)&F1lo, g_F1lo);

    cudaFuncSetAttribute(k_gemm_tc, cudaFuncAttributeMaxDynamicSharedMemorySize, GT_SMEM);
    cudaFuncSetAttribute(k_gemm_ln, cudaFuncAttributeMaxDynamicSharedMemorySize, GT_SMEM);

    const int ROWS = N_NODES;
    const int OFF_G1 = 0, OFF_G2 = 16384;
    const int LSTR = 4 * 16384 + 2 * 65536;
    auto offQ  = [&](int l) { return 32768 + l * LSTR; };
    auto offK  = [&](int l) { return offQ(l) + 16384; };
    auto offO  = [&](int l) { return offQ(l) + 49152; };
    auto offF1 = [&](int l) { return offQ(l) + 65536; };
    auto offF2 = [&](int l) { return offQ(l) + 131072; };

    PrepArgs pa;
    int blk = 0, si = 0;
    auto addseg = [&](const float* src, int K, int N, int off) {
        pa.s[si].src = src; pa.s[si].K = K; pa.s[si].N = N;
        pa.s[si].off = off; pa.s[si].blk0 = blk;
        si++; blk += K * N / 256;
    };
    addseg(Wg1, 128, 128, OFF_G1);
    addseg(Wg2, 128, 128, OFF_G2);
    for (int l = 0; l < 2; l++) {
        addseg(Wq + l * 16384, 128, 128, offQ(l));
        addseg(Wk + l * 16384, 128, 128, offK(l));
        addseg(Wv + l * 16384, 128, 128, offK(l) + 16384);
        addseg(Wo + l * 16384, 128, 128, offO(l));
        addseg(Wff1 + l * 65536, 128, 512, offF1(l));
        addseg(Wff2 + l * 65536, 512, 128, offF2(l));
    }
    pa.nseg = si;
    k_prep_all<<<blk, 256>>>(pa, whi, wlo);

    auto GEMM = [&](const __nv_bfloat16* Ah, const __nv_bfloat16* Al, int woff,
                    const float* bias, float* Cf, __half* Ch,
                    __nv_bfloat16* Chi, __nv_bfloat16* Clo, int K, int ncols,
                    int act, float premul) {
        dim3 g(ROWS / 128, ncols / 128);
        k_gemm_tc<<<g, 256, GT_SMEM>>>(Ah, Al, whi + woff, wlo + woff, bias,
                                       Cf, Ch, Chi, Clo, K, ncols, act, premul);
    };

    // ---- graph preprocessing + conversions ----
    k_init_counts<<<N_NODES / 256, 256>>>(counts);
    k_count<<<N_EDGES / 256, 256>>>(eidx, counts);
    k_scan_bsum<<<128, 256>>>(counts, bsum);
    k_scan_boff<<<1, 128>>>(bsum, boff);
    k_scan_fin<<<128, 256>>>(counts, boff, rowoff, cursor, dinv);
    k_fill<<<NTOT / 256, 256>>>(eidx, cursor, csr);
    k_cvt<<<N_NODES * DMODEL / 1024, 256>>>(xraw, xrhi, xrlo, nullptr);
    k_cvt<<<N_NODES * DMODEL / 1024, 256>>>(enc, yhi, ylo, y);

    // ---- GCN stack ----
    GEMM(xrhi, xrlo, OFF_G1, nullptr, h, nullptr, nullptr, nullptr, 128, 128, 0, 1.f);
    k_aggregate<<<N_NODES / 8, 256>>>(h, dinv, rowoff, csr, bg1, x1hi, x1lo);
    GEMM(x1hi, x1lo, OFF_G2, nullptr, h, nullptr, nullptr, nullptr, 128, 128, 0, 1.f);
    k_aggregate<<<N_NODES / 8, 256>>>(h, dinv, rowoff, csr, bg2, gxhi, gxlo);

    // ---- transformer layers ----
    for (int l = 0; l < 2; l++) {
        GEMM(yhi, ylo, offQ(l), nullptr, nullptr, Qp, nullptr, nullptr, 128, 128, 0, SC2);
        GEMM(gxhi, gxlo, offK(l), nullptr, nullptr, KVp, nullptr, nullptr, 128, 256, 0, 1.f);
        k_attn_tc<<<dim3(SEQ / 128, HEADS, BATCH), 256>>>(Qp, KVp, Abhi, Ablo);
        k_gemm_ln<<<ROWS / 128, 256, GT_SMEM>>>(Abhi, Ablo, whi + offO(l), wlo + offO(l),
                                                nullptr, y, ln1g + l * 128, ln1b + l * 128,
                                                y, yhi, ylo, 128);
        GEMM(yhi, ylo, offF1(l), bff1 + l * DFF, nullptr, nullptr, F1hi, F1lo, 128, DFF, 1, 1.f);
        if (l == 1)
            k_gemm_ln<<<ROWS / 128, 256, GT_SMEM>>>(F1hi, F1lo, whi + offF2(l), wlo + offF2(l),
                                                    bff2 + l * DMODEL, y, ln2g + l * 128,
                                                    ln2b + l * 128, outp, nullptr, nullptr, 512);
        else
            k_gemm_ln<<<ROWS / 128, 256, GT_SMEM>>>(F1hi, F1lo, whi + offF2(l), wlo + offF2(l),
                                                    bff2 + l * DMODEL, y, ln2g + l * 128,
                                                    ln2b + l * 128, y, yhi, ylo, 512);
    }
}

// round 11
// speedup vs baseline: 4.2176x; 1.0115x over previous
#include <cuda_runtime.h>
#include <cuda_bf16.h>
#include <cuda_fp16.h>
#include <math_constants.h>
#include <cstdint>

#define N_NODES 32768
#define N_EDGES 524288
#define DMODEL  128
#define BATCH   32
#define SEQ     1024
#define HEADS   8
#define DFF     512
#define NTOT    (N_EDGES + N_NODES)
#define WELEMS  425984
#define GST     72
#define QST     24
#define SC2     0.360673760222241f   /* 0.25 * log2(e) */

// ---------------- mma helpers ------------------------------------------------
__device__ __forceinline__ uint32_t cvta_s(const void* p) {
    return (uint32_t)__cvta_generic_to_shared(p);
}
__device__ __forceinline__ void ldsm4(uint32_t* r, uint32_t a) {
    asm volatile("ldmatrix.sync.aligned.m8n8.x4.shared.b16 {%0,%1,%2,%3}, [%4];"
                 : "=r"(r[0]), "=r"(r[1]), "=r"(r[2]), "=r"(r[3]) : "r"(a));
}
__device__ __forceinline__ void ldsm4t(uint32_t* r, uint32_t a) {
    asm volatile("ldmatrix.sync.aligned.m8n8.x4.trans.shared.b16 {%0,%1,%2,%3}, [%4];"
                 : "=r"(r[0]), "=r"(r[1]), "=r"(r[2]), "=r"(r[3]) : "r"(a));
}
__device__ __forceinline__ void mma_bf16(float* c, const uint32_t* a, const uint32_t* b) {
    asm volatile("mma.sync.aligned.m16n8k16.row.col.f32.bf16.bf16.f32 "
                 "{%0,%1,%2,%3}, {%4,%5,%6,%7}, {%8,%9}, {%0,%1,%2,%3};"
                 : "+f"(c[0]), "+f"(c[1]), "+f"(c[2]), "+f"(c[3])
                 : "r"(a[0]), "r"(a[1]), "r"(a[2]), "r"(a[3]), "r"(b[0]), "r"(b[1]));
}
__device__ __forceinline__ void mma_f16(float* c, const uint32_t* a, const uint32_t* b) {
    asm volatile("mma.sync.aligned.m16n8k16.row.col.f32.f16.f16.f32 "
                 "{%0,%1,%2,%3}, {%4,%5,%6,%7}, {%8,%9}, {%0,%1,%2,%3};"
                 : "+f"(c[0]), "+f"(c[1]), "+f"(c[2]), "+f"(c[3])
                 : "r"(a[0]), "r"(a[1]), "r"(a[2]), "r"(a[3]), "r"(b[0]), "r"(b[1]));
}
__device__ __forceinline__ uint32_t cvt2bf(float lo, float hi) {
    uint32_t r;
    asm("cvt.rn.bf16x2.f32 %0, %1, %2;" : "=r"(r) : "f"(hi), "f"(lo));
    return r;
}
__device__ __forceinline__ uint32_t pack_h16(float lo, float hi) {
    uint32_t r;
    asm("cvt.rn.f16x2.f32 %0, %1, %2;" : "=r"(r) : "f"(hi), "f"(lo));
    return r;
}
__device__ __forceinline__ void split_pack(float a, float b, uint32_t& hi, uint32_t& lo) {
    __nv_bfloat16 ha = __float2bfloat16(a), hb = __float2bfloat16(b);
    float ra = a - __bfloat162float(ha), rb = b - __bfloat162float(hb);
    __nv_bfloat16 la = __float2bfloat16(ra), lb = __float2bfloat16(rb);
    hi = ((uint32_t)__bfloat16_as_ushort(hb) << 16) | __bfloat16_as_ushort(ha);
    lo = ((uint32_t)__bfloat16_as_ushort(lb) << 16) | __bfloat16_as_ushort(la);
}

// ---------------- scratch ----------------------------------------------------
static __device__ float g_dinv[N_NODES];
static __device__ int   g_counts[N_NODES];
static __device__ int   g_rowoff[N_NODES + 1];
static __device__ int   g_cursor[N_NODES];
static __device__ int   g_bsum[128];
static __device__ int   g_boff[128];
static __device__ int   g_csr[NTOT];
static __device__ __nv_bfloat16 g_h[N_NODES * DMODEL];     // GCN branch: bf16
static __device__ float g_y [N_NODES * DMODEL];
static __device__ __nv_bfloat16 g_whi[WELEMS];
static __device__ __nv_bfloat16 g_wlo[WELEMS];
static __device__ __nv_bfloat16 g_xrhi[N_NODES * DMODEL];
static __device__ __nv_bfloat16 g_x1hi[N_NODES * DMODEL];
static __device__ __nv_bfloat16 g_gxhi[N_NODES * DMODEL];
static __device__ __nv_bfloat16 g_yhi[N_NODES * DMODEL];
static __device__ __nv_bfloat16 g_ylo[N_NODES * DMODEL];
static __device__ __half g_Qp[HEADS * N_NODES * 16];
static __device__ __half g_KVp[2 * HEADS * N_NODES * 16];
static __device__ __nv_bfloat16 g_Abhi[N_NODES * DMODEL];
static __device__ __nv_bfloat16 g_F1hi[N_NODES * DFF];
static __device__ __nv_bfloat16 g_F1lo[N_NODES * DFF];

// ---------------- graph preprocessing ---------------------------------------
__global__ void k_count(const int* __restrict__ eidx, int* __restrict__ counts) {
    int e = blockIdx.x * blockDim.x + threadIdx.x;
    atomicAdd(&counts[eidx[N_EDGES + e]], 1);
}
__global__ void k_scan_bsum(const int* __restrict__ counts, int* __restrict__ bsum) {
    __shared__ int ws[8];
    int t = threadIdx.x;
    int c = counts[blockIdx.x * 256 + t] + 1;
#pragma unroll
    for (int o = 16; o; o >>= 1) c += __shfl_xor_sync(0xffffffffu, c, o);
    if ((t & 31) == 0) ws[t >> 5] = c;
    __syncthreads();
    if (t == 0) {
        int s = 0;
#pragma unroll
        for (int w = 0; w < 8; w++) s += ws[w];
        bsum[blockIdx.x] = s;
    }
}
__global__ void k_scan_boff(const int* __restrict__ bsum, int* __restrict__ boff) {
    __shared__ int sm[128];
    int t = threadIdx.x;
    int v = bsum[t];
    sm[t] = v;
    __syncthreads();
    for (int off = 1; off < 128; off <<= 1) {
        int u = (t >= off) ? sm[t - off] : 0;
        __syncthreads();
        sm[t] += u;
        __syncthreads();
    }
    boff[t] = sm[t] - v;
}
__global__ void k_scan_fin(const int* __restrict__ counts, const int* __restrict__ boff,
                           int* __restrict__ rowoff, int* __restrict__ cursor,
                           float* __restrict__ dinv) {
    __shared__ int ws[8];
    int t = threadIdx.x, lane = t & 31, w = t >> 5;
    int i = blockIdx.x * 256 + t;
    int c = counts[i] + 1;
    int x = c;
#pragma unroll
    for (int o = 1; o < 32; o <<= 1) {
        int u = __shfl_up_sync(0xffffffffu, x, o);
        if (lane >= o) x += u;
    }
    if (lane == 31) ws[w] = x;
    __syncthreads();
    int wo = 0;
#pragma unroll
    for (int k = 0; k < 8; k++) if (k < w) wo += ws[k];
    int excl = boff[blockIdx.x] + wo + x - c;
    rowoff[i] = excl;
    cursor[i] = excl;
    dinv[i] = rsqrtf((float)c);
    if (i == N_NODES - 1) rowoff[N_NODES] = excl + c;
}
__global__ void k_fill(const int* __restrict__ eidx, int* __restrict__ cursor,
                       int* __restrict__ csr) {
    int e = blockIdx.x * blockDim.x + threadIdx.x;
    int s, d;
    if (e < N_EDGES) { s = eidx[e]; d = eidx[N_EDGES + e]; }
    else             { s = d = e - N_EDGES; }
    csr[atomicAdd(&cursor[d], 1)] = s;
}

// aggregate over bf16 h rows (256 B/row gather), emits bf16
__global__ void k_aggregate(const __nv_bfloat16* __restrict__ h, const float* __restrict__ dinv,
                            const int* __restrict__ rowoff, const int* __restrict__ csr,
                            const float* __restrict__ bias,
                            __nv_bfloat16* __restrict__ ohi) {
    int wid = threadIdx.x >> 5, lane = threadIdx.x & 31;
    int i = blockIdx.x * 8 + wid;
    const uint2* h2 = (const uint2*)h;      // 4 bf16 per lane-slot
    float acc0 = 0.f, acc1 = 0.f, acc2 = 0.f, acc3 = 0.f;
    int e = rowoff[i], end = rowoff[i + 1];
    for (; e < end; e++) {
        int s0 = csr[e];
        float w0 = dinv[s0];
        uint2 u = h2[s0 * 32 + lane];
        __nv_bfloat162 p0 = *(__nv_bfloat162*)&u.x;
        __nv_bfloat162 p1 = *(__nv_bfloat162*)&u.y;
        acc0 = fmaf(w0, __bfloat162float(p0.x), acc0);
        acc1 = fmaf(w0, __bfloat162float(p0.y), acc1);
        acc2 = fmaf(w0, __bfloat162float(p1.x), acc2);
        acc3 = fmaf(w0, __bfloat162float(p1.y), acc3);
    }
    float di = dinv[i];
    float4 b4 = ((const float4*)bias)[lane];
    float o0 = fmaxf(fmaf(di, acc0, b4.x), 0.f);
    float o1 = fmaxf(fmaf(di, acc1, b4.y), 0.f);
    float o2 = fmaxf(fmaf(di, acc2, b4.z), 0.f);
    float o3 = fmaxf(fmaf(di, acc3, b4.w), 0.f);
    uint2 hh;
    hh.x = cvt2bf(o0, o1);
    hh.y = cvt2bf(o2, o3);
    *(uint2*)&ohi[(size_t)i * DMODEL + lane * 4] = hh;
}

__global__ void k_cvt(const float* __restrict__ src, __nv_bfloat16* __restrict__ hi,
                      __nv_bfloat16* __restrict__ lo, float* __restrict__ fdst) {
    int i = blockIdx.x * blockDim.x + threadIdx.x;
    float4 v = ((const float4*)src)[i];
    if (lo) {
        uint2 hh, ll;
        split_pack(v.x, v.y, hh.x, ll.x);
        split_pack(v.z, v.w, hh.y, ll.y);
        ((uint2*)hi)[i] = hh;
        ((uint2*)lo)[i] = ll;
    } else {
        uint2 hh;
        hh.x = cvt2bf(v.x, v.y);
        hh.y = cvt2bf(v.z, v.w);
        ((uint2*)hi)[i] = hh;
    }
    if (fdst) ((float4*)fdst)[i] = v;
}

// ---------------- mega weight prep -------------------------------------------
struct Seg { const float* src; int K; int N; int off; int blk0; };
struct PrepArgs { Seg s[14]; int nseg; };

__global__ void k_prep_all(PrepArgs pa, __nv_bfloat16* __restrict__ hi,
                           __nv_bfloat16* __restrict__ lo) {
    int b = blockIdx.x;
    int si = 0;
    while (si + 1 < pa.nseg && pa.s[si + 1].blk0 <= b) si++;
    Seg sg = pa.s[si];
    int idx = (b - sg.blk0) * 256 + threadIdx.x;
    int k = idx / sg.N, n = idx % sg.N;
    float v = sg.src[idx];
    __nv_bfloat16 h = __float2bfloat16(v);
    __nv_bfloat16 l = __float2bfloat16(v - __bfloat162float(h));
    hi[sg.off + n * sg.K + k] = h;
    lo[sg.off + n * sg.K + k] = l;
}

// ---------------- tensor-core GEMM (hi/lo optional on A and W) ---------------
#define GT_SMEM (4 * 128 * GST * 2)
__global__ void __launch_bounds__(256)
k_gemm_tc(const __nv_bfloat16* __restrict__ Ahi, const __nv_bfloat16* __restrict__ Alo,
          const __nv_bfloat16* __restrict__ Whi, const __nv_bfloat16* __restrict__ Wlo,
          const float* __restrict__ bias, float* __restrict__ Cf,
          __half* __restrict__ Ch, __nv_bfloat16* __restrict__ Chi,
          __nv_bfloat16* __restrict__ Clo, int K, int ncols, int act, float premul) {
    extern __shared__ char smem[];
    __nv_bfloat16* As_hi = (__nv_bfloat16*)smem;
    __nv_bfloat16* As_lo = (__nv_bfloat16*)(smem + 128 * GST * 2);
    __nv_bfloat16* Ws_hi = (__nv_bfloat16*)(smem + 2 * 128 * GST * 2);
    __nv_bfloat16* Ws_lo = (__nv_bfloat16*)(smem + 3 * 128 * GST * 2);

    int tid = threadIdx.x, wid = tid >> 5, lane = tid & 31;
    int wm = wid & 3, wn = wid >> 2;
    int rowBase = blockIdx.x * 128, colBase = blockIdx.y * 128;

    float acc[2][8][4];
#pragma unroll
    for (int i = 0; i < 2; i++)
#pragma unroll
        for (int j = 0; j < 8; j++)
#pragma unroll
            for (int q = 0; q < 4; q++) acc[i][j][q] = 0.f;

    int ar = (lane & 7) + ((lane >> 3) & 1) * 8;
    int ak = (lane >> 4) * 8;
    int bn = (lane & 7) + ((lane >> 4) & 1) * 8;
    int bk = ((lane >> 3) & 1) * 8;

    uint32_t sAh = cvta_s(As_hi), sAl = cvta_s(As_lo);
    uint32_t sWh = cvta_s(Ws_hi), sWl = cvta_s(Ws_lo);

    for (int kb = 0; kb < K; kb += 64) {
#pragma unroll
        for (int j = 0; j < 4; j++) {
            int i = tid + 256 * j;
            int r = i >> 3, c = i & 7;
            *(uint4*)&As_hi[r * GST + c * 8] = *(const uint4*)&Ahi[(size_t)(rowBase + r) * K + kb + c * 8];
            if (Alo)
                *(uint4*)&As_lo[r * GST + c * 8] = *(const uint4*)&Alo[(size_t)(rowBase + r) * K + kb + c * 8];
            *(uint4*)&Ws_hi[r * GST + c * 8] = *(const uint4*)&Whi[(size_t)(colBase + r) * K + kb + c * 8];
            if (Wlo)
                *(uint4*)&Ws_lo[r * GST + c * 8] = *(const uint4*)&Wlo[(size_t)(colBase + r) * K + kb + c * 8];
        }
        __syncthreads();

#pragma unroll
        for (int ks = 0; ks < 64; ks += 16) {
            uint32_t ah[2][4], al[2][4];
#pragma unroll
            for (int ma = 0; ma < 2; ma++) {
                uint32_t off = (uint32_t)((wm * 32 + ma * 16 + ar) * GST + ks + ak) * 2;
                ldsm4(ah[ma], sAh + off);
                if (Alo) ldsm4(al[ma], sAl + off);
            }
            uint32_t bh[4][4], bl[4][4];
#pragma unroll
            for (int nb = 0; nb < 4; nb++) {
                uint32_t off = (uint32_t)((wn * 64 + nb * 16 + bn) * GST + ks + bk) * 2;
                ldsm4(bh[nb], sWh + off);
                if (Wlo) ldsm4(bl[nb], sWl + off);
            }
#pragma unroll
            for (int ma = 0; ma < 2; ma++)
#pragma unroll
                for (int na = 0; na < 8; na++) {
                    float* c = acc[ma][na];
                    const uint32_t* pbh = &bh[na >> 1][(na & 1) * 2];
                    mma_bf16(c, ah[ma], pbh);
                    if (Wlo) {
                        const uint32_t* pbl = &bl[na >> 1][(na & 1) * 2];
                        mma_bf16(c, ah[ma], pbl);
                    }
                    if (Alo) mma_bf16(c, al[ma], pbh);
                }
        }
        __syncthreads();
    }

#pragma unroll
    for (int ma = 0; ma < 2; ma++)
#pragma unroll
        for (int na = 0; na < 8; na++) {
            int row = rowBase + wm * 32 + ma * 16 + (lane >> 2);
            int col = colBase + wn * 64 + na * 8 + (lane & 3) * 2;
            float b0 = 0.f, b1 = 0.f;
            if (bias) { b0 = bias[col]; b1 = bias[col + 1]; }
            float v0 = (acc[ma][na][0] + b0) * premul, v1 = (acc[ma][na][1] + b1) * premul;
            float v2 = (acc[ma][na][2] + b0) * premul, v3 = (acc[ma][na][3] + b1) * premul;
            if (act) {
                v0 = fmaxf(v0, 0.f); v1 = fmaxf(v1, 0.f);
                v2 = fmaxf(v2, 0.f); v3 = fmaxf(v3, 0.f);
            }
            if (Cf) {
                size_t i0 = (size_t)row * ncols + col, i1 = (size_t)(row + 8) * ncols + col;
                *(float2*)&Cf[i0] = make_float2(v0, v1);
                *(float2*)&Cf[i1] = make_float2(v2, v3);
            }
            if (Ch) {   // head-major f16: [col>>4][row][col&15]
                size_t j0 = ((size_t)(col >> 4) * N_NODES + row) * 16 + (col & 15);
                size_t j1 = ((size_t)(col >> 4) * N_NODES + row + 8) * 16 + (col & 15);
                *(uint32_t*)&Ch[j0] = pack_h16(v0, v1);
                *(uint32_t*)&Ch[j1] = pack_h16(v2, v3);
            }
            if (Chi) {
                size_t i0 = (size_t)row * ncols + col, i1 = (size_t)(row + 8) * ncols + col;
                if (Clo) {
                    uint32_t h0, l0, h1, l1;
                    split_pack(v0, v1, h0, l0);
                    split_pack(v2, v3, h1, l1);
                    *(uint32_t*)&Chi[i0] = h0; *(uint32_t*)&Clo[i0] = l0;
                    *(uint32_t*)&Chi[i1] = h1; *(uint32_t*)&Clo[i1] = l1;
                } else {
                    *(uint32_t*)&Chi[i0] = cvt2bf(v0, v1);
                    *(uint32_t*)&Chi[i1] = cvt2bf(v2, v3);
                }
            }
        }
}

// ---------------- GEMM + residual + LayerNorm fused ---------------------------
__global__ void __launch_bounds__(256)
k_gemm_ln(const __nv_bfloat16* __restrict__ Ahi, const __nv_bfloat16* __restrict__ Alo,
          const __nv_bfloat16* __restrict__ Whi, const __nv_bfloat16* __restrict__ Wlo,
          const float* __restrict__ bias, const float* __restrict__ R,
          const float* __restrict__ gamma, const float* __restrict__ beta,
          float* __restrict__ Yf, __nv_bfloat16* __restrict__ Yhi,
          __nv_bfloat16* __restrict__ Ylo, int K) {
    extern __shared__ char smem[];
    __nv_bfloat16* As_hi = (__nv_bfloat16*)smem;
    __nv_bfloat16* As_lo = (__nv_bfloat16*)(smem + 128 * GST * 2);
    __nv_bfloat16* Ws_hi = (__nv_bfloat16*)(smem + 2 * 128 * GST * 2);
    __nv_bfloat16* Ws_lo = (__nv_bfloat16*)(smem + 3 * 128 * GST * 2);
    __shared__ float red[128][2][2];

    int tid = threadIdx.x, wid = tid >> 5, lane = tid & 31;
    int wm = wid & 3, wn = wid >> 2;
    int rowBase = blockIdx.x * 128;

    float acc[2][8][4];
#pragma unroll
    for (int i = 0; i < 2; i++)
#pragma unroll
        for (int j = 0; j < 8; j++)
#pragma unroll
            for (int q = 0; q < 4; q++) acc[i][j][q] = 0.f;

    int ar = (lane & 7) + ((lane >> 3) & 1) * 8;
    int ak = (lane >> 4) * 8;
    int bn = (lane & 7) + ((lane >> 4) & 1) * 8;
    int bk = ((lane >> 3) & 1) * 8;

    uint32_t sAh = cvta_s(As_hi), sAl = cvta_s(As_lo);
    uint32_t sWh = cvta_s(Ws_hi), sWl = cvta_s(Ws_lo);

    for (int kb = 0; kb < K; kb += 64) {
#pragma unroll
        for (int j = 0; j < 4; j++) {
            int i = tid + 256 * j;
            int r = i >> 3, c = i & 7;
            *(uint4*)&As_hi[r * GST + c * 8] = *(const uint4*)&Ahi[(size_t)(rowBase + r) * K + kb + c * 8];
            if (Alo)
                *(uint4*)&As_lo[r * GST + c * 8] = *(const uint4*)&Alo[(size_t)(rowBase + r) * K + kb + c * 8];
            *(uint4*)&Ws_hi[r * GST + c * 8] = *(const uint4*)&Whi[(size_t)r * K + kb + c * 8];
            if (Wlo)
                *(uint4*)&Ws_lo[r * GST + c * 8] = *(const uint4*)&Wlo[(size_t)r * K + kb + c * 8];
        }
        __syncthreads();

#pragma unroll
        for (int ks = 0; ks < 64; ks += 16) {
            uint32_t ah[2][4], al[2][4];
#pragma unroll
            for (int ma = 0; ma < 2; ma++) {
                uint32_t off = (uint32_t)((wm * 32 + ma * 16 + ar) * GST + ks + ak) * 2;
                ldsm4(ah[ma], sAh + off);
                if (Alo) ldsm4(al[ma], sAl + off);
            }
            uint32_t bh[4][4], bl[4][4];
#pragma unroll
            for (int nb = 0; nb < 4; nb++) {
                uint32_t off = (uint32_t)((wn * 64 + nb * 16 + bn) * GST + ks + bk) * 2;
                ldsm4(bh[nb], sWh + off);
                if (Wlo) ldsm4(bl[nb], sWl + off);
            }
#pragma unroll
            for (int ma = 0; ma < 2; ma++)
#pragma unroll
                for (int na = 0; na < 8; na++) {
                    float* c = acc[ma][na];
                    const uint32_t* pbh = &bh[na >> 1][(na & 1) * 2];
                    mma_bf16(c, ah[ma], pbh);
                    if (Wlo) {
                        const uint32_t* pbl = &bl[na >> 1][(na & 1) * 2];
                        mma_bf16(c, ah[ma], pbl);
                    }
                    if (Alo) mma_bf16(c, al[ma], pbh);
                }
        }
        __syncthreads();
    }

#pragma unroll
    for (int ma = 0; ma < 2; ma++)
#pragma unroll
        for (int na = 0; na < 8; na++) {
            int row = rowBase + wm * 32 + ma * 16 + (lane >> 2);
            int col = wn * 64 + na * 8 + (lane & 3) * 2;
            float b0 = 0.f, b1 = 0.f;
            if (bias) { b0 = bias[col]; b1 = bias[col + 1]; }
            float2 r0 = *(const float2*)&R[(size_t)row * DMODEL + col];
            float2 r1 = *(const float2*)&R[(size_t)(row + 8) * DMODEL + col];
            acc[ma][na][0] += b0 + r0.x;
            acc[ma][na][1] += b1 + r0.y;
            acc[ma][na][2] += b0 + r1.x;
            acc[ma][na][3] += b1 + r1.y;
        }

#pragma unroll
    for (int ma = 0; ma < 2; ma++)
#pragma unroll
        for (int hr = 0; hr < 2; hr++) {
            float s = 0.f, s2 = 0.f;
#pragma unroll
            for (int na = 0; na < 8; na++) {
                float a = acc[ma][na][hr * 2], b = acc[ma][na][hr * 2 + 1];
                s += a + b;
                s2 += a * a + b * b;
            }
            s  += __shfl_xor_sync(0xffffffffu, s, 1);
            s  += __shfl_xor_sync(0xffffffffu, s, 2);
            s2 += __shfl_xor_sync(0xffffffffu, s2, 1);
            s2 += __shfl_xor_sync(0xffffffffu, s2, 2);
            int rl = wm * 32 + ma * 16 + (lane >> 2) + hr * 8;
            if ((lane & 3) == 0) { red[rl][wn][0] = s; red[rl][wn][1] = s2; }
        }
    __syncthreads();

#pragma unroll
    for (int ma = 0; ma < 2; ma++)
#pragma unroll
        for (int hr = 0; hr < 2; hr++) {
            int rl = wm * 32 + ma * 16 + (lane >> 2) + hr * 8;
            float S  = red[rl][0][0] + red[rl][1][0];
            float S2 = red[rl][0][1] + red[rl][1][1];
            float mu = S * (1.f / 128.f);
            float var = S2 * (1.f / 128.f) - mu * mu;
            float inv = rsqrtf(var + 1e-5f);
            int row = rowBase + rl;
#pragma unroll
            for (int na = 0; na < 8; na++) {
                int col = wn * 64 + na * 8 + (lane & 3) * 2;
                float g0 = gamma[col], g1 = gamma[col + 1];
                float t0 = beta[col], t1 = beta[col + 1];
                float v0 = fmaf((acc[ma][na][hr * 2] - mu) * inv, g0, t0);
                float v1 = fmaf((acc[ma][na][hr * 2 + 1] - mu) * inv, g1, t1);
                *(float2*)&Yf[(size_t)row * DMODEL + col] = make_float2(v0, v1);
                if (Yhi) {
                    uint32_t hh, ll;
                    split_pack(v0, v1, hh, ll);
                    *(uint32_t*)&Yhi[(size_t)row * DMODEL + col] = hh;
                    *(uint32_t*)&Ylo[(size_t)row * DMODEL + col] = ll;
                }
            }
        }
}

// ---------------- flash attention (f16, h2exp2) -------------------------------
__global__ void __launch_bounds__(256)
k_attn_tc(const __half* __restrict__ Qp, const __half* __restrict__ KVp,
          __nv_bfloat16* __restrict__ Ohi) {
    __shared__ __half sQ[128 * QST];
    __shared__ __half sK[64 * QST];
    __shared__ __half sV[64 * QST];

    int b = blockIdx.z, hd = blockIdx.y, qbase = blockIdx.x * 128;
    int tid = threadIdx.x, wm = tid >> 5, lane = tid & 31;

    const __half* Qh = Qp + ((size_t)hd * N_NODES + b * SEQ + qbase) * 16;
    const __half* Kh = KVp + ((size_t)hd * N_NODES + b * SEQ) * 16;
    const __half* Vh = KVp + ((size_t)(hd + HEADS) * N_NODES + b * SEQ) * 16;

    {
        int row = tid >> 1, half = tid & 1;
        *(uint4*)&sQ[row * QST + half * 8] = *(const uint4*)&Qh[row * 16 + half * 8];
    }
    int slot = tid & 127, trow = slot >> 1, thalf = slot & 1;
    const __half* tsrc = (tid < 128) ? Kh : Vh;
    __half* tdst = (tid < 128) ? sK : sV;

    uint4 rbuf = *(const uint4*)&tsrc[(size_t)trow * 16 + thalf * 8];
    *(uint4*)&tdst[trow * QST + thalf * 8] = rbuf;
    __syncthreads();

    int ar = (lane & 7) + ((lane >> 3) & 1) * 8;
    int ak = (lane >> 4) * 8;
    int bn = (lane & 7) + ((lane >> 4) & 1) * 8;
    int bk = ((lane >> 3) & 1) * 8;
    int vkey = (lane & 7) + ((lane >> 3) & 1) * 8;
    int vdh = ((lane >> 4) & 1) * 8;

    uint32_t sQa = cvta_s(sQ), sKa = cvta_s(sK), sVa = cvta_s(sV);
    uint32_t qf[4];
    ldsm4(qf, sQa + (uint32_t)((wm * 16 + ar) * QST + ak) * 2);

    float mst[2] = {-CUDART_INF_F, -CUDART_INF_F};
    float lst[2] = {0.f, 0.f};
    float of[2][4] = {{0.f, 0.f, 0.f, 0.f}, {0.f, 0.f, 0.f, 0.f}};

    for (int kt = 0; kt < SEQ / 64; kt++) {
        if (kt + 1 < SEQ / 64)
            rbuf = *(const uint4*)&tsrc[(size_t)((kt + 1) * 64 + trow) * 16 + thalf * 8];

        float sf[8][4];
#pragma unroll
        for (int j = 0; j < 8; j++)
#pragma unroll
            for (int q = 0; q < 4; q++) sf[j][q] = 0.f;
#pragma unroll
        for (int nb = 0; nb < 4; nb++) {
            uint32_t kf[4];
            ldsm4(kf, sKa + (uint32_t)((nb * 16 + bn) * QST + bk) * 2);
            mma_f16(sf[2 * nb], qf, &kf[0]);
            mma_f16(sf[2 * nb + 1], qf, &kf[2]);
        }

        __half2 ep[8][2];
#pragma unroll
        for (int hr = 0; hr < 2; hr++) {
            float mx = sf[0][hr * 2];
#pragma unroll
            for (int j = 0; j < 8; j++) {
                mx = fmaxf(mx, sf[j][hr * 2]);
                mx = fmaxf(mx, sf[j][hr * 2 + 1]);
            }
            mx = fmaxf(mx, __shfl_xor_sync(0xffffffffu, mx, 1));
            mx = fmaxf(mx, __shfl_xor_sync(0xffffffffu, mx, 2));
            float mnew = fmaxf(mst[hr], mx);
            float corr = exp2f(mst[hr] - mnew);
            __half2 hsum = __floats2half2_rn(0.f, 0.f);
#pragma unroll
            for (int j = 0; j < 8; j++) {
                float d0 = sf[j][hr * 2] - mnew;
                float d1 = sf[j][hr * 2 + 1] - mnew;
                __half2 p2 = h2exp2(__floats2half2_rn(d0, d1));
                ep[j][hr] = p2;
                hsum = __hadd2(hsum, p2);
            }
            float2 fs = __half22float2(hsum);
            float rsum = fs.x + fs.y;
            rsum += __shfl_xor_sync(0xffffffffu, rsum, 1);
            rsum += __shfl_xor_sync(0xffffffffu, rsum, 2);
            lst[hr] = lst[hr] * corr + rsum;
            mst[hr] = mnew;
#pragma unroll
            for (int nh = 0; nh < 2; nh++) {
                of[nh][hr * 2] *= corr;
                of[nh][hr * 2 + 1] *= corr;
            }
        }

#pragma unroll
        for (int kf = 0; kf < 4; kf++) {
            uint32_t vf[4];
            ldsm4t(vf, sVa + (uint32_t)((kf * 16 + vkey) * QST + vdh) * 2);
            uint32_t pa[4];
            pa[0] = *(uint32_t*)&ep[2 * kf][0];
            pa[1] = *(uint32_t*)&ep[2 * kf][1];
            pa[2] = *(uint32_t*)&ep[2 * kf + 1][0];
            pa[3] = *(uint32_t*)&ep[2 * kf + 1][1];
            mma_f16(of[0], pa, &vf[0]);
            mma_f16(of[1], pa, &vf[2]);
        }

        __syncthreads();
        if (kt + 1 < SEQ / 64)
            *(uint4*)&tdst[trow * QST + thalf * 8] = rbuf;
        __syncthreads();
    }

#pragma unroll
    for (int hr = 0; hr < 2; hr++) {
        float inv = 1.f / lst[hr];
        int grow = b * SEQ + qbase + wm * 16 + (lane >> 2) + hr * 8;
#pragma unroll
        for (int nh = 0; nh < 2; nh++) {
            float v0 = of[nh][hr * 2] * inv;
            float v1 = of[nh][hr * 2 + 1] * inv;
            int col = hd * 16 + nh * 8 + (lane & 3) * 2;
            *(uint32_t*)&Ohi[(size_t)grow * DMODEL + col] = cvt2bf(v0, v1);
        }
    }
}

// ---------------- host orchestration -----------------------------------------
extern "C" void kernel_launch(void* const* d_in, const int* in_sizes, int n_in,
                              void* d_out, int out_size) {
    const float* enc   = (const float*)d_in[0];
    const float* xraw  = (const float*)d_in[2];
    const int*   eidx  = (const int*)  d_in[3];
    const float* Wg1   = (const float*)d_in[4];
    const float* bg1   = (const float*)d_in[5];
    const float* Wg2   = (const float*)d_in[6];
    const float* bg2   = (const float*)d_in[7];
    const float* Wq    = (const float*)d_in[8];
    const float* Wk    = (const float*)d_in[9];
    const float* Wv    = (const float*)d_in[10];
    const float* Wo    = (const float*)d_in[11];
    const float* Wff1  = (const float*)d_in[12];
    const float* bff1  = (const float*)d_in[13];
    const float* Wff2  = (const float*)d_in[14];
    const float* bff2  = (const float*)d_in[15];
    const float* ln1g  = (const float*)d_in[16];
    const float* ln1b  = (const float*)d_in[17];
    const float* ln2g  = (const float*)d_in[18];
    const float* ln2b  = (const float*)d_in[19];
    float* outp = (float*)d_out;

    float *dinv, *y;
    int *counts, *rowoff, *cursor, *csr, *bsum, *boff;
    __nv_bfloat16 *h, *whi, *wlo, *xrhi, *x1hi, *gxhi;
    __nv_bfloat16 *yhi, *ylo, *Abhi, *F1hi, *F1lo;
    __half *Qp, *KVp;
    cudaGetSymbolAddress((void**)&dinv,   g_dinv);
    cudaGetSymbolAddress((void**)&counts, g_counts);
    cudaGetSymbolAddress((void**)&rowoff, g_rowoff);
    cudaGetSymbolAddress((void**)&cursor, g_cursor);
    cudaGetSymbolAddress((void**)&csr,    g_csr);
    cudaGetSymbolAddress((void**)&bsum,   g_bsum);
    cudaGetSymbolAddress((void**)&boff,   g_boff);
    cudaGetSymbolAddress((void**)&h,   g_h);
    cudaGetSymbolAddress((void**)&y,   g_y);
    cudaGetSymbolAddress((void**)&whi, g_whi);
    cudaGetSymbolAddress((void**)&wlo, g_wlo);
    cudaGetSymbolAddress((void**)&xrhi, g_xrhi);
    cudaGetSymbolAddress((void**)&x1hi, g_x1hi);
    cudaGetSymbolAddress((void**)&gxhi, g_gxhi);
    cudaGetSymbolAddress((void**)&yhi, g_yhi);
    cudaGetSymbolAddress((void**)&ylo, g_ylo);
    cudaGetSymbolAddress((void**)&Qp,  g_Qp);
    cudaGetSymbolAddress((void**)&KVp, g_KVp);
    cudaGetSymbolAddress((void**)&Abhi, g_Abhi);
    cudaGetSymbolAddress((void**)&F1hi, g_F1hi);
    cudaGetSymbolAddress((void**)&F1lo, g_F1lo);

    cudaFuncSetAttribute(k_gemm_tc, cudaFuncAttributeMaxDynamicSharedMemorySize, GT_SMEM);
    cudaFuncSetAttribute(k_gemm_ln, cudaFuncAttributeMaxDynamicSharedMemorySize, GT_SMEM);

    const int ROWS = N_NODES;
    const int OFF_G1 = 0, OFF_G2 = 16384;
    const int LSTR = 4 * 16384 + 2 * 65536;
    auto offQ  = [&](int l) { return 32768 + l * LSTR; };
    auto offK  = [&](int l) { return offQ(l) + 16384; };
    auto offO  = [&](int l) { return offQ(l) + 49152; };
    auto offF1 = [&](int l) { return offQ(l) + 65536; };
    auto offF2 = [&](int l) { return offQ(l) + 131072; };

    PrepArgs pa;
    int blk = 0, si = 0;
    auto addseg = [&](const float* src, int K, int N, int off) {
        pa.s[si].src = src; pa.s[si].K = K; pa.s[si].N = N;
        pa.s[si].off = off; pa.s[si].blk0 = blk;
        si++; blk += K * N / 256;
    };
    addseg(Wg1, 128, 128, OFF_G1);
    addseg(Wg2, 128, 128, OFF_G2);
    for (int l = 0; l < 2; l++) {
        addseg(Wq + l * 16384, 128, 128, offQ(l));
        addseg(Wk + l * 16384, 128, 128, offK(l));
        addseg(Wv + l * 16384, 128, 128, offK(l) + 16384);
        addseg(Wo + l * 16384, 128, 128, offO(l));
        addseg(Wff1 + l * 65536, 128, 512, offF1(l));
        addseg(Wff2 + l * 65536, 512, 128, offF2(l));
    }
    pa.nseg = si;
    k_prep_all<<<blk, 256>>>(pa, whi, wlo);

    auto GEMM = [&](const __nv_bfloat16* Ah, const __nv_bfloat16* Al, int woff,
                    const __nv_bfloat16* Wl, const float* bias, float* Cf, __half* Ch,
                    __nv_bfloat16* Chi, __nv_bfloat16* Clo, int K, int ncols,
                    int act, float premul) {
        dim3 g(ROWS / 128, ncols / 128);
        k_gemm_tc<<<g, 256, GT_SMEM>>>(Ah, Al, whi + woff, Wl, bias,
                                       Cf, Ch, Chi, Clo, K, ncols, act, premul);
    };

    // ---- graph preprocessing + conversions ----
    cudaMemsetAsync(counts, 0, N_NODES * sizeof(int));
    k_count<<<N_EDGES / 256, 256>>>(eidx, counts);
    k_scan_bsum<<<128, 256>>>(counts, bsum);
    k_scan_boff<<<1, 128>>>(bsum, boff);
    k_scan_fin<<<128, 256>>>(counts, boff, rowoff, cursor, dinv);
    k_fill<<<NTOT / 256, 256>>>(eidx, cursor, csr);
    k_cvt<<<N_NODES * DMODEL / 1024, 256>>>(xraw, xrhi, nullptr, nullptr);
    k_cvt<<<N_NODES * DMODEL / 1024, 256>>>(enc, yhi, ylo, y);

    // ---- GCN stack (pure bf16 branch: feeds K/V only) ----
    GEMM(xrhi, nullptr, OFF_G1, nullptr, nullptr, nullptr, nullptr, h, nullptr, 128, 128, 0, 1.f);
    k_aggregate<<<N_NODES / 8, 256>>>(h, dinv, rowoff, csr, bg1, x1hi);
    GEMM(x1hi, nullptr, OFF_G2, nullptr, nullptr, nullptr, nullptr, h, nullptr, 128, 128, 0, 1.f);
    k_aggregate<<<N_NODES / 8, 256>>>(h, dinv, rowoff, csr, bg2, gxhi);

    // ---- transformer layers ----
    for (int l = 0; l < 2; l++) {
        GEMM(yhi, nullptr, offQ(l), nullptr, nullptr, nullptr, Qp, nullptr, nullptr, 128, 128, 0, SC2);
        GEMM(gxhi, nullptr, offK(l), nullptr, nullptr, nullptr, KVp, nullptr, nullptr, 128, 256, 0, 1.f);
        k_attn_tc<<<dim3(SEQ / 128, HEADS, BATCH), 256>>>(Qp, KVp, Abhi);
        k_gemm_ln<<<ROWS / 128, 256, GT_SMEM>>>(Abhi, nullptr, whi + offO(l), nullptr,
                                                nullptr, y, ln1g + l * 128, ln1b + l * 128,
                                                y, yhi, ylo, 128);
        GEMM(yhi, ylo, offF1(l), wlo + offF1(l), bff1 + l * DFF, nullptr, nullptr,
             F1hi, F1lo, 128, DFF, 1, 1.f);
        if (l == 1)
            k_gemm_ln<<<ROWS / 128, 256, GT_SMEM>>>(F1hi, F1lo, whi + offF2(l), wlo + offF2(l),
                                                    bff2 + l * DMODEL, y, ln2g + l * 128,
                                                    ln2b + l * 128, outp, nullptr, nullptr, 512);
        else
            k_gemm_ln<<<ROWS / 128, 256, GT_SMEM>>>(F1hi, F1lo, whi + offF2(l), wlo + offF2(l),
                                                    bff2 + l * DMODEL, y, ln2g + l * 128,
                                                    ln2b + l * 128, y, yhi, ylo, 512);
    }
}

// round 15
// speedup vs baseline: 4.3068x; 1.0212x over previous
#include <cuda_runtime.h>
#include <cuda_bf16.h>
#include <cuda_fp16.h>
#include <math_constants.h>
#include <cstdint>

#define N_NODES 32768
#define N_EDGES 524288
#define DMODEL  128
#define BATCH   32
#define SEQ     1024
#define HEADS   8
#define DFF     512
#define NTOT    (N_EDGES + N_NODES)
#define WELEMS  425984
#define GST     72
#define QST     24
#define SC2     0.360673760222241f   /* 0.25 * log2(e) */

// ---------------- mma helpers ------------------------------------------------
__device__ __forceinline__ uint32_t cvta_s(const void* p) {
    return (uint32_t)__cvta_generic_to_shared(p);
}
__device__ __forceinline__ void ldsm4(uint32_t* r, uint32_t a) {
    asm volatile("ldmatrix.sync.aligned.m8n8.x4.shared.b16 {%0,%1,%2,%3}, [%4];"
                 : "=r"(r[0]), "=r"(r[1]), "=r"(r[2]), "=r"(r[3]) : "r"(a));
}
__device__ __forceinline__ void ldsm4t(uint32_t* r, uint32_t a) {
    asm volatile("ldmatrix.sync.aligned.m8n8.x4.trans.shared.b16 {%0,%1,%2,%3}, [%4];"
                 : "=r"(r[0]), "=r"(r[1]), "=r"(r[2]), "=r"(r[3]) : "r"(a));
}
__device__ __forceinline__ void mma_bf16(float* c, const uint32_t* a, const uint32_t* b) {
    asm volatile("mma.sync.aligned.m16n8k16.row.col.f32.bf16.bf16.f32 "
                 "{%0,%1,%2,%3}, {%4,%5,%6,%7}, {%8,%9}, {%0,%1,%2,%3};"
                 : "+f"(c[0]), "+f"(c[1]), "+f"(c[2]), "+f"(c[3])
                 : "r"(a[0]), "r"(a[1]), "r"(a[2]), "r"(a[3]), "r"(b[0]), "r"(b[1]));
}
__device__ __forceinline__ void mma_f16(float* c, const uint32_t* a, const uint32_t* b) {
    asm volatile("mma.sync.aligned.m16n8k16.row.col.f32.f16.f16.f32 "
                 "{%0,%1,%2,%3}, {%4,%5,%6,%7}, {%8,%9}, {%0,%1,%2,%3};"
                 : "+f"(c[0]), "+f"(c[1]), "+f"(c[2]), "+f"(c[3])
                 : "r"(a[0]), "r"(a[1]), "r"(a[2]), "r"(a[3]), "r"(b[0]), "r"(b[1]));
}
__device__ __forceinline__ uint32_t cvt2bf(float lo, float hi) {
    uint32_t r;
    asm("cvt.rn.bf16x2.f32 %0, %1, %2;" : "=r"(r) : "f"(hi), "f"(lo));
    return r;
}
__device__ __forceinline__ uint32_t pack_h16(float lo, float hi) {
    uint32_t r;
    asm("cvt.rn.f16x2.f32 %0, %1, %2;" : "=r"(r) : "f"(hi), "f"(lo));
    return r;
}
__device__ __forceinline__ void split_pack(float a, float b, uint32_t& hi, uint32_t& lo) {
    __nv_bfloat16 ha = __float2bfloat16(a), hb = __float2bfloat16(b);
    float ra = a - __bfloat162float(ha), rb = b - __bfloat162float(hb);
    __nv_bfloat16 la = __float2bfloat16(ra), lb = __float2bfloat16(rb);
    hi = ((uint32_t)__bfloat16_as_ushort(hb) << 16) | __bfloat16_as_ushort(ha);
    lo = ((uint32_t)__bfloat16_as_ushort(lb) << 16) | __bfloat16_as_ushort(la);
}

// ---------------- scratch ----------------------------------------------------
static __device__ float g_dinv[N_NODES];
static __device__ int   g_counts[N_NODES];
static __device__ int   g_rowoff[N_NODES + 1];
static __device__ int   g_cursor[N_NODES];
static __device__ int   g_bsum[128];
static __device__ int   g_boff[128];
static __device__ int   g_csr[NTOT];
static __device__ __nv_bfloat16 g_h[N_NODES * DMODEL];
static __device__ float g_y [N_NODES * DMODEL];
static __device__ __nv_bfloat16 g_whi[WELEMS];
static __device__ __nv_bfloat16 g_wlo[WELEMS];
static __device__ __nv_bfloat16 g_xrhi[N_NODES * DMODEL];
static __device__ __nv_bfloat16 g_x1hi[N_NODES * DMODEL];
static __device__ __nv_bfloat16 g_gxhi[N_NODES * DMODEL];
static __device__ __nv_bfloat16 g_yhi[N_NODES * DMODEL];
static __device__ __nv_bfloat16 g_ylo[N_NODES * DMODEL];
static __device__ __half g_Qp[HEADS * N_NODES * 16];
static __device__ __half g_KVp0[2 * HEADS * N_NODES * 16];
static __device__ __half g_KVp1[2 * HEADS * N_NODES * 16];
static __device__ __nv_bfloat16 g_Abhi[N_NODES * DMODEL];
static __device__ __nv_bfloat16 g_F1hi[N_NODES * DFF];
static __device__ __nv_bfloat16 g_F1lo[N_NODES * DFF];

// ---------------- graph preprocessing ---------------------------------------
__global__ void k_count(const int* __restrict__ eidx, int* __restrict__ counts) {
    int e = blockIdx.x * blockDim.x + threadIdx.x;
    atomicAdd(&counts[eidx[N_EDGES + e]], 1);
}
__global__ void k_scan_bsum(const int* __restrict__ counts, int* __restrict__ bsum) {
    __shared__ int ws[8];
    int t = threadIdx.x;
    int c = counts[blockIdx.x * 256 + t] + 1;
#pragma unroll
    for (int o = 16; o; o >>= 1) c += __shfl_xor_sync(0xffffffffu, c, o);
    if ((t & 31) == 0) ws[t >> 5] = c;
    __syncthreads();
    if (t == 0) {
        int s = 0;
#pragma unroll
        for (int w = 0; w < 8; w++) s += ws[w];
        bsum[blockIdx.x] = s;
    }
}
__global__ void k_scan_boff(const int* __restrict__ bsum, int* __restrict__ boff) {
    __shared__ int sm[128];
    int t = threadIdx.x;
    int v = bsum[t];
    sm[t] = v;
    __syncthreads();
    for (int off = 1; off < 128; off <<= 1) {
        int u = (t >= off) ? sm[t - off] : 0;
        __syncthreads();
        sm[t] += u;
        __syncthreads();
    }
    boff[t] = sm[t] - v;
}
__global__ void k_scan_fin(const int* __restrict__ counts, const int* __restrict__ boff,
                           int* __restrict__ rowoff, int* __restrict__ cursor,
                           float* __restrict__ dinv) {
    __shared__ int ws[8];
    int t = threadIdx.x, lane = t & 31, w = t >> 5;
    int i = blockIdx.x * 256 + t;
    int c = counts[i] + 1;
    int x = c;
#pragma unroll
    for (int o = 1; o < 32; o <<= 1) {
        int u = __shfl_up_sync(0xffffffffu, x, o);
        if (lane >= o) x += u;
    }
    if (lane == 31) ws[w] = x;
    __syncthreads();
    int wo = 0;
#pragma unroll
    for (int k = 0; k < 8; k++) if (k < w) wo += ws[k];
    int excl = boff[blockIdx.x] + wo + x - c;
    rowoff[i] = excl;
    cursor[i] = excl;
    dinv[i] = rsqrtf((float)c);
    if (i == N_NODES - 1) rowoff[N_NODES] = excl + c;
}
__global__ void k_fill(const int* __restrict__ eidx, int* __restrict__ cursor,
                       int* __restrict__ csr) {
    int e = blockIdx.x * blockDim.x + threadIdx.x;
    int s, d;
    if (e < N_EDGES) { s = eidx[e]; d = eidx[N_EDGES + e]; }
    else             { s = d = e - N_EDGES; }
    csr[atomicAdd(&cursor[d], 1)] = s;
}

__global__ void k_aggregate(const __nv_bfloat16* __restrict__ h, const float* __restrict__ dinv,
                            const int* __restrict__ rowoff, const int* __restrict__ csr,
                            const float* __restrict__ bias,
                            __nv_bfloat16* __restrict__ ohi) {
    int wid = threadIdx.x >> 5, lane = threadIdx.x & 31;
    int i = blockIdx.x * 8 + wid;
    const uint2* h2 = (const uint2*)h;
    float acc0 = 0.f, acc1 = 0.f, acc2 = 0.f, acc3 = 0.f;
    int e = rowoff[i], end = rowoff[i + 1];
    for (; e < end; e++) {
        int s0 = csr[e];
        float w0 = dinv[s0];
        uint2 u = h2[s0 * 32 + lane];
        __nv_bfloat162 p0 = *(__nv_bfloat162*)&u.x;
        __nv_bfloat162 p1 = *(__nv_bfloat162*)&u.y;
        acc0 = fmaf(w0, __bfloat162float(p0.x), acc0);
        acc1 = fmaf(w0, __bfloat162float(p0.y), acc1);
        acc2 = fmaf(w0, __bfloat162float(p1.x), acc2);
        acc3 = fmaf(w0, __bfloat162float(p1.y), acc3);
    }
    float di = dinv[i];
    float4 b4 = ((const float4*)bias)[lane];
    float o0 = fmaxf(fmaf(di, acc0, b4.x), 0.f);
    float o1 = fmaxf(fmaf(di, acc1, b4.y), 0.f);
    float o2 = fmaxf(fmaf(di, acc2, b4.z), 0.f);
    float o3 = fmaxf(fmaf(di, acc3, b4.w), 0.f);
    uint2 hh;
    hh.x = cvt2bf(o0, o1);
    hh.y = cvt2bf(o2, o3);
    *(uint2*)&ohi[(size_t)i * DMODEL + lane * 4] = hh;
}

__global__ void k_cvt(const float* __restrict__ src, __nv_bfloat16* __restrict__ hi,
                      __nv_bfloat16* __restrict__ lo, float* __restrict__ fdst) {
    int i = blockIdx.x * blockDim.x + threadIdx.x;
    float4 v = ((const float4*)src)[i];
    if (lo) {
        uint2 hh, ll;
        split_pack(v.x, v.y, hh.x, ll.x);
        split_pack(v.z, v.w, hh.y, ll.y);
        ((uint2*)hi)[i] = hh;
        ((uint2*)lo)[i] = ll;
    } else {
        uint2 hh;
        hh.x = cvt2bf(v.x, v.y);
        hh.y = cvt2bf(v.z, v.w);
        ((uint2*)hi)[i] = hh;
    }
    if (fdst) ((float4*)fdst)[i] = v;
}

// ---------------- mega weight prep -------------------------------------------
struct Seg { const float* src; int K; int N; int off; int blk0; };
struct PrepArgs { Seg s[14]; int nseg; };

__global__ void k_prep_all(PrepArgs pa, __nv_bfloat16* __restrict__ hi,
                           __nv_bfloat16* __restrict__ lo) {
    int b = blockIdx.x;
    int si = 0;
    while (si + 1 < pa.nseg && pa.s[si + 1].blk0 <= b) si++;
    Seg sg = pa.s[si];
    int idx = (b - sg.blk0) * 256 + threadIdx.x;
    int k = idx / sg.N, n = idx % sg.N;
    float v = sg.src[idx];
    __nv_bfloat16 h = __float2bfloat16(v);
    __nv_bfloat16 l = __float2bfloat16(v - __bfloat162float(h));
    hi[sg.off + n * sg.K + k] = h;
    lo[sg.off + n * sg.K + k] = l;
}

// ---------------- tensor-core GEMM -------------------------------------------
#define GT_SMEM (4 * 128 * GST * 2)
__global__ void __launch_bounds__(256)
k_gemm_tc(const __nv_bfloat16* __restrict__ Ahi, const __nv_bfloat16* __restrict__ Alo,
          const __nv_bfloat16* __restrict__ Whi, const __nv_bfloat16* __restrict__ Wlo,
          const float* __restrict__ bias, float* __restrict__ Cf,
          __half* __restrict__ Ch, __nv_bfloat16* __restrict__ Chi,
          __nv_bfloat16* __restrict__ Clo, int K, int ncols, int act, float premul) {
    extern __shared__ char smem[];
    __nv_bfloat16* As_hi = (__nv_bfloat16*)smem;
    __nv_bfloat16* As_lo = (__nv_bfloat16*)(smem + 128 * GST * 2);
    __nv_bfloat16* Ws_hi = (__nv_bfloat16*)(smem + 2 * 128 * GST * 2);
    __nv_bfloat16* Ws_lo = (__nv_bfloat16*)(smem + 3 * 128 * GST * 2);

    int tid = threadIdx.x, wid = tid >> 5, lane = tid & 31;
    int wm = wid & 3, wn = wid >> 2;
    int rowBase = blockIdx.x * 128, colBase = blockIdx.y * 128;

    float acc[2][8][4];
#pragma unroll
    for (int i = 0; i < 2; i++)
#pragma unroll
        for (int j = 0; j < 8; j++)
#pragma unroll
            for (int q = 0; q < 4; q++) acc[i][j][q] = 0.f;

    int ar = (lane & 7) + ((lane >> 3) & 1) * 8;
    int ak = (lane >> 4) * 8;
    int bn = (lane & 7) + ((lane >> 4) & 1) * 8;
    int bk = ((lane >> 3) & 1) * 8;

    uint32_t sAh = cvta_s(As_hi), sAl = cvta_s(As_lo);
    uint32_t sWh = cvta_s(Ws_hi), sWl = cvta_s(Ws_lo);

    for (int kb = 0; kb < K; kb += 64) {
#pragma unroll
        for (int j = 0; j < 4; j++) {
            int i = tid + 256 * j;
            int r = i >> 3, c = i & 7;
            *(uint4*)&As_hi[r * GST + c * 8] = *(const uint4*)&Ahi[(size_t)(rowBase + r) * K + kb + c * 8];
            if (Alo)
                *(uint4*)&As_lo[r * GST + c * 8] = *(const uint4*)&Alo[(size_t)(rowBase + r) * K + kb + c * 8];
            *(uint4*)&Ws_hi[r * GST + c * 8] = *(const uint4*)&Whi[(size_t)(colBase + r) * K + kb + c * 8];
            if (Wlo)
                *(uint4*)&Ws_lo[r * GST + c * 8] = *(const uint4*)&Wlo[(size_t)(colBase + r) * K + kb + c * 8];
        }
        __syncthreads();

#pragma unroll
        for (int ks = 0; ks < 64; ks += 16) {
            uint32_t ah[2][4], al[2][4];
#pragma unroll
            for (int ma = 0; ma < 2; ma++) {
                uint32_t off = (uint32_t)((wm * 32 + ma * 16 + ar) * GST + ks + ak) * 2;
                ldsm4(ah[ma], sAh + off);
                if (Alo) ldsm4(al[ma], sAl + off);
            }
            uint32_t bh[4][4], bl[4][4];
#pragma unroll
            for (int nb = 0; nb < 4; nb++) {
                uint32_t off = (uint32_t)((wn * 64 + nb * 16 + bn) * GST + ks + bk) * 2;
                ldsm4(bh[nb], sWh + off);
                if (Wlo) ldsm4(bl[nb], sWl + off);
            }
#pragma unroll
            for (int ma = 0; ma < 2; ma++)
#pragma unroll
                for (int na = 0; na < 8; na++) {
                    float* c = acc[ma][na];
                    const uint32_t* pbh = &bh[na >> 1][(na & 1) * 2];
                    mma_bf16(c, ah[ma], pbh);
                    if (Wlo) {
                        const uint32_t* pbl = &bl[na >> 1][(na & 1) * 2];
                        mma_bf16(c, ah[ma], pbl);
                    }
                    if (Alo) mma_bf16(c, al[ma], pbh);
                }
        }
        __syncthreads();
    }

#pragma unroll
    for (int ma = 0; ma < 2; ma++)
#pragma unroll
        for (int na = 0; na < 8; na++) {
            int row = rowBase + wm * 32 + ma * 16 + (lane >> 2);
            int col = colBase + wn * 64 + na * 8 + (lane & 3) * 2;
            float b0 = 0.f, b1 = 0.f;
            if (bias) { b0 = bias[col]; b1 = bias[col + 1]; }
            float v0 = (acc[ma][na][0] + b0) * premul, v1 = (acc[ma][na][1] + b1) * premul;
            float v2 = (acc[ma][na][2] + b0) * premul, v3 = (acc[ma][na][3] + b1) * premul;
            if (act) {
                v0 = fmaxf(v0, 0.f); v1 = fmaxf(v1, 0.f);
                v2 = fmaxf(v2, 0.f); v3 = fmaxf(v3, 0.f);
            }
            if (Cf) {
                size_t i0 = (size_t)row * ncols + col, i1 = (size_t)(row + 8) * ncols + col;
                *(float2*)&Cf[i0] = make_float2(v0, v1);
                *(float2*)&Cf[i1] = make_float2(v2, v3);
            }
            if (Ch) {
                size_t j0 = ((size_t)(col >> 4) * N_NODES + row) * 16 + (col & 15);
                size_t j1 = ((size_t)(col >> 4) * N_NODES + row + 8) * 16 + (col & 15);
                *(uint32_t*)&Ch[j0] = pack_h16(v0, v1);
                *(uint32_t*)&Ch[j1] = pack_h16(v2, v3);
            }
            if (Chi) {
                size_t i0 = (size_t)row * ncols + col, i1 = (size_t)(row + 8) * ncols + col;
                if (Clo) {
                    uint32_t h0, l0, h1, l1;
                    split_pack(v0, v1, h0, l0);
                    split_pack(v2, v3, h1, l1);
                    *(uint32_t*)&Chi[i0] = h0; *(uint32_t*)&Clo[i0] = l0;
                    *(uint32_t*)&Chi[i1] = h1; *(uint32_t*)&Clo[i1] = l1;
                } else {
                    *(uint32_t*)&Chi[i0] = cvt2bf(v0, v1);
                    *(uint32_t*)&Chi[i1] = cvt2bf(v2, v3);
                }
            }
        }
}

// ---------------- GEMM + residual + LayerNorm fused ---------------------------
__global__ void __launch_bounds__(256)
k_gemm_ln(const __nv_bfloat16* __restrict__ Ahi, const __nv_bfloat16* __restrict__ Alo,
          const __nv_bfloat16* __restrict__ Whi, const __nv_bfloat16* __restrict__ Wlo,
          const float* __restrict__ bias, const float* __restrict__ R,
          const float* __restrict__ gamma, const float* __restrict__ beta,
          float* __restrict__ Yf, __nv_bfloat16* __restrict__ Yhi,
          __nv_bfloat16* __restrict__ Ylo, int K) {
    extern __shared__ char smem[];
    __nv_bfloat16* As_hi = (__nv_bfloat16*)smem;
    __nv_bfloat16* As_lo = (__nv_bfloat16*)(smem + 128 * GST * 2);
    __nv_bfloat16* Ws_hi = (__nv_bfloat16*)(smem + 2 * 128 * GST * 2);
    __nv_bfloat16* Ws_lo = (__nv_bfloat16*)(smem + 3 * 128 * GST * 2);
    __shared__ float red[128][2][2];

    int tid = threadIdx.x, wid = tid >> 5, lane = tid & 31;
    int wm = wid & 3, wn = wid >> 2;
    int rowBase = blockIdx.x * 128;

    float acc[2][8][4];
#pragma unroll
    for (int i = 0; i < 2; i++)
#pragma unroll
        for (int j = 0; j < 8; j++)
#pragma unroll
            for (int q = 0; q < 4; q++) acc[i][j][q] = 0.f;

    int ar = (lane & 7) + ((lane >> 3) & 1) * 8;
    int ak = (lane >> 4) * 8;
    int bn = (lane & 7) + ((lane >> 4) & 1) * 8;
    int bk = ((lane >> 3) & 1) * 8;

    uint32_t sAh = cvta_s(As_hi), sAl = cvta_s(As_lo);
    uint32_t sWh = cvta_s(Ws_hi), sWl = cvta_s(Ws_lo);

    for (int kb = 0; kb < K; kb += 64) {
#pragma unroll
        for (int j = 0; j < 4; j++) {
            int i = tid + 256 * j;
            int r = i >> 3, c = i & 7;
            *(uint4*)&As_hi[r * GST + c * 8] = *(const uint4*)&Ahi[(size_t)(rowBase + r) * K + kb + c * 8];
            if (Alo)
                *(uint4*)&As_lo[r * GST + c * 8] = *(const uint4*)&Alo[(size_t)(rowBase + r) * K + kb + c * 8];
            *(uint4*)&Ws_hi[r * GST + c * 8] = *(const uint4*)&Whi[(size_t)r * K + kb + c * 8];
            if (Wlo)
                *(uint4*)&Ws_lo[r * GST + c * 8] = *(const uint4*)&Wlo[(size_t)r * K + kb + c * 8];
        }
        __syncthreads();

#pragma unroll
        for (int ks = 0; ks < 64; ks += 16) {
            uint32_t ah[2][4], al[2][4];
#pragma unroll
            for (int ma = 0; ma < 2; ma++) {
                uint32_t off = (uint32_t)((wm * 32 + ma * 16 + ar) * GST + ks + ak) * 2;
                ldsm4(ah[ma], sAh + off);
                if (Alo) ldsm4(al[ma], sAl + off);
            }
            uint32_t bh[4][4], bl[4][4];
#pragma unroll
            for (int nb = 0; nb < 4; nb++) {
                uint32_t off = (uint32_t)((wn * 64 + nb * 16 + bn) * GST + ks + bk) * 2;
                ldsm4(bh[nb], sWh + off);
                if (Wlo) ldsm4(bl[nb], sWl + off);
            }
#pragma unroll
            for (int ma = 0; ma < 2; ma++)
#pragma unroll
                for (int na = 0; na < 8; na++) {
                    float* c = acc[ma][na];
                    const uint32_t* pbh = &bh[na >> 1][(na & 1) * 2];
                    mma_bf16(c, ah[ma], pbh);
                    if (Wlo) {
                        const uint32_t* pbl = &bl[na >> 1][(na & 1) * 2];
                        mma_bf16(c, ah[ma], pbl);
                    }
                    if (Alo) mma_bf16(c, al[ma], pbh);
                }
        }
        __syncthreads();
    }

#pragma unroll
    for (int ma = 0; ma < 2; ma++)
#pragma unroll
        for (int na = 0; na < 8; na++) {
            int row = rowBase + wm * 32 + ma * 16 + (lane >> 2);
            int col = wn * 64 + na * 8 + (lane & 3) * 2;
            float b0 = 0.f, b1 = 0.f;
            if (bias) { b0 = bias[col]; b1 = bias[col + 1]; }
            float2 r0 = *(const float2*)&R[(size_t)row * DMODEL + col];
            float2 r1 = *(const float2*)&R[(size_t)(row + 8) * DMODEL + col];
            acc[ma][na][0] += b0 + r0.x;
            acc[ma][na][1] += b1 + r0.y;
            acc[ma][na][2] += b0 + r1.x;
            acc[ma][na][3] += b1 + r1.y;
        }

#pragma unroll
    for (int ma = 0; ma < 2; ma++)
#pragma unroll
        for (int hr = 0; hr < 2; hr++) {
            float s = 0.f, s2 = 0.f;
#pragma unroll
            for (int na = 0; na < 8; na++) {
                float a = acc[ma][na][hr * 2], b = acc[ma][na][hr * 2 + 1];
                s += a + b;
                s2 += a * a + b * b;
            }
            s  += __shfl_xor_sync(0xffffffffu, s, 1);
            s  += __shfl_xor_sync(0xffffffffu, s, 2);
            s2 += __shfl_xor_sync(0xffffffffu, s2, 1);
            s2 += __shfl_xor_sync(0xffffffffu, s2, 2);
            int rl = wm * 32 + ma * 16 + (lane >> 2) + hr * 8;
            if ((lane & 3) == 0) { red[rl][wn][0] = s; red[rl][wn][1] = s2; }
        }
    __syncthreads();

#pragma unroll
    for (int ma = 0; ma < 2; ma++)
#pragma unroll
        for (int hr = 0; hr < 2; hr++) {
            int rl = wm * 32 + ma * 16 + (lane >> 2) + hr * 8;
            float S  = red[rl][0][0] + red[rl][1][0];
            float S2 = red[rl][0][1] + red[rl][1][1];
            float mu = S * (1.f / 128.f);
            float var = S2 * (1.f / 128.f) - mu * mu;
            float inv = rsqrtf(var + 1e-5f);
            int row = rowBase + rl;
#pragma unroll
            for (int na = 0; na < 8; na++) {
                int col = wn * 64 + na * 8 + (lane & 3) * 2;
                float g0 = gamma[col], g1 = gamma[col + 1];
                float t0 = beta[col], t1 = beta[col + 1];
                float v0 = fmaf((acc[ma][na][hr * 2] - mu) * inv, g0, t0);
                float v1 = fmaf((acc[ma][na][hr * 2 + 1] - mu) * inv, g1, t1);
                *(float2*)&Yf[(size_t)row * DMODEL + col] = make_float2(v0, v1);
                if (Yhi) {
                    uint32_t hh, ll;
                    split_pack(v0, v1, hh, ll);
                    *(uint32_t*)&Yhi[(size_t)row * DMODEL + col] = hh;
                    *(uint32_t*)&Ylo[(size_t)row * DMODEL + col] = ll;
                }
            }
        }
}

// ---------------- flash attention (f16, h2exp2) -------------------------------
__global__ void __launch_bounds__(256)
k_attn_tc(const __half* __restrict__ Qp, const __half* __restrict__ KVp,
          __nv_bfloat16* __restrict__ Ohi) {
    __shared__ __half sQ[128 * QST];
    __shared__ __half sK[64 * QST];
    __shared__ __half sV[64 * QST];

    int b = blockIdx.z, hd = blockIdx.y, qbase = blockIdx.x * 128;
    int tid = threadIdx.x, wm = tid >> 5, lane = tid & 31;

    const __half* Qh = Qp + ((size_t)hd * N_NODES + b * SEQ + qbase) * 16;
    const __half* Kh = KVp + ((size_t)hd * N_NODES + b * SEQ) * 16;
    const __half* Vh = KVp + ((size_t)(hd + HEADS) * N_NODES + b * SEQ) * 16;

    {
        int row = tid >> 1, half = tid & 1;
        *(uint4*)&sQ[row * QST + half * 8] = *(const uint4*)&Qh[row * 16 + half * 8];
    }
    int slot = tid & 127, trow = slot >> 1, thalf = slot & 1;
    const __half* tsrc = (tid < 128) ? Kh : Vh;
    __half* tdst = (tid < 128) ? sK : sV;

    uint4 rbuf = *(const uint4*)&tsrc[(size_t)trow * 16 + thalf * 8];
    *(uint4*)&tdst[trow * QST + thalf * 8] = rbuf;
    __syncthreads();

    int ar = (lane & 7) + ((lane >> 3) & 1) * 8;
    int ak = (lane >> 4) * 8;
    int bn = (lane & 7) + ((lane >> 4) & 1) * 8;
    int bk = ((lane >> 3) & 1) * 8;
    int vkey = (lane & 7) + ((lane >> 3) & 1) * 8;
    int vdh = ((lane >> 4) & 1) * 8;

    uint32_t sQa = cvta_s(sQ), sKa = cvta_s(sK), sVa = cvta_s(sV);
    uint32_t qf[4];
    ldsm4(qf, sQa + (uint32_t)((wm * 16 + ar) * QST + ak) * 2);

    float mst[2] = {-CUDART_INF_F, -CUDART_INF_F};
    float lst[2] = {0.f, 0.f};
    float of[2][4] = {{0.f, 0.f, 0.f, 0.f}, {0.f, 0.f, 0.f, 0.f}};

    for (int kt = 0; kt < SEQ / 64; kt++) {
        if (kt + 1 < SEQ / 64)
            rbuf = *(const uint4*)&tsrc[(size_t)((kt + 1) * 64 + trow) * 16 + thalf * 8];

        float sf[8][4];
#pragma unroll
        for (int j = 0; j < 8; j++)
#pragma unroll
            for (int q = 0; q < 4; q++) sf[j][q] = 0.f;
#pragma unroll
        for (int nb = 0; nb < 4; nb++) {
            uint32_t kf[4];
            ldsm4(kf, sKa + (uint32_t)((nb * 16 + bn) * QST + bk) * 2);
            mma_f16(sf[2 * nb], qf, &kf[0]);
            mma_f16(sf[2 * nb + 1], qf, &kf[2]);
        }

        __half2 ep[8][2];
#pragma unroll
        for (int hr = 0; hr < 2; hr++) {
            float mx = sf[0][hr * 2];
#pragma unroll
            for (int j = 0; j < 8; j++) {
                mx = fmaxf(mx, sf[j][hr * 2]);
                mx = fmaxf(mx, sf[j][hr * 2 + 1]);
            }
            mx = fmaxf(mx, __shfl_xor_sync(0xffffffffu, mx, 1));
            mx = fmaxf(mx, __shfl_xor_sync(0xffffffffu, mx, 2));
            float mnew = fmaxf(mst[hr], mx);
            float corr = exp2f(mst[hr] - mnew);
            __half2 hsum = __floats2half2_rn(0.f, 0.f);
#pragma unroll
            for (int j = 0; j < 8; j++) {
                float d0 = sf[j][hr * 2] - mnew;
                float d1 = sf[j][hr * 2 + 1] - mnew;
                __half2 p2 = h2exp2(__floats2half2_rn(d0, d1));
                ep[j][hr] = p2;
                hsum = __hadd2(hsum, p2);
            }
            float2 fs = __half22float2(hsum);
            float rsum = fs.x + fs.y;
            rsum += __shfl_xor_sync(0xffffffffu, rsum, 1);
            rsum += __shfl_xor_sync(0xffffffffu, rsum, 2);
            lst[hr] = lst[hr] * corr + rsum;
            mst[hr] = mnew;
#pragma unroll
            for (int nh = 0; nh < 2; nh++) {
                of[nh][hr * 2] *= corr;
                of[nh][hr * 2 + 1] *= corr;
            }
        }

#pragma unroll
        for (int kf = 0; kf < 4; kf++) {
            uint32_t vf[4];
            ldsm4t(vf, sVa + (uint32_t)((kf * 16 + vkey) * QST + vdh) * 2);
            uint32_t pa[4];
            pa[0] = *(uint32_t*)&ep[2 * kf][0];
            pa[1] = *(uint32_t*)&ep[2 * kf][1];
            pa[2] = *(uint32_t*)&ep[2 * kf + 1][0];
            pa[3] = *(uint32_t*)&ep[2 * kf + 1][1];
            mma_f16(of[0], pa, &vf[0]);
            mma_f16(of[1], pa, &vf[2]);
        }

        __syncthreads();
        if (kt + 1 < SEQ / 64)
            *(uint4*)&tdst[trow * QST + thalf * 8] = rbuf;
        __syncthreads();
    }

#pragma unroll
    for (int hr = 0; hr < 2; hr++) {
        float inv = 1.f / lst[hr];
        int grow = b * SEQ + qbase + wm * 16 + (lane >> 2) + hr * 8;
#pragma unroll
        for (int nh = 0; nh < 2; nh++) {
            float v0 = of[nh][hr * 2] * inv;
            float v1 = of[nh][hr * 2 + 1] * inv;
            int col = hd * 16 + nh * 8 + (lane & 3) * 2;
            *(uint32_t*)&Ohi[(size_t)grow * DMODEL + col] = cvt2bf(v0, v1);
        }
    }
}

// ---------------- host orchestration -----------------------------------------
extern "C" void kernel_launch(void* const* d_in, const int* in_sizes, int n_in,
                              void* d_out, int out_size) {
    const float* enc   = (const float*)d_in[0];
    const float* xraw  = (const float*)d_in[2];
    const int*   eidx  = (const int*)  d_in[3];
    const float* Wg1   = (const float*)d_in[4];
    const float* bg1   = (const float*)d_in[5];
    const float* Wg2   = (const float*)d_in[6];
    const float* bg2   = (const float*)d_in[7];
    const float* Wq    = (const float*)d_in[8];
    const float* Wk    = (const float*)d_in[9];
    const float* Wv    = (const float*)d_in[10];
    const float* Wo    = (const float*)d_in[11];
    const float* Wff1  = (const float*)d_in[12];
    const float* bff1  = (const float*)d_in[13];
    const float* Wff2  = (const float*)d_in[14];
    const float* bff2  = (const float*)d_in[15];
    const float* ln1g  = (const float*)d_in[16];
    const float* ln1b  = (const float*)d_in[17];
    const float* ln2g  = (const float*)d_in[18];
    const float* ln2b  = (const float*)d_in[19];
    float* outp = (float*)d_out;

    float *dinv, *y;
    int *counts, *rowoff, *cursor, *csr, *bsum, *boff;
    __nv_bfloat16 *h, *whi, *wlo, *xrhi, *x1hi, *gxhi;
    __nv_bfloat16 *yhi, *ylo, *Abhi, *F1hi, *F1lo;
    __half *Qp, *KVp0, *KVp1;
    cudaGetSymbolAddress((void**)&dinv,   g_dinv);
    cudaGetSymbolAddress((void**)&counts, g_counts);
    cudaGetSymbolAddress((void**)&rowoff, g_rowoff);
    cudaGetSymbolAddress((void**)&cursor, g_cursor);
    cudaGetSymbolAddress((void**)&csr,    g_csr);
    cudaGetSymbolAddress((void**)&bsum,   g_bsum);
    cudaGetSymbolAddress((void**)&boff,   g_boff);
    cudaGetSymbolAddress((void**)&h,   g_h);
    cudaGetSymbolAddress((void**)&y,   g_y);
    cudaGetSymbolAddress((void**)&whi, g_whi);
    cudaGetSymbolAddress((void**)&wlo, g_wlo);
    cudaGetSymbolAddress((void**)&xrhi, g_xrhi);
    cudaGetSymbolAddress((void**)&x1hi, g_x1hi);
    cudaGetSymbolAddress((void**)&gxhi, g_gxhi);
    cudaGetSymbolAddress((void**)&yhi, g_yhi);
    cudaGetSymbolAddress((void**)&ylo, g_ylo);
    cudaGetSymbolAddress((void**)&Qp,  g_Qp);
    cudaGetSymbolAddress((void**)&KVp0, g_KVp0);
    cudaGetSymbolAddress((void**)&KVp1, g_KVp1);
    cudaGetSymbolAddress((void**)&Abhi, g_Abhi);
    cudaGetSymbolAddress((void**)&F1hi, g_F1hi);
    cudaGetSymbolAddress((void**)&F1lo, g_F1lo);

    cudaFuncSetAttribute(k_gemm_tc, cudaFuncAttributeMaxDynamicSharedMemorySize, GT_SMEM);
    cudaFuncSetAttribute(k_gemm_ln, cudaFuncAttributeMaxDynamicSharedMemorySize, GT_SMEM);

    // persistent secondary stream + fork/join events (host resources only;
    // created once, reused every call -> identical captured work each time)
    static cudaStream_t sB = nullptr;
    static cudaEvent_t eFork = nullptr, eW = nullptr, eKV0 = nullptr, eKV1 = nullptr;
    if (!sB) {
        cudaStreamCreateWithFlags(&sB, cudaStreamNonBlocking);
        cudaEventCreateWithFlags(&eFork, cudaEventDisableTiming);
        cudaEventCreateWithFlags(&eW,    cudaEventDisableTiming);
        cudaEventCreateWithFlags(&eKV0,  cudaEventDisableTiming);
        cudaEventCreateWithFlags(&eKV1,  cudaEventDisableTiming);
    }

    const int ROWS = N_NODES;
    const int OFF_G1 = 0, OFF_G2 = 16384;
    const int LSTR = 4 * 16384 + 2 * 65536;
    auto offQ  = [&](int l) { return 32768 + l * LSTR; };
    auto offK  = [&](int l) { return offQ(l) + 16384; };
    auto offO  = [&](int l) { return offQ(l) + 49152; };
    auto offF1 = [&](int l) { return offQ(l) + 65536; };
    auto offF2 = [&](int l) { return offQ(l) + 131072; };

    PrepArgs pa;
    int blk = 0, si = 0;
    auto addseg = [&](const float* src, int K, int N, int off) {
        pa.s[si].src = src; pa.s[si].K = K; pa.s[si].N = N;
        pa.s[si].off = off; pa.s[si].blk0 = blk;
        si++; blk += K * N / 256;
    };
    addseg(Wg1, 128, 128, OFF_G1);
    addseg(Wg2, 128, 128, OFF_G2);
    for (int l = 0; l < 2; l++) {
        addseg(Wq + l * 16384, 128, 128, offQ(l));
        addseg(Wk + l * 16384, 128, 128, offK(l));
        addseg(Wv + l * 16384, 128, 128, offK(l) + 16384);
        addseg(Wo + l * 16384, 128, 128, offO(l));
        addseg(Wff1 + l * 65536, 128, 512, offF1(l));
        addseg(Wff2 + l * 65536, 512, 128, offF2(l));
    }
    pa.nseg = si;

    auto GEMM = [&](cudaStream_t st, const __nv_bfloat16* Ah, const __nv_bfloat16* Al,
                    int woff, const __nv_bfloat16* Wl, const float* bias, float* Cf,
                    __half* Ch, __nv_bfloat16* Chi, __nv_bfloat16* Clo, int K, int ncols,
                    int act, float premul) {
        dim3 g(ROWS / 128, ncols / 128);
        k_gemm_tc<<<g, 256, GT_SMEM, st>>>(Ah, Al, whi + woff, Wl, bias,
                                           Cf, Ch, Chi, Clo, K, ncols, act, premul);
    };

    // ===== fork: stream B gets the whole GCN/KV branch =====
    cudaEventRecord(eFork, 0);
    cudaStreamWaitEvent(sB, eFork, 0);

    // main stream: weight prep (both branches need it) -> eW
    k_prep_all<<<blk, 256>>>(pa, whi, wlo);
    cudaEventRecord(eW, 0);
    cudaStreamWaitEvent(sB, eW, 0);

    // stream B: graph preprocessing + GCN + both KV GEMMs
    cudaMemsetAsync(counts, 0, N_NODES * sizeof(int), sB);
    k_count<<<N_EDGES / 256, 256, 0, sB>>>(eidx, counts);
    k_scan_bsum<<<128, 256, 0, sB>>>(counts, bsum);
    k_scan_boff<<<1, 128, 0, sB>>>(bsum, boff);
    k_scan_fin<<<128, 256, 0, sB>>>(counts, boff, rowoff, cursor, dinv);
    k_fill<<<NTOT / 256, 256, 0, sB>>>(eidx, cursor, csr);
    k_cvt<<<N_NODES * DMODEL / 1024, 256, 0, sB>>>(xraw, xrhi, nullptr, nullptr);
    GEMM(sB, xrhi, nullptr, OFF_G1, nullptr, nullptr, nullptr, nullptr, h, nullptr, 128, 128, 0, 1.f);
    k_aggregate<<<N_NODES / 8, 256, 0, sB>>>(h, dinv, rowoff, csr, bg1, x1hi);
    GEMM(sB, x1hi, nullptr, OFF_G2, nullptr, nullptr, nullptr, nullptr, h, nullptr, 128, 128, 0, 1.f);
    k_aggregate<<<N_NODES / 8, 256, 0, sB>>>(h, dinv, rowoff, csr, bg2, gxhi);
    GEMM(sB, gxhi, nullptr, offK(0), nullptr, nullptr, nullptr, KVp0, nullptr, nullptr, 128, 256, 0, 1.f);
    cudaEventRecord(eKV0, sB);
    GEMM(sB, gxhi, nullptr, offK(1), nullptr, nullptr, nullptr, KVp1, nullptr, nullptr, 128, 256, 0, 1.f);
    cudaEventRecord(eKV1, sB);

    // main stream: enc conversion + transformer critical path
    k_cvt<<<N_NODES * DMODEL / 1024, 256>>>(enc, yhi, ylo, y);

    for (int l = 0; l < 2; l++) {
        __half* KVp = (l == 0) ? KVp0 : KVp1;
        GEMM(0, yhi, nullptr, offQ(l), nullptr, nullptr, nullptr, Qp, nullptr, nullptr, 128, 128, 0, SC2);
        cudaStreamWaitEvent(0, (l == 0) ? eKV0 : eKV1, 0);
        k_attn_tc<<<dim3(SEQ / 128, HEADS, BATCH), 256>>>(Qp, KVp, Abhi);
        k_gemm_ln<<<ROWS / 128, 256, GT_SMEM>>>(Abhi, nullptr, whi + offO(l), nullptr,
                                                nullptr, y, ln1g + l * 128, ln1b + l * 128,
                                                y, yhi, ylo, 128);
        GEMM(0, yhi, ylo, offF1(l), wlo + offF1(l), bff1 + l * DFF, nullptr, nullptr,
             F1hi, F1lo, 128, DFF, 1, 1.f);
        if (l == 1)
            k_gemm_ln<<<ROWS / 128, 256, GT_SMEM>>>(F1hi, F1lo, whi + offF2(l), wlo + offF2(l),
                                                    bff2 + l * DMODEL, y, ln2g + l * 128,
                                                    ln2b + l * 128, outp, nullptr, nullptr, 512);
        else
            k_gemm_ln<<<ROWS / 128, 256, GT_SMEM>>>(F1hi, F1lo, whi + offF2(l), wlo + offF2(l),
                                                    bff2 + l * DMODEL, y, ln2g + l * 128,
                                                    ln2b + l * 128, y, yhi, ylo, 512);
    }
}